// round 1
// baseline (speedup 1.0000x reference)
#include <cuda_runtime.h>

#define Bb 64
#define Nn 50
#define Tt 30
#define Ee 300
#define FNf 400
#define Aa 200
#define Gg 400

// ---------------- scratch (device globals; no allocation allowed) ----------------
__device__ float g_C[(long)Bb * Nn * Tt * FNf];     // conv output [B*N*T, FN]
__device__ float g_A1[(long)Bb * Nn * Tt * Aa];     // C @ v       [B*N*T, A]
__device__ float g_scores[Bb * Nn * Tt];
__device__ float g_alpha[Bb * Nn * Tt];
__device__ float g_E[Bb * Nn * FNf];                // news embed  [B*N, FN]
__device__ float g_GX[Bb * Nn * 3 * Gg];            // E @ W_ih^T  [B*N, 3G]
__device__ float g_h[2][Gg * Bb];                   // transposed h: [G][B], ping-pong

// ---------------- 1. embedding gather + conv1d(K=3,pad=1) + ReLU ----------------
__global__ __launch_bounds__(512) void conv_kernel(const int* __restrict__ title,
                                                   const float* __restrict__ word_emb,
                                                   const float* __restrict__ conv_w,
                                                   const float* __restrict__ conv_b) {
    __shared__ float s_emb[32 * Ee];   // rows 0 and 31 are the zero padding
    int bn = blockIdx.x;
    const int* tw = title + bn * Tt;
    for (int i = threadIdx.x; i < Ee; i += 512) {
        s_emb[i] = 0.f;
        s_emb[31 * Ee + i] = 0.f;
    }
    for (int i = threadIdx.x; i < Tt * Ee; i += 512) {
        int t = i / Ee, e = i - t * Ee;
        s_emb[(t + 1) * Ee + e] = word_emb[(long)tw[t] * Ee + e];
    }
    __syncthreads();
    int f = threadIdx.x;
    if (f >= FNf) return;
    float acc[Tt];
    float bias = conv_b[f];
#pragma unroll
    for (int t = 0; t < Tt; t++) acc[t] = bias;
    for (int e = 0; e < Ee; ++e) {
        float w0 = conv_w[(0 * Ee + e) * FNf + f];
        float w1 = conv_w[(1 * Ee + e) * FNf + f];
        float w2 = conv_w[(2 * Ee + e) * FNf + f];
        float xp = s_emb[0 * Ee + e];
        float xc = s_emb[1 * Ee + e];
#pragma unroll
        for (int t = 0; t < Tt; t++) {
            float xn = s_emb[(t + 2) * Ee + e];
            acc[t] += xp * w0;
            acc[t] += xc * w1;
            acc[t] += xn * w2;
            xp = xc; xc = xn;
        }
    }
    float* Cout = g_C + (long)bn * Tt * FNf;
#pragma unroll
    for (int t = 0; t < Tt; t++) Cout[t * FNf + f] = fmaxf(acc[t], 0.f);
}

// ---------------- generic tiled SGEMM: C[M,N] = A[M,K] @ op(B) ----------------
// TB==0: B is [K,N] row-major (NN).  TB==1: B is [N,K] row-major (NT, i.e. A@B^T).
// Requires K % 16 == 0, M % 64 == 0. N arbitrary (guarded).
template <int TB>
__global__ __launch_bounds__(256) void sgemm_kernel(const float* __restrict__ Ap,
                                                    const float* __restrict__ Bp,
                                                    float* __restrict__ Cp,
                                                    int M, int N, int K) {
    __shared__ float As[16][64];
    __shared__ float Bs[16][68];
    int tid = threadIdx.x;
    int row0 = blockIdx.y * 64;
    int col0 = blockIdx.x * 64;
    int am = tid >> 2, ak = (tid & 3) * 4;
    int ty = tid >> 4, tx = tid & 15;
    float acc[4][4] = {};
    for (int k0 = 0; k0 < K; k0 += 16) {
        {
            const float* src = Ap + (long)(row0 + am) * K + k0 + ak;
            float4 v = *(const float4*)src;   // row0+am < M guaranteed (M%64==0)
            As[ak + 0][am] = v.x; As[ak + 1][am] = v.y;
            As[ak + 2][am] = v.z; As[ak + 3][am] = v.w;
        }
        if (TB == 0) {
            int bk = tid >> 6, c = tid & 63;
#pragma unroll
            for (int i = 0; i < 4; i++) {
                int kk = bk * 4 + i;
                Bs[kk][c] = (col0 + c < N) ? Bp[(long)(k0 + kk) * N + col0 + c] : 0.f;
            }
        } else {
            int bn = tid >> 2, bk4 = (tid & 3) * 4;
            float4 v = make_float4(0.f, 0.f, 0.f, 0.f);
            if (col0 + bn < N)
                v = *(const float4*)(Bp + (long)(col0 + bn) * K + k0 + bk4);
            Bs[bk4 + 0][bn] = v.x; Bs[bk4 + 1][bn] = v.y;
            Bs[bk4 + 2][bn] = v.z; Bs[bk4 + 3][bn] = v.w;
        }
        __syncthreads();
#pragma unroll
        for (int kk = 0; kk < 16; kk++) {
            float a[4], bb[4];
#pragma unroll
            for (int i = 0; i < 4; i++) a[i] = As[kk][ty * 4 + i];
#pragma unroll
            for (int j = 0; j < 4; j++) bb[j] = Bs[kk][tx * 4 + j];
#pragma unroll
            for (int i = 0; i < 4; i++)
#pragma unroll
                for (int j = 0; j < 4; j++) acc[i][j] += a[i] * bb[j];
        }
        __syncthreads();
    }
#pragma unroll
    for (int i = 0; i < 4; i++) {
        int r = row0 + ty * 4 + i;
#pragma unroll
        for (int j = 0; j < 4; j++) {
            int c = col0 + tx * 4 + j;
            if (c < N) Cp[(long)r * N + c] = acc[i][j];
        }
    }
}

// ---------------- 3. scores: s = tanh(A1 + vb) @ q, one warp per row ----------------
__global__ __launch_bounds__(256) void score_kernel(const float* __restrict__ vb,
                                                    const float* __restrict__ q) {
    int warp = (blockIdx.x * blockDim.x + threadIdx.x) >> 5;
    int lane = threadIdx.x & 31;
    if (warp >= Bb * Nn * Tt) return;
    const float* row = g_A1 + (long)warp * Aa;
    float s = 0.f;
    for (int j = lane; j < Aa; j += 32) s += tanhf(row[j] + vb[j]) * q[j];
#pragma unroll
    for (int o = 16; o; o >>= 1) s += __shfl_xor_sync(0xffffffffu, s, o);
    if (lane == 0) g_scores[warp] = s;
}

// ---------------- 4. softmax over the N (titles) axis, per (b,t) ----------------
__global__ void softmax_kernel() {
    int idx = blockIdx.x * blockDim.x + threadIdx.x;
    if (idx >= Bb * Tt) return;
    int b = idx / Tt, t = idx - b * Tt;
    const float* s = g_scores + b * Nn * Tt + t;
    float mx = -1e30f;
    for (int n = 0; n < Nn; n++) mx = fmaxf(mx, s[n * Tt]);
    float sum = 0.f;
    for (int n = 0; n < Nn; n++) sum += __expf(s[n * Tt] - mx);
    float inv = 1.f / sum;
    float* al = g_alpha + b * Nn * Tt + t;
    for (int n = 0; n < Nn; n++) al[n * Tt] = __expf(s[n * Tt] - mx) * inv;
}

// ---------------- 5. weighted sum over words: E[b,n,f] = sum_t alpha*C ----------------
__global__ __launch_bounds__(128) void wsum_kernel() {
    int bn = blockIdx.x;
    __shared__ float al[Tt];
    if (threadIdx.x < Tt) al[threadIdx.x] = g_alpha[bn * Tt + threadIdx.x];
    __syncthreads();
    const float* Cr = g_C + (long)bn * Tt * FNf;
    for (int f = threadIdx.x; f < FNf; f += 128) {
        float acc = 0.f;
#pragma unroll
        for (int t = 0; t < Tt; t++) acc += al[t] * Cr[t * FNf + f];
        g_E[bn * FNf + f] = acc;
    }
}

// ---------------- 6. GRU ----------------
__global__ void h0_kernel(const int* __restrict__ uid, const float* __restrict__ user_emb) {
    int i = blockIdx.x * blockDim.x + threadIdx.x;
    if (i >= Gg * Bb) return;
    int e = i >> 6, b = i & 63;
    g_h[0][e * Bb + b] = user_emb[(long)uid[b] * Gg + e];
}

// one step; block = 4 g-rows x 64 batch; reads h from buf[n&1], writes buf[(n+1)&1]
__global__ __launch_bounds__(256) void gru_step(const float* __restrict__ W_hh,
                                                const float* __restrict__ b_ih,
                                                const float* __restrict__ b_hh,
                                                const int* __restrict__ lens, int n) {
    int b = threadIdx.x & 63;
    int gi = threadIdx.x >> 6;
    int g = blockIdx.x * 4 + gi;
    const float* hin = g_h[n & 1];
    float* hout = g_h[(n + 1) & 1];
    const float* wr = W_hh + (long)g * Gg;
    const float* wz = W_hh + (long)(Gg + g) * Gg;
    const float* wn = W_hh + (long)(2 * Gg + g) * Gg;
    float hr = 0.f, hz = 0.f, hn = 0.f;
#pragma unroll 4
    for (int e = 0; e < Gg; e++) {
        float hv = hin[e * Bb + b];
        hr += wr[e] * hv;
        hz += wz[e] * hv;
        hn += wn[e] * hv;
    }
    hr += b_hh[g]; hz += b_hh[Gg + g]; hn += b_hh[2 * Gg + g];
    const float* gx = g_GX + (long)(b * Nn + n) * (3 * Gg);
    float xr = gx[g] + b_ih[g];
    float xz = gx[Gg + g] + b_ih[Gg + g];
    float xn = gx[2 * Gg + g] + b_ih[2 * Gg + g];
    float hprev = hin[g * Bb + b];
    float r = 1.f / (1.f + __expf(-(xr + hr)));
    float z = 1.f / (1.f + __expf(-(xz + hz)));
    float nv = tanhf(xn + r * hn);
    float hnew = (1.f - z) * nv + z * hprev;
    hout[g * Bb + b] = (n < lens[b]) ? hnew : hprev;
}

__global__ void final_kernel(float* __restrict__ out) {
    int i = blockIdx.x * blockDim.x + threadIdx.x;
    if (i >= Bb * Gg) return;
    int b = i / Gg, g = i - b * Gg;
    out[i] = g_h[0][g * Bb + b];   // after 50 steps, final h lives in buffer 0
}

// ---------------- launch ----------------
extern "C" void kernel_launch(void* const* d_in, const int* in_sizes, int n_in,
                              void* d_out, int out_size) {
    const int*   user_id   = (const int*)d_in[0];
    const int*   title     = (const int*)d_in[1];
    const int*   hist_len  = (const int*)d_in[2];
    const float* word_emb  = (const float*)d_in[3];
    const float* conv_w    = (const float*)d_in[4];
    const float* conv_b    = (const float*)d_in[5];
    const float* v         = (const float*)d_in[6];
    const float* vb        = (const float*)d_in[7];
    const float* q         = (const float*)d_in[8];
    const float* user_emb  = (const float*)d_in[9];
    const float* W_ih      = (const float*)d_in[10];
    const float* W_hh      = (const float*)d_in[11];
    const float* b_ih      = (const float*)d_in[12];
    const float* b_hh      = (const float*)d_in[13];
    float* out = (float*)d_out;

    // 1. conv + relu -> g_C
    conv_kernel<<<Bb * Nn, 512>>>(title, word_emb, conv_w, conv_b);

    // 2. A1 = C @ v   (M=96000, N=200, K=400)
    {
        float* A1p; cudaGetSymbolAddress((void**)&A1p, g_A1);
        float* Cp;  cudaGetSymbolAddress((void**)&Cp, g_C);
        dim3 grid((Aa + 63) / 64, (Bb * Nn * Tt) / 64);
        sgemm_kernel<0><<<grid, 256>>>(Cp, v, A1p, Bb * Nn * Tt, Aa, FNf);
    }

    // 3. scores
    score_kernel<<<(Bb * Nn * Tt * 32 + 255) / 256, 256>>>(vb, q);

    // 4. softmax over titles
    softmax_kernel<<<(Bb * Tt + 255) / 256, 256>>>();

    // 5. weighted sum -> g_E
    wsum_kernel<<<Bb * Nn, 128>>>();

    // 6. GX = E @ W_ih^T   (M=3200, N=1200, K=400)
    {
        float* Ep;  cudaGetSymbolAddress((void**)&Ep, g_E);
        float* GXp; cudaGetSymbolAddress((void**)&GXp, g_GX);
        dim3 grid((3 * Gg + 63) / 64, (Bb * Nn) / 64);
        sgemm_kernel<1><<<grid, 256>>>(Ep, W_ih, GXp, Bb * Nn, 3 * Gg, FNf);
    }

    // 7. GRU
    h0_kernel<<<(Gg * Bb + 255) / 256, 256>>>(user_id, user_emb);
    for (int n = 0; n < Nn; n++)
        gru_step<<<Gg / 4, 256>>>(W_hh, b_ih, b_hh, hist_len, n);

    final_kernel<<<(Bb * Gg + 255) / 256, 256>>>(out);
}

// round 2
// speedup vs baseline: 2.1191x; 2.1191x over previous
#include <cuda_runtime.h>
#include <cstdint>

#define Bb 64
#define Nn 50
#define Tt 30
#define Ee 300
#define EeP 304
#define FNf 400
#define Aa 200
#define Gg 400
#define KC 912                      // conv GEMM K (3*304)
#define MROWS (Bb*Nn*Tt)            // 96000

// ---------------- scratch (device globals; no allocation allowed) ----------------
__device__ float g_X[(long)Bb * Nn * 32 * EeP];   // padded gathered embeddings
__device__ float g_Wp[KC * FNf];                  // padded conv weights [912][400]
__device__ float g_C[(long)MROWS * FNf];          // conv output [96000][400]
__device__ float g_scores[MROWS];
__device__ float g_alpha[MROWS];
__device__ float g_E[Bb * Nn * FNf];
__device__ float g_GX[Bb * Nn * 3 * Gg];
__device__ float g_h[2][Bb * Gg];                 // h layout [b][g], ping-pong
__device__ int   g_bar[64];                       // grid barrier counters

// ---------------- prep kernels ----------------
__global__ __launch_bounds__(256) void gather_kernel(const int* __restrict__ title,
                                                     const float* __restrict__ word_emb) {
    int bn = blockIdx.x;
    float* X = g_X + (long)bn * 32 * EeP;
    for (int i = threadIdx.x; i < EeP; i += 256) { X[i] = 0.f; X[31 * EeP + i] = 0.f; }
    const int* tw = title + bn * Tt;
    for (int i = threadIdx.x; i < Tt * EeP; i += 256) {
        int s = i / EeP, e = i - s * EeP;
        float v = 0.f;
        if (e < Ee) v = word_emb[(long)tw[s] * Ee + e];
        X[(s + 1) * EeP + e] = v;
    }
}

__global__ void wpad_kernel(const float* __restrict__ conv_w) {
    int i = blockIdx.x * 256 + threadIdx.x;
    if (i >= KC * FNf) return;
    int k = i / FNf, n = i - k * FNf;
    int tap = k / EeP, e = k - tap * EeP;
    g_Wp[i] = (e < Ee) ? conv_w[(tap * Ee + e) * FNf + n] : 0.f;
}

// ---------------- tf32 tensor-core GEMM, 128x128x16 tiles ----------------
__device__ __forceinline__ uint32_t f2tf(float f) {
    uint32_t r; asm("cvt.rna.tf32.f32 %0, %1;" : "=r"(r) : "f"(f)); return r;
}
__device__ __forceinline__ void mma1688(float* c, const uint32_t* a, const uint32_t* b) {
    asm volatile("mma.sync.aligned.m16n8k8.row.col.f32.tf32.tf32.f32 "
                 "{%0,%1,%2,%3}, {%4,%5,%6,%7}, {%8,%9}, {%0,%1,%2,%3};"
                 : "+f"(c[0]), "+f"(c[1]), "+f"(c[2]), "+f"(c[3])
                 : "r"(a[0]), "r"(a[1]), "r"(a[2]), "r"(a[3]), "r"(b[0]), "r"(b[1]));
}

__device__ __forceinline__ void stA(uint32_t (*As)[136], int ak, int ar, float4 x, float4 y) {
    As[ak + 0][ar] = f2tf(x.x); As[ak + 1][ar] = f2tf(x.y);
    As[ak + 2][ar] = f2tf(x.z); As[ak + 3][ar] = f2tf(x.w);
    As[ak + 4][ar] = f2tf(y.x); As[ak + 5][ar] = f2tf(y.y);
    As[ak + 6][ar] = f2tf(y.z); As[ak + 7][ar] = f2tf(y.w);
}
__device__ __forceinline__ void stB(uint32_t (*Bs)[136], int kk, int c4, float4 u, float4 w) {
    Bs[kk][c4 + 0] = f2tf(u.x); Bs[kk][c4 + 1] = f2tf(u.y);
    Bs[kk][c4 + 2] = f2tf(u.z); Bs[kk][c4 + 3] = f2tf(u.w);
    Bs[kk + 8][c4 + 0] = f2tf(w.x); Bs[kk + 8][c4 + 1] = f2tf(w.y);
    Bs[kk + 8][c4 + 2] = f2tf(w.z); Bs[kk + 8][c4 + 3] = f2tf(w.w);
}

// EPI 0: conv rows from g_X, epilogue bias+ReLU -> Cptr
// EPI 1: plain rows, epilogue tanh(acc+vb)*q row-reduced into g_scores (no store)
template <int EPI>
__global__ __launch_bounds__(256) void tf32gemm(const float* __restrict__ Aptr,
                                                const float* __restrict__ Bptr,
                                                float* __restrict__ Cptr,
                                                const float* __restrict__ bias,
                                                const float* __restrict__ qv,
                                                int N, int K) {
    __shared__ uint32_t As[2][16][136];
    __shared__ uint32_t Bs[2][16][136];
    int tid = threadIdx.x;
    int lane = tid & 31, wid = tid >> 5;
    int warpM = wid & 1, warpN = wid >> 1;
    int row0 = blockIdx.y * 128, col0 = blockIdx.x * 128;

    int arow = tid >> 1;
    int akoff = (tid & 1) * 8;
    long abase;
    {
        int r = row0 + arow;
        if (EPI == 0) { int bn = r / Tt, t = r - bn * Tt; abase = (long)(bn * 32 + t) * EeP; }
        else abase = (long)r * K;
    }
    const float* Arow_p = Aptr + abase + akoff;

    int bkk = tid >> 5;                 // 0..7
    int bc4 = (tid & 31) * 4;
    bool bvalid = (col0 + bc4) < N;
    const float* Bp0 = Bptr + (long)bkk * N + col0 + bc4;
    const float4 Z4 = make_float4(0.f, 0.f, 0.f, 0.f);

    float acc[4][4][4];
#pragma unroll
    for (int i = 0; i < 4; i++)
#pragma unroll
        for (int j = 0; j < 4; j++)
#pragma unroll
            for (int k = 0; k < 4; k++) acc[i][j][k] = 0.f;

    {   // stage 0
        float4 x = *(const float4*)(Arow_p);
        float4 y = *(const float4*)(Arow_p + 4);
        float4 u = bvalid ? *(const float4*)(Bp0) : Z4;
        float4 w = bvalid ? *(const float4*)(Bp0 + 8L * N) : Z4;
        stA(As[0], akoff, arow, x, y);
        stB(Bs[0], bkk, bc4, u, w);
    }
    __syncthreads();

    int s = 0;
    for (int k0 = 0; k0 < K; k0 += 16) {
        bool more = (k0 + 16) < K;
        float4 x, y, u, w;
        if (more) {
            x = *(const float4*)(Arow_p + k0 + 16);
            y = *(const float4*)(Arow_p + k0 + 20);
            u = bvalid ? *(const float4*)(Bp0 + (long)(k0 + 16) * N) : Z4;
            w = bvalid ? *(const float4*)(Bp0 + (long)(k0 + 24) * N) : Z4;
        }
#pragma unroll
        for (int kh = 0; kh < 2; kh++) {
            int kc = kh * 8 + (lane & 3);
            uint32_t af[4][4], bf[4][2];
#pragma unroll
            for (int mt = 0; mt < 4; mt++) {
                int m0 = warpM * 64 + mt * 16 + (lane >> 2);
                af[mt][0] = As[s][kc][m0];
                af[mt][1] = As[s][kc][m0 + 8];
                af[mt][2] = As[s][kc + 4][m0];
                af[mt][3] = As[s][kc + 4][m0 + 8];
            }
#pragma unroll
            for (int nt = 0; nt < 4; nt++) {
                int n0 = warpN * 32 + nt * 8 + (lane >> 2);
                bf[nt][0] = Bs[s][kc][n0];
                bf[nt][1] = Bs[s][kc + 4][n0];
            }
#pragma unroll
            for (int mt = 0; mt < 4; mt++)
#pragma unroll
                for (int nt = 0; nt < 4; nt++)
                    mma1688(acc[mt][nt], af[mt], bf[nt]);
        }
        if (more) {
            stA(As[s ^ 1], akoff, arow, x, y);
            stB(Bs[s ^ 1], bkk, bc4, u, w);
            __syncthreads();
            s ^= 1;
        }
    }

    if (EPI == 0) {
#pragma unroll
        for (int mt = 0; mt < 4; mt++) {
            int rb = row0 + warpM * 64 + mt * 16 + (lane >> 2);
#pragma unroll
            for (int nt = 0; nt < 4; nt++) {
                int c = col0 + warpN * 32 + nt * 8 + (lane & 3) * 2;
                if (c < N) {
                    float b0 = bias[c], b1 = bias[c + 1];
                    float2 v0 = make_float2(fmaxf(acc[mt][nt][0] + b0, 0.f),
                                            fmaxf(acc[mt][nt][1] + b1, 0.f));
                    float2 v1 = make_float2(fmaxf(acc[mt][nt][2] + b0, 0.f),
                                            fmaxf(acc[mt][nt][3] + b1, 0.f));
                    *(float2*)&Cptr[(long)rb * N + c] = v0;
                    *(float2*)&Cptr[(long)(rb + 8) * N + c] = v1;
                }
            }
        }
    } else {
#pragma unroll
        for (int mt = 0; mt < 4; mt++) {
            float slo = 0.f, shi = 0.f;
#pragma unroll
            for (int nt = 0; nt < 4; nt++) {
                int c = col0 + warpN * 32 + nt * 8 + (lane & 3) * 2;
                if (c < N) {
                    float q0 = qv[c], q1 = qv[c + 1];
                    float v0 = bias[c], v1 = bias[c + 1];
                    slo += tanhf(acc[mt][nt][0] + v0) * q0 + tanhf(acc[mt][nt][1] + v1) * q1;
                    shi += tanhf(acc[mt][nt][2] + v0) * q0 + tanhf(acc[mt][nt][3] + v1) * q1;
                }
            }
            slo += __shfl_xor_sync(0xffffffffu, slo, 1);
            slo += __shfl_xor_sync(0xffffffffu, slo, 2);
            shi += __shfl_xor_sync(0xffffffffu, shi, 1);
            shi += __shfl_xor_sync(0xffffffffu, shi, 2);
            if ((lane & 3) == 0) {
                int r = row0 + warpM * 64 + mt * 16 + (lane >> 2);
                atomicAdd(&g_scores[r], slo);
                atomicAdd(&g_scores[r + 8], shi);
            }
        }
    }
}

// ---------------- softmax over titles ----------------
__global__ void softmax_kernel() {
    int idx = blockIdx.x * blockDim.x + threadIdx.x;
    if (idx >= Bb * Tt) return;
    int b = idx / Tt, t = idx - b * Tt;
    const float* s = g_scores + b * Nn * Tt + t;
    float mx = -1e30f;
    for (int n = 0; n < Nn; n++) mx = fmaxf(mx, s[n * Tt]);
    float sum = 0.f;
    for (int n = 0; n < Nn; n++) sum += __expf(s[n * Tt] - mx);
    float inv = 1.f / sum;
    float* al = g_alpha + b * Nn * Tt + t;
    for (int n = 0; n < Nn; n++) al[n * Tt] = __expf(s[n * Tt] - mx) * inv;
}

// ---------------- weighted sum over words ----------------
__global__ __launch_bounds__(128) void wsum_kernel() {
    int bn = blockIdx.x;
    __shared__ float al[Tt];
    if (threadIdx.x < Tt) al[threadIdx.x] = g_alpha[bn * Tt + threadIdx.x];
    __syncthreads();
    const float* Cr = g_C + (long)bn * Tt * FNf;
    for (int f = threadIdx.x; f < FNf; f += 128) {
        float acc = 0.f;
#pragma unroll
        for (int t = 0; t < Tt; t++) acc += al[t] * Cr[t * FNf + f];
        g_E[bn * FNf + f] = acc;
    }
}

// ---------------- fp32 SGEMM (NT) with bias: GX = E @ W_ih^T + b_ih ----------------
__global__ __launch_bounds__(256) void sgemm_nt_bias(const float* __restrict__ Ap,
                                                     const float* __restrict__ Bp,
                                                     float* __restrict__ Cp,
                                                     const float* __restrict__ bias,
                                                     int M, int N, int K) {
    __shared__ float As[16][64];
    __shared__ float Bs[16][68];
    int tid = threadIdx.x;
    int row0 = blockIdx.y * 64;
    int col0 = blockIdx.x * 64;
    int am = tid >> 2, ak = (tid & 3) * 4;
    int ty = tid >> 4, tx = tid & 15;
    float acc[4][4] = {};
    for (int k0 = 0; k0 < K; k0 += 16) {
        {
            const float* src = Ap + (long)(row0 + am) * K + k0 + ak;
            float4 v = *(const float4*)src;
            As[ak + 0][am] = v.x; As[ak + 1][am] = v.y;
            As[ak + 2][am] = v.z; As[ak + 3][am] = v.w;
        }
        {
            int bn = tid >> 2, bk4 = (tid & 3) * 4;
            float4 v = make_float4(0.f, 0.f, 0.f, 0.f);
            if (col0 + bn < N)
                v = *(const float4*)(Bp + (long)(col0 + bn) * K + k0 + bk4);
            Bs[bk4 + 0][bn] = v.x; Bs[bk4 + 1][bn] = v.y;
            Bs[bk4 + 2][bn] = v.z; Bs[bk4 + 3][bn] = v.w;
        }
        __syncthreads();
#pragma unroll
        for (int kk = 0; kk < 16; kk++) {
            float a[4], bb[4];
#pragma unroll
            for (int i = 0; i < 4; i++) a[i] = As[kk][ty * 4 + i];
#pragma unroll
            for (int j = 0; j < 4; j++) bb[j] = Bs[kk][tx * 4 + j];
#pragma unroll
            for (int i = 0; i < 4; i++)
#pragma unroll
                for (int j = 0; j < 4; j++) acc[i][j] += a[i] * bb[j];
        }
        __syncthreads();
    }
#pragma unroll
    for (int i = 0; i < 4; i++) {
        int r = row0 + ty * 4 + i;
#pragma unroll
        for (int j = 0; j < 4; j++) {
            int c = col0 + tx * 4 + j;
            if (c < N) Cp[(long)r * N + c] = acc[i][j] + bias[c];
        }
    }
}

// ---------------- persistent GRU: 100 blocks, manual grid barrier ----------------
__global__ __launch_bounds__(256) void gru_persist(const int* __restrict__ uid,
                                                   const float* __restrict__ user_emb,
                                                   const float* __restrict__ W_hh,
                                                   const float* __restrict__ b_hh,
                                                   const int* __restrict__ lens,
                                                   float* __restrict__ out) {
    __shared__ float s_w[3 * 4 * Gg];
    int tid = threadIdx.x, blk = blockIdx.x;
    int b = tid & 63, gi = tid >> 6;
    int g = blk * 4 + gi;
    for (int i = tid; i < 3 * 4 * Gg; i += 256) {
        int j = i / (4 * Gg); int rem = i - j * (4 * Gg);
        int gi2 = rem / Gg; int e = rem - gi2 * Gg;
        s_w[i] = W_hh[((long)j * Gg + blk * 4 + gi2) * Gg + e];
    }
    float bh_r = b_hh[g], bh_z = b_hh[Gg + g], bh_n = b_hh[2 * Gg + g];
    int len = lens[b];
    float myh = user_emb[(long)uid[b] * Gg + g];
    g_h[0][b * Gg + g] = myh;
    __syncthreads();

    const float4* wr4 = (const float4*)(s_w + gi * Gg);
    const float4* wz4 = (const float4*)(s_w + 4 * Gg + gi * Gg);
    const float4* wn4 = (const float4*)(s_w + 8 * Gg + gi * Gg);

    for (int n = 0; n < Nn; n++) {
        // ---- grid barrier n ----
        __threadfence();
        __syncthreads();
        if (tid == 0) {
            atomicAdd(&g_bar[n], 1);
            while (*((volatile int*)&g_bar[n]) < (int)gridDim.x) { }
        }
        __syncthreads();
        // ---- step ----
        const float* hin = g_h[n & 1];
        const float4* h4 = (const float4*)(hin + b * Gg);
        float hr = 0.f, hz = 0.f, hn = 0.f;
#pragma unroll 4
        for (int e4 = 0; e4 < Gg / 4; e4++) {
            float4 hv = __ldcg(h4 + e4);
            float4 a = wr4[e4], bz = wz4[e4], cn = wn4[e4];
            hr += a.x * hv.x + a.y * hv.y + a.z * hv.z + a.w * hv.w;
            hz += bz.x * hv.x + bz.y * hv.y + bz.z * hv.z + bz.w * hv.w;
            hn += cn.x * hv.x + cn.y * hv.y + cn.z * hv.z + cn.w * hv.w;
        }
        hr += bh_r; hz += bh_z; hn += bh_n;
        const float* gx = g_GX + (long)(b * Nn + n) * (3 * Gg);
        float xr = gx[g], xz = gx[Gg + g], xn = gx[2 * Gg + g];
        float r = 1.f / (1.f + __expf(-(xr + hr)));
        float z = 1.f / (1.f + __expf(-(xz + hz)));
        float nv = tanhf(xn + r * hn);
        float hnew = (1.f - z) * nv + z * myh;
        if (n < len) myh = hnew;
        g_h[(n + 1) & 1][b * Gg + g] = myh;
    }
    out[b * Gg + g] = myh;
}

// ---------------- launch ----------------
extern "C" void kernel_launch(void* const* d_in, const int* in_sizes, int n_in,
                              void* d_out, int out_size) {
    const int*   user_id  = (const int*)d_in[0];
    const int*   title    = (const int*)d_in[1];
    const int*   hist_len = (const int*)d_in[2];
    const float* word_emb = (const float*)d_in[3];
    const float* conv_w   = (const float*)d_in[4];
    const float* conv_b   = (const float*)d_in[5];
    const float* v        = (const float*)d_in[6];
    const float* vb       = (const float*)d_in[7];
    const float* q        = (const float*)d_in[8];
    const float* user_emb = (const float*)d_in[9];
    const float* W_ih     = (const float*)d_in[10];
    const float* W_hh     = (const float*)d_in[11];
    const float* b_ih     = (const float*)d_in[12];
    const float* b_hh     = (const float*)d_in[13];
    float* out = (float*)d_out;

    float *Xp, *Wpp, *Cp, *Ep, *GXp, *sc;
    int* bar;
    cudaGetSymbolAddress((void**)&Xp, g_X);
    cudaGetSymbolAddress((void**)&Wpp, g_Wp);
    cudaGetSymbolAddress((void**)&Cp, g_C);
    cudaGetSymbolAddress((void**)&Ep, g_E);
    cudaGetSymbolAddress((void**)&GXp, g_GX);
    cudaGetSymbolAddress((void**)&sc, g_scores);
    cudaGetSymbolAddress((void**)&bar, g_bar);

    gather_kernel<<<Bb * Nn, 256>>>(title, word_emb);
    wpad_kernel<<<(KC * FNf + 255) / 256, 256>>>(conv_w);
    cudaMemsetAsync(sc, 0, MROWS * sizeof(float));
    cudaMemsetAsync(bar, 0, 64 * sizeof(int));

    {   // conv: C[96000,400] = X @ Wp, tf32 tensor cores, bias+ReLU fused
        dim3 grid((FNf + 127) / 128, MROWS / 128);
        tf32gemm<0><<<grid, 256>>>(Xp, Wpp, Cp, conv_b, nullptr, FNf, KC);
    }
    {   // attention scores fused: tanh(C@v + vb) @ q -> g_scores
        dim3 grid((Aa + 127) / 128, MROWS / 128);
        tf32gemm<1><<<grid, 256>>>(Cp, v, nullptr, vb, q, Aa, FNf);
    }
    softmax_kernel<<<(Bb * Tt + 255) / 256, 256>>>();
    wsum_kernel<<<Bb * Nn, 128>>>();
    {   // GX = E @ W_ih^T + b_ih
        dim3 grid((3 * Gg + 63) / 64, (Bb * Nn) / 64);
        sgemm_nt_bias<<<grid, 256>>>(Ep, W_ih, GXp, b_ih, Bb * Nn, 3 * Gg, FNf);
    }
    gru_persist<<<100, 256>>>(user_id, user_emb, W_hh, b_hh, hist_len, out);
}

// round 5
// speedup vs baseline: 2.3345x; 1.1016x over previous
#include <cuda_runtime.h>
#include <cstdint>

#define Bb 64
#define Nn 50
#define Tt 30
#define Ee 300
#define EeP 304
#define FNf 400
#define Aa 200
#define Gg 400
#define KCv 912            // conv GEMM K = 3*304
#define MROWS (Bb*Nn*Tt)   // 96000
#define MTILE 256
#define LDK 20             // smem k-stride (16 + 4 pad) -> conflict-free
#define AST (MTILE*LDK)    // floats per A stage

// ---------------- scratch ----------------
__device__ float g_X[(long)Bb * Nn * 32 * EeP];   // gathered embeddings (RNA tf32-rounded)
__device__ float g_Wt[FNf * KCv];                 // conv weights [400 n][912 k] RNA
__device__ float g_vT[208 * 400];                 // v^T padded [208][400] RNA
__device__ float g_C[(long)MROWS * 400];          // conv out fp32
__device__ float g_scores[MROWS];
__device__ float g_alpha[MROWS];
__device__ float g_E[3328 * 400];                 // news embed (rows 3200+ stay 0)
__device__ float g_GXt[Nn * 1200 * Bb];           // transposed GX: [n][3G][b]
__device__ float g_h[2][Bb * Gg];
__device__ int   g_bar[64];

// ---------------- helpers ----------------
__device__ __forceinline__ float rna_tf32(float f) {
    uint32_t r; asm("cvt.rna.tf32.f32 %0, %1;" : "=r"(r) : "f"(f));
    return __uint_as_float(r);
}
__device__ __forceinline__ uint32_t smem_u32(const void* p) {
    uint32_t a;
    asm("{ .reg .u64 t; cvta.to.shared.u64 t, %1; cvt.u32.u64 %0, t; }" : "=r"(a) : "l"(p));
    return a;
}
__device__ __forceinline__ void cpasync16(uint32_t dst, const float* src) {
    asm volatile("cp.async.cg.shared.global [%0], [%1], 16;" :: "r"(dst), "l"(src));
}
__device__ __forceinline__ void cpcommit() { asm volatile("cp.async.commit_group;" ::: "memory"); }
template <int N> __device__ __forceinline__ void cpwait() {
    asm volatile("cp.async.wait_group %0;" :: "n"(N) : "memory");
}
__device__ __forceinline__ void mma1688(float* c, const uint32_t* a, uint32_t b0, uint32_t b1) {
    asm volatile("mma.sync.aligned.m16n8k8.row.col.f32.tf32.tf32.f32 "
                 "{%0,%1,%2,%3}, {%4,%5,%6,%7}, {%8,%9}, {%0,%1,%2,%3};"
                 : "+f"(c[0]), "+f"(c[1]), "+f"(c[2]), "+f"(c[3])
                 : "r"(a[0]), "r"(a[1]), "r"(a[2]), "r"(a[3]), "r"(b0), "r"(b1));
}

// ---------------- prep ----------------
__global__ __launch_bounds__(256) void gather_kernel(const int* __restrict__ title,
                                                     const float* __restrict__ word_emb) {
    int bn = blockIdx.x;
    float* X = g_X + (long)bn * 32 * EeP;
    for (int i = threadIdx.x; i < EeP; i += 256) { X[i] = 0.f; X[31 * EeP + i] = 0.f; }
    const int* tw = title + bn * Tt;
    for (int idx = threadIdx.x; idx < Tt * EeP; idx += 256) {
        int s = idx / EeP, e = idx - s * EeP;
        float v = (e < Ee) ? rna_tf32(word_emb[(long)tw[s] * Ee + e]) : 0.f;
        X[(s + 1) * EeP + e] = v;
    }
}
__global__ void wtr_kernel(const float* __restrict__ conv_w) {
    int i = blockIdx.x * 256 + threadIdx.x;
    if (i >= FNf * KCv) return;
    int n = i / KCv, k = i - n * KCv;
    int tap = k / EeP, e = k - tap * EeP;
    g_Wt[i] = (e < Ee) ? rna_tf32(conv_w[(tap * Ee + e) * FNf + n]) : 0.f;
}
__global__ void vtr_kernel(const float* __restrict__ v) {
    int i = blockIdx.x * 256 + threadIdx.x;
    if (i >= 208 * 400) return;
    int a = i / 400, f = i - a * 400;
    g_vT[i] = (a < Aa) ? rna_tf32(v[f * Aa + a]) : 0.f;
}

// ---------------- tf32 cp.async GEMM: 256 x (NT*16) tile ----------------
// EPI 0: conv rows via g_X map; bias+ReLU -> OutF [.][400]
// EPI 1: attn; tanh(+vb)*q row-reduce -> atomicAdd g_scores
// EPI 2: GX; bias; transposed store to g_GXt (guard r < 3200)
template <int NT, int EPI>
__global__ __launch_bounds__(256, 1) void tfgemm(const float* __restrict__ A,
                                                 const float* __restrict__ B,
                                                 float* __restrict__ OutF,
                                                 const float* __restrict__ bias,
                                                 const float* __restrict__ qv,
                                                 int colbase, int lda, int ldb,
                                                 int Ksteps, int Nvalid) {
    constexpr int NTILE = NT * 16;
    constexpr int BST = NTILE * LDK;
    constexpr int NB = NTILE * 4;          // 16B chunks per B stage
    extern __shared__ float dsm[];
    __shared__ float s_bias[128];
    __shared__ float s_qv[128];

    int tid = threadIdx.x, lane = tid & 31, wid = tid >> 5;
    int warpM = wid & 3, warpN = wid >> 2;
    int row0 = blockIdx.y * MTILE;
    int col0 = colbase + blockIdx.x * NTILE;

    for (int i = tid; i < NTILE; i += 256) {
        int c = col0 + i;
        s_bias[i] = (c < Nvalid) ? bias[c] : 0.f;
        if (EPI == 1) s_qv[i] = (c < Nvalid) ? qv[c] : 0.f;
    }

    uint32_t su = smem_u32(dsm);
    // A loader: 4 chunks/thread
    const float* aptr[4];
    uint32_t aoff[4];
#pragma unroll
    for (int j = 0; j < 4; j++) {
        int i = tid + j * 256;
        int m = i >> 2, kc = i & 3;
        int gr = row0 + m;
        long ro;
        if (EPI == 0) ro = (long)(gr / Tt) * (32 * EeP) + (long)(gr % Tt) * EeP;
        else          ro = (long)gr * lda;
        aptr[j] = A + ro + kc * 4;
        aoff[j] = (uint32_t)(m * LDK + kc * 4) * 4;
    }
    // B loader: up to 2 chunks/thread
    const float* bptr[2];
    uint32_t boff[2];
    bool bok[2];
#pragma unroll
    for (int j = 0; j < 2; j++) {
        int i = tid + j * 256;
        bok[j] = (i < NB);
        int n = i >> 2, kc = i & 3;
        if (!bok[j]) { n = 0; kc = 0; }
        bptr[j] = B + (long)(col0 + n) * ldb + kc * 4;
        boff[j] = (uint32_t)(n * LDK + kc * 4) * 4;
    }

    float acc[4][NT][4];
#pragma unroll
    for (int i = 0; i < 4; i++)
#pragma unroll
        for (int j = 0; j < NT; j++)
#pragma unroll
            for (int k = 0; k < 4; k++) acc[i][j][k] = 0.f;

#define LOAD_STAGE(s, buf)                                                      \
    {                                                                           \
        uint32_t ab = su + (uint32_t)(buf) * (AST * 4);                         \
        _Pragma("unroll")                                                       \
        for (int j = 0; j < 4; j++) cpasync16(ab + aoff[j], aptr[j] + (s) * 16);\
        uint32_t bb = su + (uint32_t)(3 * AST + (buf) * BST) * 4;               \
        _Pragma("unroll")                                                       \
        for (int j = 0; j < 2; j++)                                             \
            if (bok[j]) cpasync16(bb + boff[j], bptr[j] + (s) * 16);            \
        cpcommit();                                                             \
    }

    LOAD_STAGE(0, 0)
    LOAD_STAGE(1, 1)
    cpwait<1>();
    __syncthreads();

    // fragment base offsets (floats)
    int r4 = lane >> 2, c4 = lane & 3;
    int aFrag = (warpM * 64 + r4) * LDK + c4;
    int bFrag = 3 * AST + (warpN * NT * 8 + r4) * LDK + c4;

    for (int s = 0; s < Ksteps; s++) {
        int buf = s % 3;
        const float* Ab = dsm + buf * AST + aFrag;
        const float* Bbp = dsm + buf * BST + bFrag;
#pragma unroll
        for (int kh = 0; kh < 2; kh++) {
            const float* Ak = Ab + kh * 8;
            const float* Bk = Bbp + kh * 8;
            uint32_t af[4][4];
#pragma unroll
            for (int mt = 0; mt < 4; mt++) {
                const float* p = Ak + mt * 16 * LDK;
                af[mt][0] = __float_as_uint(p[0]);
                af[mt][1] = __float_as_uint(p[8 * LDK]);
                af[mt][2] = __float_as_uint(p[4]);
                af[mt][3] = __float_as_uint(p[8 * LDK + 4]);
            }
#pragma unroll
            for (int nt = 0; nt < NT; nt++) {
                const float* pb = Bk + nt * 8 * LDK;
                uint32_t b0 = __float_as_uint(pb[0]);
                uint32_t b1 = __float_as_uint(pb[4]);
#pragma unroll
                for (int mt = 0; mt < 4; mt++) mma1688(acc[mt][nt], af[mt], b0, b1);
            }
        }
        if (s + 2 < Ksteps) {
            int nb = (s + 2) % 3;
            LOAD_STAGE(s + 2, nb)
            cpwait<1>();
        } else {
            cpwait<0>();
        }
        __syncthreads();
    }
#undef LOAD_STAGE

    // ---------------- epilogues ----------------
    if (EPI == 0) {
#pragma unroll
        for (int mt = 0; mt < 4; mt++) {
            int r = row0 + warpM * 64 + mt * 16 + r4;
#pragma unroll
            for (int nt = 0; nt < NT; nt++) {
                int il = warpN * NT * 8 + nt * 8 + c4 * 2;
                int c = col0 + il;
                float b0 = s_bias[il], b1 = s_bias[il + 1];
                float2 v0 = make_float2(fmaxf(acc[mt][nt][0] + b0, 0.f),
                                        fmaxf(acc[mt][nt][1] + b1, 0.f));
                float2 v1 = make_float2(fmaxf(acc[mt][nt][2] + b0, 0.f),
                                        fmaxf(acc[mt][nt][3] + b1, 0.f));
                *(float2*)&OutF[(long)r * 400 + c] = v0;
                *(float2*)&OutF[(long)(r + 8) * 400 + c] = v1;
            }
        }
    } else if (EPI == 1) {
#pragma unroll
        for (int mt = 0; mt < 4; mt++) {
            float slo = 0.f, shi = 0.f;
#pragma unroll
            for (int nt = 0; nt < NT; nt++) {
                int il = warpN * NT * 8 + nt * 8 + c4 * 2;
                float v0 = s_bias[il], v1 = s_bias[il + 1];
                float q0 = s_qv[il], q1 = s_qv[il + 1];
                slo += tanhf(acc[mt][nt][0] + v0) * q0 + tanhf(acc[mt][nt][1] + v1) * q1;
                shi += tanhf(acc[mt][nt][2] + v0) * q0 + tanhf(acc[mt][nt][3] + v1) * q1;
            }
            slo += __shfl_xor_sync(0xffffffffu, slo, 1);
            slo += __shfl_xor_sync(0xffffffffu, slo, 2);
            shi += __shfl_xor_sync(0xffffffffu, shi, 1);
            shi += __shfl_xor_sync(0xffffffffu, shi, 2);
            if (c4 == 0) {
                int r = row0 + warpM * 64 + mt * 16 + r4;
                atomicAdd(&g_scores[r], slo);
                atomicAdd(&g_scores[r + 8], shi);
            }
        }
    } else {
#pragma unroll
        for (int mt = 0; mt < 4; mt++) {
            int r0 = row0 + warpM * 64 + mt * 16 + r4;
            int r1 = r0 + 8;
#pragma unroll
            for (int nt = 0; nt < NT; nt++) {
                int il = warpN * NT * 8 + nt * 8 + c4 * 2;
                int c = col0 + il;
                float b0 = s_bias[il], b1 = s_bias[il + 1];
                if (r0 < 3200) {
                    int bu = r0 / Nn, n_ = r0 - bu * Nn;
                    g_GXt[((long)n_ * 1200 + c) * Bb + bu] = acc[mt][nt][0] + b0;
                    g_GXt[((long)n_ * 1200 + c + 1) * Bb + bu] = acc[mt][nt][1] + b1;
                }
                if (r1 < 3200) {
                    int bu = r1 / Nn, n_ = r1 - bu * Nn;
                    g_GXt[((long)n_ * 1200 + c) * Bb + bu] = acc[mt][nt][2] + b0;
                    g_GXt[((long)n_ * 1200 + c + 1) * Bb + bu] = acc[mt][nt][3] + b1;
                }
            }
        }
    }
}

// ---------------- softmax over titles ----------------
__global__ void softmax_kernel() {
    int idx = blockIdx.x * blockDim.x + threadIdx.x;
    if (idx >= Bb * Tt) return;
    int b = idx / Tt, t = idx - b * Tt;
    const float* s = g_scores + b * Nn * Tt + t;
    float mx = -1e30f;
    for (int n = 0; n < Nn; n++) mx = fmaxf(mx, s[n * Tt]);
    float sum = 0.f;
    for (int n = 0; n < Nn; n++) sum += __expf(s[n * Tt] - mx);
    float inv = 1.f / sum;
    float* al = g_alpha + b * Nn * Tt + t;
    for (int n = 0; n < Nn; n++) al[n * Tt] = __expf(s[n * Tt] - mx) * inv;
}

// ---------------- weighted sum over words ----------------
__global__ __launch_bounds__(128) void wsum_kernel() {
    int bn = blockIdx.x;
    __shared__ float al[Tt];
    if (threadIdx.x < Tt) al[threadIdx.x] = g_alpha[bn * Tt + threadIdx.x];
    __syncthreads();
    const float* Cr = g_C + (long)bn * Tt * 400;
    for (int f = threadIdx.x; f < 400; f += 128) {
        float acc = 0.f;
#pragma unroll
        for (int t = 0; t < Tt; t++) acc += al[t] * Cr[t * 400 + f];
        g_E[bn * 400 + f] = acc;
    }
}

// ---------------- persistent GRU ----------------
__global__ __launch_bounds__(256) void gru_persist(const int* __restrict__ uid,
                                                   const float* __restrict__ user_emb,
                                                   const float* __restrict__ W_hh,
                                                   const float* __restrict__ b_ih,
                                                   const float* __restrict__ b_hh,
                                                   const int* __restrict__ lens,
                                                   float* __restrict__ out) {
    __shared__ float s_w[3 * 4 * Gg];
    int tid = threadIdx.x, blk = blockIdx.x;
    int b = tid & 63, gi = tid >> 6;
    int g = blk * 4 + gi;
    for (int i = tid; i < 3 * 4 * Gg; i += 256) {
        int j = i / (4 * Gg); int rem = i - j * (4 * Gg);
        int gi2 = rem / Gg; int e = rem - gi2 * Gg;
        s_w[i] = W_hh[((long)j * Gg + blk * 4 + gi2) * Gg + e];
    }
    float bi_r = b_ih[g], bi_z = b_ih[Gg + g], bi_n = b_ih[2 * Gg + g];
    float bh_r = b_hh[g], bh_z = b_hh[Gg + g], bh_n = b_hh[2 * Gg + g];
    int len = lens[b];
    float myh = user_emb[(long)uid[b] * Gg + g];
    g_h[0][b * Gg + g] = myh;
    __syncthreads();

    const float4* wr4 = (const float4*)(s_w + gi * Gg);
    const float4* wz4 = (const float4*)(s_w + 4 * Gg + gi * Gg);
    const float4* wn4 = (const float4*)(s_w + 8 * Gg + gi * Gg);

    for (int n = 0; n < Nn; n++) {
        __threadfence();
        __syncthreads();
        if (tid == 0) {
            atomicAdd(&g_bar[n], 1);
            while (*((volatile int*)&g_bar[n]) < (int)gridDim.x) { }
        }
        __syncthreads();
        const float* hin = g_h[n & 1];
        const float4* h4 = (const float4*)(hin + b * Gg);
        float hr = 0.f, hz = 0.f, hn = 0.f;
#pragma unroll 4
        for (int e4 = 0; e4 < Gg / 4; e4++) {
            float4 hv = __ldcg(h4 + e4);
            float4 a = wr4[e4], bz = wz4[e4], cn = wn4[e4];
            hr += a.x * hv.x + a.y * hv.y + a.z * hv.z + a.w * hv.w;
            hz += bz.x * hv.x + bz.y * hv.y + bz.z * hv.z + bz.w * hv.w;
            hn += cn.x * hv.x + cn.y * hv.y + cn.z * hv.z + cn.w * hv.w;
        }
        hr += bh_r; hz += bh_z; hn += bh_n;
        const float* gxt = g_GXt + (long)n * 1200 * Bb;
        float xr = gxt[(0 * Gg + g) * Bb + b] + bi_r;
        float xz = gxt[(1 * Gg + g) * Bb + b] + bi_z;
        float xn = gxt[(2 * Gg + g) * Bb + b] + bi_n;
        float r = 1.f / (1.f + __expf(-(xr + hr)));
        float z = 1.f / (1.f + __expf(-(xz + hz)));
        float nv = tanhf(xn + r * hn);
        float hnew = (1.f - z) * nv + z * myh;
        if (n < len) myh = hnew;
        g_h[(n + 1) & 1][b * Gg + g] = myh;
    }
    out[b * Gg + g] = myh;
}

// ---------------- launch ----------------
extern "C" void kernel_launch(void* const* d_in, const int* in_sizes, int n_in,
                              void* d_out, int out_size) {
    const int*   user_id  = (const int*)d_in[0];
    const int*   title    = (const int*)d_in[1];
    const int*   hist_len = (const int*)d_in[2];
    const float* word_emb = (const float*)d_in[3];
    const float* conv_w   = (const float*)d_in[4];
    const float* conv_b   = (const float*)d_in[5];
    const float* v        = (const float*)d_in[6];
    const float* vb       = (const float*)d_in[7];
    const float* q        = (const float*)d_in[8];
    const float* user_emb = (const float*)d_in[9];
    const float* W_ih     = (const float*)d_in[10];
    const float* W_hh     = (const float*)d_in[11];
    const float* b_ih     = (const float*)d_in[12];
    const float* b_hh     = (const float*)d_in[13];
    float* out = (float*)d_out;

    float *Xp, *Wtp, *vTp, *Cp, *Ep, *scp;
    int* bar;
    cudaGetSymbolAddress((void**)&Xp, g_X);
    cudaGetSymbolAddress((void**)&Wtp, g_Wt);
    cudaGetSymbolAddress((void**)&vTp, g_vT);
    cudaGetSymbolAddress((void**)&Cp, g_C);
    cudaGetSymbolAddress((void**)&Ep, g_E);
    cudaGetSymbolAddress((void**)&scp, g_scores);
    cudaGetSymbolAddress((void**)&bar, g_bar);

    auto smemsz = [](int nt) { return (3 * (AST + nt * 16 * LDK)) * (int)sizeof(float); };
    cudaFuncSetAttribute(tfgemm<5, 0>, cudaFuncAttributeMaxDynamicSharedMemorySize, smemsz(5));
    cudaFuncSetAttribute(tfgemm<8, 1>, cudaFuncAttributeMaxDynamicSharedMemorySize, smemsz(8));
    cudaFuncSetAttribute(tfgemm<5, 1>, cudaFuncAttributeMaxDynamicSharedMemorySize, smemsz(5));
    cudaFuncSetAttribute(tfgemm<8, 2>, cudaFuncAttributeMaxDynamicSharedMemorySize, smemsz(8));
    cudaFuncSetAttribute(tfgemm<3, 2>, cudaFuncAttributeMaxDynamicSharedMemorySize, smemsz(3));

    gather_kernel<<<Bb * Nn, 256>>>(title, word_emb);
    wtr_kernel<<<(FNf * KCv + 255) / 256, 256>>>(conv_w);
    vtr_kernel<<<(208 * 400 + 255) / 256, 256>>>(v);
    cudaMemsetAsync(scp, 0, MROWS * sizeof(float));
    cudaMemsetAsync(bar, 0, 64 * sizeof(int));

    // conv: C = X @ Wt^T + b, ReLU.  N = 5 x 80 cols, K = 912 (57 stages)
    tfgemm<5, 0><<<dim3(5, MROWS / MTILE), 256, smemsz(5)>>>(
        Xp, Wtp, Cp, conv_b, nullptr, 0, 0, KCv, 57, FNf);
    // attn: scores = sum tanh(C @ vT^T + vb) * q.  cols 0-127 then 128-207
    tfgemm<8, 1><<<dim3(1, MROWS / MTILE), 256, smemsz(8)>>>(
        Cp, vTp, nullptr, vb, q, 0, 400, 400, 25, Aa);
    tfgemm<5, 1><<<dim3(1, MROWS / MTILE), 256, smemsz(5)>>>(
        Cp, vTp, nullptr, vb, q, 128, 400, 400, 25, Aa);

    softmax_kernel<<<(Bb * Tt + 255) / 256, 256>>>();
    wsum_kernel<<<Bb * Nn, 128>>>();

    // GX^T: (E @ W_ih^T + b_ih) transposed. N = 9x128 + 48, M = 13 x 256 (3328)
    tfgemm<8, 2><<<dim3(9, 13), 256, smemsz(8)>>>(
        Ep, W_ih, nullptr, b_ih, nullptr, 0, 400, 400, 25, 1200);
    tfgemm<3, 2><<<dim3(1, 13), 256, smemsz(3)>>>(
        Ep, W_ih, nullptr, b_ih, nullptr, 1152, 400, 400, 25, 1200);

    gru_persist<<<100, 256>>>(user_id, user_emb, W_hh, b_ih, b_hh, hist_len, out);
}

// round 6
// speedup vs baseline: 2.4358x; 1.0434x over previous
#include <cuda_runtime.h>
#include <cstdint>

#define Bb 64
#define Nn 50
#define Tt 30
#define Ee 300
#define EeP 304
#define FNf 400
#define Aa 200
#define Gg 400
#define KCv 912            // conv GEMM K = 3*304
#define MROWS (Bb*Nn*Tt)   // 96000
#define LDK 20             // smem k-stride (16 + 4 pad) -> conflict-free

// ---------------- scratch ----------------
__device__ float g_X[(long)Bb * Nn * 32 * EeP];   // gathered embeddings (RNA)
__device__ float g_Wt[FNf * KCv];                 // conv weights [400][912] RNA
__device__ float g_vT[208 * 400];                 // v^T padded [208][400] RNA
__device__ float g_Wihr[1200 * 400];              // W_ih RNA copy
__device__ float g_C[(long)MROWS * 400];          // conv out (RNA-rounded)
__device__ float g_scores[MROWS];
__device__ float g_alpha[MROWS];
__device__ float g_E[3328 * 400];                 // news embed (RNA; rows 3200+ zero)
__device__ float g_GXt[Nn * 1200 * Bb];           // transposed GX: [n][3G][b]
__device__ float g_h[2][Bb * Gg];
__device__ int   g_bar[64];

// ---------------- helpers ----------------
__device__ __forceinline__ float rna_tf32(float f) {
    uint32_t r; asm("cvt.rna.tf32.f32 %0, %1;" : "=r"(r) : "f"(f));
    return __uint_as_float(r);
}
__device__ __forceinline__ uint32_t smem_u32(const void* p) {
    uint32_t a;
    asm("{ .reg .u64 t; cvta.to.shared.u64 t, %1; cvt.u32.u64 %0, t; }" : "=r"(a) : "l"(p));
    return a;
}
__device__ __forceinline__ void cpasync16(uint32_t dst, const float* src) {
    asm volatile("cp.async.cg.shared.global [%0], [%1], 16;" :: "r"(dst), "l"(src));
}
__device__ __forceinline__ void cpcommit() { asm volatile("cp.async.commit_group;" ::: "memory"); }
template <int N> __device__ __forceinline__ void cpwait() {
    asm volatile("cp.async.wait_group %0;" :: "n"(N) : "memory");
}
__device__ __forceinline__ void mma1688(float* c, const uint32_t* a, uint32_t b0, uint32_t b1) {
    asm volatile("mma.sync.aligned.m16n8k8.row.col.f32.tf32.tf32.f32 "
                 "{%0,%1,%2,%3}, {%4,%5,%6,%7}, {%8,%9}, {%0,%1,%2,%3};"
                 : "+f"(c[0]), "+f"(c[1]), "+f"(c[2]), "+f"(c[3])
                 : "r"(a[0]), "r"(a[1]), "r"(a[2]), "r"(a[3]), "r"(b0), "r"(b1));
}

// ---------------- prep ----------------
__global__ __launch_bounds__(256) void gather_kernel(const int* __restrict__ title,
                                                     const float* __restrict__ word_emb) {
    int bn = blockIdx.x;
    float* X = g_X + (long)bn * 32 * EeP;
    for (int i = threadIdx.x; i < EeP; i += 256) { X[i] = 0.f; X[31 * EeP + i] = 0.f; }
    const int* tw = title + bn * Tt;
    for (int idx = threadIdx.x; idx < Tt * EeP; idx += 256) {
        int s = idx / EeP, e = idx - s * EeP;
        float v = (e < Ee) ? rna_tf32(word_emb[(long)tw[s] * Ee + e]) : 0.f;
        X[(s + 1) * EeP + e] = v;
    }
}
__global__ void wtr_kernel(const float* __restrict__ conv_w) {
    int i = blockIdx.x * 256 + threadIdx.x;
    if (i >= FNf * KCv) return;
    int n = i / KCv, k = i - n * KCv;
    int tap = k / EeP, e = k - tap * EeP;
    g_Wt[i] = (e < Ee) ? rna_tf32(conv_w[(tap * Ee + e) * FNf + n]) : 0.f;
}
__global__ void vtr_kernel(const float* __restrict__ v) {
    int i = blockIdx.x * 256 + threadIdx.x;
    if (i >= 208 * 400) return;
    int a = i / 400, f = i - a * 400;
    g_vT[i] = (a < Aa) ? rna_tf32(v[f * Aa + a]) : 0.f;
}
__global__ void wihr_kernel(const float* __restrict__ W_ih) {
    int i = blockIdx.x * 256 + threadIdx.x;
    if (i >= 1200 * 400) return;
    g_Wihr[i] = rna_tf32(W_ih[i]);
}

// ---------------- tf32 cp.async GEMM: MT x (NT*16) tile, 3-stage ----------------
// EPI 0: conv rows via g_X map; bias+ReLU+RNA -> OutF[.][400]
// EPI 1: attn; tanh(+vb)*q block-reduce -> OutF[row] (g_scores)
// EPI 2: GX; bias; transposed store to g_GXt (guard r < 3200)
template <int MT, int NT, int EPI, int MINB>
__global__ __launch_bounds__(256, MINB) void tfgemm(const float* __restrict__ A,
                                                    const float* __restrict__ B,
                                                    float* __restrict__ OutF,
                                                    const float* __restrict__ bias,
                                                    const float* __restrict__ qv,
                                                    int colbase, int lda, int ldb,
                                                    int Ksteps, int Nvalid) {
    constexpr int NTILE = NT * 16;
    constexpr int ASTt = MT * LDK;
    constexpr int BST = NTILE * LDK;
    constexpr int ACH = MT / 64;                 // A 16B chunks per thread
    constexpr int BCH = (NTILE * 4 + 255) / 256; // B 16B chunks per thread
    constexpr int NB = NTILE * 4;
    constexpr int MTt = MT / 64;                 // m subtiles per warp
    extern __shared__ float dsm[];
    __shared__ float s_bias[224];
    __shared__ float s_qv[224];
    __shared__ float s_red[256];

    int tid = threadIdx.x, lane = tid & 31, wid = tid >> 5;
    int warpM = wid & 3, warpN = wid >> 2;
    int row0 = blockIdx.y * MT;
    int col0 = colbase + blockIdx.x * NTILE;

    for (int i = tid; i < NTILE; i += 256) {
        int c = col0 + i;
        s_bias[i] = (c < Nvalid) ? bias[c] : 0.f;
        if (EPI == 1) s_qv[i] = (c < Nvalid) ? qv[c] : 0.f;
    }
    if (EPI == 1) for (int i = tid; i < MT; i += 256) s_red[i] = 0.f;

    uint32_t su = smem_u32(dsm);
    const float* aptr[ACH];
    uint32_t aoff[ACH];
#pragma unroll
    for (int j = 0; j < ACH; j++) {
        int i = tid + j * 256;
        int m = i >> 2, kc = i & 3;
        int gr = row0 + m;
        long ro;
        if (EPI == 0) ro = (long)(gr / Tt) * (32 * EeP) + (long)(gr % Tt) * EeP;
        else          ro = (long)gr * lda;
        aptr[j] = A + ro + kc * 4;
        aoff[j] = (uint32_t)(m * LDK + kc * 4) * 4;
    }
    const float* bptr[BCH];
    uint32_t boff[BCH];
    bool bok[BCH];
#pragma unroll
    for (int j = 0; j < BCH; j++) {
        int i = tid + j * 256;
        bok[j] = (i < NB);
        int n = i >> 2, kc = i & 3;
        if (!bok[j]) { n = 0; kc = 0; }
        bptr[j] = B + (long)(col0 + n) * ldb + kc * 4;
        boff[j] = (uint32_t)(n * LDK + kc * 4) * 4;
    }

    float acc[MTt][NT][4];
#pragma unroll
    for (int i = 0; i < MTt; i++)
#pragma unroll
        for (int j = 0; j < NT; j++)
#pragma unroll
            for (int k = 0; k < 4; k++) acc[i][j][k] = 0.f;

#define LOAD_STAGE(s, buf)                                                       \
    {                                                                            \
        uint32_t ab = su + (uint32_t)(buf) * (ASTt * 4);                         \
        _Pragma("unroll")                                                        \
        for (int j = 0; j < ACH; j++) cpasync16(ab + aoff[j], aptr[j] + (s) * 16);\
        uint32_t bb = su + (uint32_t)(3 * ASTt + (buf) * BST) * 4;               \
        _Pragma("unroll")                                                        \
        for (int j = 0; j < BCH; j++)                                            \
            if (bok[j]) cpasync16(bb + boff[j], bptr[j] + (s) * 16);             \
        cpcommit();                                                              \
    }

    LOAD_STAGE(0, 0)
    LOAD_STAGE(1, 1)
    cpwait<1>();
    __syncthreads();

    int r4 = lane >> 2, c4 = lane & 3;
    int aFrag = (warpM * (MT / 4) + r4) * LDK + c4;
    int bFrag = 3 * ASTt + (warpN * NT * 8 + r4) * LDK + c4;

    for (int s = 0; s < Ksteps; s++) {
        int buf = s % 3;
        const float* Ab = dsm + buf * ASTt + aFrag;
        const float* Bbp = dsm + buf * BST + bFrag;
#pragma unroll
        for (int kh = 0; kh < 2; kh++) {
            const float* Ak = Ab + kh * 8;
            const float* Bk = Bbp + kh * 8;
            uint32_t af[MTt][4];
#pragma unroll
            for (int mt = 0; mt < MTt; mt++) {
                const float* p = Ak + mt * 16 * LDK;
                af[mt][0] = __float_as_uint(p[0]);
                af[mt][1] = __float_as_uint(p[8 * LDK]);
                af[mt][2] = __float_as_uint(p[4]);
                af[mt][3] = __float_as_uint(p[8 * LDK + 4]);
            }
#pragma unroll
            for (int nt = 0; nt < NT; nt++) {
                const float* pb = Bk + nt * 8 * LDK;
                uint32_t b0 = __float_as_uint(pb[0]);
                uint32_t b1 = __float_as_uint(pb[4]);
#pragma unroll
                for (int mt = 0; mt < MTt; mt++) mma1688(acc[mt][nt], af[mt], b0, b1);
            }
        }
        if (s + 2 < Ksteps) {
            int nb = (s + 2) % 3;
            LOAD_STAGE(s + 2, nb)
            cpwait<1>();
        } else {
            cpwait<0>();
        }
        __syncthreads();
    }
#undef LOAD_STAGE

    // ---------------- epilogues ----------------
    if (EPI == 0) {
#pragma unroll
        for (int mt = 0; mt < MTt; mt++) {
            int r = row0 + warpM * (MT / 4) + mt * 16 + r4;
#pragma unroll
            for (int nt = 0; nt < NT; nt++) {
                int il = warpN * NT * 8 + nt * 8 + c4 * 2;
                int c = col0 + il;
                float b0 = s_bias[il], b1 = s_bias[il + 1];
                float2 v0 = make_float2(rna_tf32(fmaxf(acc[mt][nt][0] + b0, 0.f)),
                                        rna_tf32(fmaxf(acc[mt][nt][1] + b1, 0.f)));
                float2 v1 = make_float2(rna_tf32(fmaxf(acc[mt][nt][2] + b0, 0.f)),
                                        rna_tf32(fmaxf(acc[mt][nt][3] + b1, 0.f)));
                *(float2*)&OutF[(long)r * 400 + c] = v0;
                *(float2*)&OutF[(long)(r + 8) * 400 + c] = v1;
            }
        }
    } else if (EPI == 1) {
#pragma unroll
        for (int mt = 0; mt < MTt; mt++) {
            float slo = 0.f, shi = 0.f;
#pragma unroll
            for (int nt = 0; nt < NT; nt++) {
                int il = warpN * NT * 8 + nt * 8 + c4 * 2;
                float v0 = s_bias[il], v1 = s_bias[il + 1];
                float q0 = s_qv[il], q1 = s_qv[il + 1];
                slo += tanhf(acc[mt][nt][0] + v0) * q0 + tanhf(acc[mt][nt][1] + v1) * q1;
                shi += tanhf(acc[mt][nt][2] + v0) * q0 + tanhf(acc[mt][nt][3] + v1) * q1;
            }
            slo += __shfl_xor_sync(0xffffffffu, slo, 1);
            slo += __shfl_xor_sync(0xffffffffu, slo, 2);
            shi += __shfl_xor_sync(0xffffffffu, shi, 1);
            shi += __shfl_xor_sync(0xffffffffu, shi, 2);
            if (c4 == 0) {
                int rl = warpM * (MT / 4) + mt * 16 + r4;
                atomicAdd(&s_red[rl], slo);
                atomicAdd(&s_red[rl + 8], shi);
            }
        }
        __syncthreads();
        for (int i = tid; i < MT; i += 256) OutF[row0 + i] = s_red[i];
    } else {
#pragma unroll
        for (int mt = 0; mt < MTt; mt++) {
            int r0 = row0 + warpM * (MT / 4) + mt * 16 + r4;
            int r1 = r0 + 8;
#pragma unroll
            for (int nt = 0; nt < NT; nt++) {
                int il = warpN * NT * 8 + nt * 8 + c4 * 2;
                int c = col0 + il;
                float b0 = s_bias[il], b1 = s_bias[il + 1];
                if (r0 < 3200) {
                    int bu = r0 / Nn, n_ = r0 - bu * Nn;
                    g_GXt[((long)n_ * 1200 + c) * Bb + bu] = acc[mt][nt][0] + b0;
                    g_GXt[((long)n_ * 1200 + c + 1) * Bb + bu] = acc[mt][nt][1] + b1;
                }
                if (r1 < 3200) {
                    int bu = r1 / Nn, n_ = r1 - bu * Nn;
                    g_GXt[((long)n_ * 1200 + c) * Bb + bu] = acc[mt][nt][2] + b0;
                    g_GXt[((long)n_ * 1200 + c + 1) * Bb + bu] = acc[mt][nt][3] + b1;
                }
            }
        }
    }
}

// ---------------- softmax over titles ----------------
__global__ void softmax_kernel() {
    int idx = blockIdx.x * blockDim.x + threadIdx.x;
    if (idx >= Bb * Tt) return;
    int b = idx / Tt, t = idx - b * Tt;
    const float* s = g_scores + b * Nn * Tt + t;
    float mx = -1e30f;
    for (int n = 0; n < Nn; n++) mx = fmaxf(mx, s[n * Tt]);
    float sum = 0.f;
    for (int n = 0; n < Nn; n++) sum += __expf(s[n * Tt] - mx);
    float inv = 1.f / sum;
    float* al = g_alpha + b * Nn * Tt + t;
    for (int n = 0; n < Nn; n++) al[n * Tt] = __expf(s[n * Tt] - mx) * inv;
}

// ---------------- weighted sum over words (RNA-rounded E) ----------------
__global__ __launch_bounds__(128) void wsum_kernel() {
    int bn = blockIdx.x;
    __shared__ float al[Tt];
    if (threadIdx.x < Tt) al[threadIdx.x] = g_alpha[bn * Tt + threadIdx.x];
    __syncthreads();
    const float* Cr = g_C + (long)bn * Tt * 400;
    for (int f = threadIdx.x; f < 400; f += 128) {
        float acc = 0.f;
#pragma unroll
        for (int t = 0; t < Tt; t++) acc += al[t] * Cr[t * 400 + f];
        g_E[bn * 400 + f] = rna_tf32(acc);
    }
}

// ---------------- persistent GRU ----------------
__global__ __launch_bounds__(256) void gru_persist(const int* __restrict__ uid,
                                                   const float* __restrict__ user_emb,
                                                   const float* __restrict__ W_hh,
                                                   const float* __restrict__ b_ih,
                                                   const float* __restrict__ b_hh,
                                                   const int* __restrict__ lens,
                                                   float* __restrict__ out) {
    __shared__ float s_w[3 * 4 * Gg];
    int tid = threadIdx.x, blk = blockIdx.x;
    int b = tid & 63, gi = tid >> 6;
    int g = blk * 4 + gi;
    for (int i = tid; i < 3 * 4 * Gg; i += 256) {
        int j = i / (4 * Gg); int rem = i - j * (4 * Gg);
        int gi2 = rem / Gg; int e = rem - gi2 * Gg;
        s_w[i] = W_hh[((long)j * Gg + blk * 4 + gi2) * Gg + e];
    }
    float bi_r = b_ih[g], bi_z = b_ih[Gg + g], bi_n = b_ih[2 * Gg + g];
    float bh_r = b_hh[g], bh_z = b_hh[Gg + g], bh_n = b_hh[2 * Gg + g];
    int len = lens[b];
    float myh = user_emb[(long)uid[b] * Gg + g];
    g_h[0][b * Gg + g] = myh;
    __syncthreads();

    const float4* wr4 = (const float4*)(s_w + gi * Gg);
    const float4* wz4 = (const float4*)(s_w + 4 * Gg + gi * Gg);
    const float4* wn4 = (const float4*)(s_w + 8 * Gg + gi * Gg);

    for (int n = 0; n < Nn; n++) {
        __threadfence();
        __syncthreads();
        if (tid == 0) {
            atomicAdd(&g_bar[n], 1);
            while (*((volatile int*)&g_bar[n]) < (int)gridDim.x) { }
        }
        __syncthreads();
        const float* hin = g_h[n & 1];
        const float4* h4 = (const float4*)(hin + b * Gg);
        float hr = 0.f, hz = 0.f, hn = 0.f;
#pragma unroll 4
        for (int e4 = 0; e4 < Gg / 4; e4++) {
            float4 hv = __ldcg(h4 + e4);
            float4 a = wr4[e4], bz = wz4[e4], cn = wn4[e4];
            hr += a.x * hv.x + a.y * hv.y + a.z * hv.z + a.w * hv.w;
            hz += bz.x * hv.x + bz.y * hv.y + bz.z * hv.z + bz.w * hv.w;
            hn += cn.x * hv.x + cn.y * hv.y + cn.z * hv.z + cn.w * hv.w;
        }
        hr += bh_r; hz += bh_z; hn += bh_n;
        const float* gxt = g_GXt + (long)n * 1200 * Bb;
        float xr = gxt[(0 * Gg + g) * Bb + b] + bi_r;
        float xz = gxt[(1 * Gg + g) * Bb + b] + bi_z;
        float xn = gxt[(2 * Gg + g) * Bb + b] + bi_n;
        float r = 1.f / (1.f + __expf(-(xr + hr)));
        float z = 1.f / (1.f + __expf(-(xz + hz)));
        float nv = tanhf(xn + r * hn);
        float hnew = (1.f - z) * nv + z * myh;
        if (n < len) myh = hnew;
        g_h[(n + 1) & 1][b * Gg + g] = myh;
    }
    out[b * Gg + g] = myh;
}

// ---------------- launch ----------------
extern "C" void kernel_launch(void* const* d_in, const int* in_sizes, int n_in,
                              void* d_out, int out_size) {
    const int*   user_id  = (const int*)d_in[0];
    const int*   title    = (const int*)d_in[1];
    const int*   hist_len = (const int*)d_in[2];
    const float* word_emb = (const float*)d_in[3];
    const float* conv_w   = (const float*)d_in[4];
    const float* conv_b   = (const float*)d_in[5];
    const float* v        = (const float*)d_in[6];
    const float* vb       = (const float*)d_in[7];
    const float* q        = (const float*)d_in[8];
    const float* user_emb = (const float*)d_in[9];
    const float* W_ih     = (const float*)d_in[10];
    const float* W_hh     = (const float*)d_in[11];
    const float* b_ih     = (const float*)d_in[12];
    const float* b_hh     = (const float*)d_in[13];
    float* out = (float*)d_out;

    float *Xp, *Wtp, *vTp, *Wihp, *Cp, *Ep, *scp;
    int* bar;
    cudaGetSymbolAddress((void**)&Xp, g_X);
    cudaGetSymbolAddress((void**)&Wtp, g_Wt);
    cudaGetSymbolAddress((void**)&vTp, g_vT);
    cudaGetSymbolAddress((void**)&Wihp, g_Wihr);
    cudaGetSymbolAddress((void**)&Cp, g_C);
    cudaGetSymbolAddress((void**)&Ep, g_E);
    cudaGetSymbolAddress((void**)&scp, g_scores);
    cudaGetSymbolAddress((void**)&bar, g_bar);

    auto smemsz = [](int mt, int nt) {
        return (3 * (mt * LDK + nt * 16 * LDK)) * (int)sizeof(float);
    };
    cudaFuncSetAttribute((const void*)tfgemm<128, 5, 0, 2>,
                         cudaFuncAttributeMaxDynamicSharedMemorySize, smemsz(128, 5));
    cudaFuncSetAttribute((const void*)tfgemm<128, 13, 1, 1>,
                         cudaFuncAttributeMaxDynamicSharedMemorySize, smemsz(128, 13));
    cudaFuncSetAttribute((const void*)tfgemm<256, 8, 2, 1>,
                         cudaFuncAttributeMaxDynamicSharedMemorySize, smemsz(256, 8));
    cudaFuncSetAttribute((const void*)tfgemm<256, 3, 2, 1>,
                         cudaFuncAttributeMaxDynamicSharedMemorySize, smemsz(256, 3));

    gather_kernel<<<Bb * Nn, 256>>>(title, word_emb);
    wtr_kernel<<<(FNf * KCv + 255) / 256, 256>>>(conv_w);
    vtr_kernel<<<(208 * 400 + 255) / 256, 256>>>(v);
    wihr_kernel<<<(1200 * 400 + 255) / 256, 256>>>(W_ih);
    cudaMemsetAsync(bar, 0, 64 * sizeof(int));

    // conv: C = X @ Wt^T + b, ReLU, RNA.  MT=128, N = 5 x 80 cols, K=912 (57 stages)
    tfgemm<128, 5, 0, 2><<<dim3(5, MROWS / 128), 256, smemsz(128, 5)>>>(
        Xp, Wtp, Cp, conv_b, nullptr, 0, 0, KCv, 57, FNf);
    // attn (single kernel): scores = sum_c tanh(C @ vT^T + vb) * q, all 208 cols
    tfgemm<128, 13, 1, 1><<<dim3(1, MROWS / 128), 256, smemsz(128, 13)>>>(
        Cp, vTp, scp, vb, q, 0, 400, 400, 25, Aa);

    softmax_kernel<<<(Bb * Tt + 255) / 256, 256>>>();
    wsum_kernel<<<Bb * Nn, 128>>>();

    // GX^T: (E @ W_ih^T + b_ih) transposed. N = 9x128 + 48, M = 13 x 256
    tfgemm<256, 8, 2, 1><<<dim3(9, 13), 256, smemsz(256, 8)>>>(
        Ep, Wihp, nullptr, b_ih, nullptr, 0, 400, 400, 25, 1200);
    tfgemm<256, 3, 2, 1><<<dim3(1, 13), 256, smemsz(256, 3)>>>(
        Ep, Wihp, nullptr, b_ih, nullptr, 1152, 400, 400, 25, 1200);

    gru_persist<<<100, 256>>>(user_id, user_emb, W_hh, b_ih, b_hh, hist_len, out);
}

// round 7
// speedup vs baseline: 2.8209x; 1.1581x over previous
#include <cuda_runtime.h>
#include <cuda_fp16.h>
#include <cstdint>

#define Bb 64
#define Nn 50
#define Tt 30
#define Ee 300
#define EeP 320
#define FNf 400
#define Aa 200
#define Gg 400
#define KCv 960            // conv GEMM K = 3*320
#define KP 416             // padded K for attn/GX
#define MROWS (Bb*Nn*Tt)   // 96000
#define LDKH 40            // smem k-stride in halves (32 + 8 pad)

// ---------------- scratch ----------------
__device__ __half g_X[(long)Bb * Nn * 32 * EeP];   // gathered embeddings
__device__ __half g_Wt[FNf * KCv];                 // conv weights [400][960]
__device__ __half g_vT[208 * KP];                  // v^T padded [208][416]
__device__ __half g_Wih[1200 * KP];                // W_ih padded [1200][416]
__device__ __half g_C[(long)MROWS * KP];           // conv out [96000][416]
__device__ float  g_scores[MROWS];
__device__ float  g_alpha[MROWS];
__device__ __half g_E[3328 * KP];                  // news embed (rows>=3200 zero)
__device__ float  g_GXt[Nn * 1200 * Bb];           // transposed GX: [n][3G][b]
__device__ float  g_h[2][Bb * Gg];
__device__ int    g_bar[64];

// ---------------- helpers ----------------
__device__ __forceinline__ uint32_t smem_u32(const void* p) {
    uint32_t a;
    asm("{ .reg .u64 t; cvta.to.shared.u64 t, %1; cvt.u32.u64 %0, t; }" : "=r"(a) : "l"(p));
    return a;
}
__device__ __forceinline__ void cpasync16(uint32_t dst, const void* src) {
    asm volatile("cp.async.cg.shared.global [%0], [%1], 16;" :: "r"(dst), "l"(src));
}
__device__ __forceinline__ void cpcommit() { asm volatile("cp.async.commit_group;" ::: "memory"); }
template <int N> __device__ __forceinline__ void cpwait() {
    asm volatile("cp.async.wait_group %0;" :: "n"(N) : "memory");
}
__device__ __forceinline__ void mma16816(float* c, const uint32_t* a, uint32_t b0, uint32_t b1) {
    asm volatile("mma.sync.aligned.m16n8k16.row.col.f32.f16.f16.f32 "
                 "{%0,%1,%2,%3}, {%4,%5,%6,%7}, {%8,%9}, {%0,%1,%2,%3};"
                 : "+f"(c[0]), "+f"(c[1]), "+f"(c[2]), "+f"(c[3])
                 : "r"(a[0]), "r"(a[1]), "r"(a[2]), "r"(a[3]), "r"(b0), "r"(b1));
}

// ---------------- prep ----------------
__global__ __launch_bounds__(256) void gather_kernel(const int* __restrict__ title,
                                                     const float* __restrict__ word_emb) {
    int bn = blockIdx.x;
    __half* X = g_X + (long)bn * 32 * EeP;
    const __half z = __float2half(0.f);
    for (int i = threadIdx.x; i < EeP; i += 256) { X[i] = z; X[31 * EeP + i] = z; }
    const int* tw = title + bn * Tt;
    for (int idx = threadIdx.x; idx < Tt * EeP; idx += 256) {
        int s = idx / EeP, e = idx - s * EeP;
        float v = (e < Ee) ? word_emb[(long)tw[s] * Ee + e] : 0.f;
        X[(s + 1) * EeP + e] = __float2half_rn(v);
    }
}
__global__ void wtr_kernel(const float* __restrict__ conv_w) {
    int i = blockIdx.x * 256 + threadIdx.x;
    if (i >= FNf * KCv) return;
    int n = i / KCv, k = i - n * KCv;
    int tap = k / EeP, e = k - tap * EeP;
    float v = (e < Ee) ? conv_w[(tap * Ee + e) * FNf + n] : 0.f;
    g_Wt[i] = __float2half_rn(v);
}
__global__ void vtr_kernel(const float* __restrict__ v) {
    int i = blockIdx.x * 256 + threadIdx.x;
    if (i >= 208 * KP) return;
    int a = i / KP, f = i - a * KP;
    float x = (a < Aa && f < FNf) ? v[f * Aa + a] : 0.f;
    g_vT[i] = __float2half_rn(x);
}
__global__ void wihh_kernel(const float* __restrict__ W_ih) {
    int i = blockIdx.x * 256 + threadIdx.x;
    if (i >= 1200 * KP) return;
    int n = i / KP, k = i - n * KP;
    float x = (k < FNf) ? W_ih[n * FNf + k] : 0.f;
    g_Wih[i] = __float2half_rn(x);
}

// ---------------- fp16 cp.async GEMM: MT x (NT*16) tile, K-stage 32, 3-stage ----------------
// EPI 0: conv rows via g_X map; bias+ReLU -> half OutH[.][416]
// EPI 1: attn; tanh(+vb)*q block-reduce -> OutF[row] (g_scores)
// EPI 2: GX; bias; transposed fp32 store to g_GXt (guard r < 3200)
template <int MT, int NT, int EPI, int MINB>
__global__ __launch_bounds__(256, MINB) void hgemm(const __half* __restrict__ A,
                                                   const __half* __restrict__ B,
                                                   float* __restrict__ OutF,
                                                   __half* __restrict__ OutH,
                                                   const float* __restrict__ bias,
                                                   const float* __restrict__ qv,
                                                   int colbase, int lda, int ldb,
                                                   int Ksteps, int Nvalid) {
    constexpr int NTILE = NT * 16;
    constexpr int ASTh = MT * LDKH;              // halves per A stage
    constexpr int BSTh = NTILE * LDKH;
    constexpr int ACH = MT / 64;                 // A 16B chunks per thread
    constexpr int BCH = (NTILE * 4 + 255) / 256;
    constexpr int NB = NTILE * 4;
    constexpr int MTt = MT / 64;
    extern __shared__ __half dsm[];
    __shared__ float s_bias[224];
    __shared__ float s_qv[224];
    __shared__ float s_red[256];

    int tid = threadIdx.x, lane = tid & 31, wid = tid >> 5;
    int warpM = wid & 3, warpN = wid >> 2;
    int row0 = blockIdx.y * MT;
    int col0 = colbase + blockIdx.x * NTILE;

    for (int i = tid; i < NTILE; i += 256) {
        int c = col0 + i;
        s_bias[i] = (c < Nvalid) ? bias[c] : 0.f;
        if (EPI == 1) s_qv[i] = (c < Nvalid) ? qv[c] : 0.f;
    }
    if (EPI == 1) for (int i = tid; i < MT; i += 256) s_red[i] = 0.f;

    uint32_t su = smem_u32(dsm);
    const __half* aptr[ACH];
    uint32_t aoff[ACH];
#pragma unroll
    for (int j = 0; j < ACH; j++) {
        int i = tid + j * 256;
        int m = i >> 2, kc = i & 3;
        int gr = row0 + m;
        long ro;
        if (EPI == 0) ro = (long)(gr / Tt) * (32 * EeP) + (long)(gr % Tt) * EeP;
        else          ro = (long)gr * lda;
        aptr[j] = A + ro + kc * 8;
        aoff[j] = (uint32_t)(m * 80 + kc * 16);          // bytes
    }
    const __half* bptr[BCH];
    uint32_t boff[BCH];
    bool bok[BCH];
#pragma unroll
    for (int j = 0; j < BCH; j++) {
        int i = tid + j * 256;
        bok[j] = (i < NB);
        int n = i >> 2, kc = i & 3;
        if (!bok[j]) { n = 0; kc = 0; }
        bptr[j] = B + (long)(col0 + n) * ldb + kc * 8;
        boff[j] = (uint32_t)(n * 80 + kc * 16);
    }

    float acc[MTt][NT][4];
#pragma unroll
    for (int i = 0; i < MTt; i++)
#pragma unroll
        for (int j = 0; j < NT; j++)
#pragma unroll
            for (int k = 0; k < 4; k++) acc[i][j][k] = 0.f;

#define LOAD_STAGE(s, buf)                                                        \
    {                                                                             \
        uint32_t ab = su + (uint32_t)(buf) * (ASTh * 2);                          \
        _Pragma("unroll")                                                         \
        for (int j = 0; j < ACH; j++) cpasync16(ab + aoff[j], aptr[j] + (s) * 32);\
        uint32_t bb = su + (uint32_t)(3 * ASTh + (buf) * BSTh) * 2;               \
        _Pragma("unroll")                                                         \
        for (int j = 0; j < BCH; j++)                                             \
            if (bok[j]) cpasync16(bb + boff[j], bptr[j] + (s) * 32);              \
        cpcommit();                                                               \
    }

    LOAD_STAGE(0, 0)
    LOAD_STAGE(1, 1)
    cpwait<1>();
    __syncthreads();

    int r4 = lane >> 2, c4 = lane & 3;
    // fragment base offsets in halves
    int aFrag = (warpM * (MT / 4) + r4) * LDKH + 2 * c4;
    int bFrag = 3 * ASTh + (warpN * NT * 8 + r4) * LDKH + 2 * c4;

    for (int s = 0; s < Ksteps; s++) {
        int buf = s % 3;
        const __half* Ab = dsm + buf * ASTh + aFrag;
        const __half* Bp = dsm + buf * BSTh + bFrag;
#pragma unroll
        for (int kh = 0; kh < 2; kh++) {
            const __half* Ak = Ab + kh * 16;
            const __half* Bk = Bp + kh * 16;
            uint32_t af[MTt][4];
#pragma unroll
            for (int mt = 0; mt < MTt; mt++) {
                const __half* p = Ak + mt * 16 * LDKH;
                af[mt][0] = *(const uint32_t*)(p);
                af[mt][1] = *(const uint32_t*)(p + 8 * LDKH);
                af[mt][2] = *(const uint32_t*)(p + 8);
                af[mt][3] = *(const uint32_t*)(p + 8 * LDKH + 8);
            }
#pragma unroll
            for (int nt = 0; nt < NT; nt++) {
                const __half* pb = Bk + nt * 8 * LDKH;
                uint32_t b0 = *(const uint32_t*)(pb);
                uint32_t b1 = *(const uint32_t*)(pb + 8);
#pragma unroll
                for (int mt = 0; mt < MTt; mt++) mma16816(acc[mt][nt], af[mt], b0, b1);
            }
        }
        if (s + 2 < Ksteps) {
            int nb = (s + 2) % 3;
            LOAD_STAGE(s + 2, nb)
            cpwait<1>();
        } else {
            cpwait<0>();
        }
        __syncthreads();
    }
#undef LOAD_STAGE

    // ---------------- epilogues ----------------
    if (EPI == 0) {
#pragma unroll
        for (int mt = 0; mt < MTt; mt++) {
            int r = row0 + warpM * (MT / 4) + mt * 16 + r4;
#pragma unroll
            for (int nt = 0; nt < NT; nt++) {
                int il = warpN * NT * 8 + nt * 8 + c4 * 2;
                int c = col0 + il;
                float b0 = s_bias[il], b1 = s_bias[il + 1];
                __half2 h0 = __floats2half2_rn(fmaxf(acc[mt][nt][0] + b0, 0.f),
                                               fmaxf(acc[mt][nt][1] + b1, 0.f));
                __half2 h1 = __floats2half2_rn(fmaxf(acc[mt][nt][2] + b0, 0.f),
                                               fmaxf(acc[mt][nt][3] + b1, 0.f));
                *(__half2*)&OutH[(long)r * KP + c] = h0;
                *(__half2*)&OutH[(long)(r + 8) * KP + c] = h1;
            }
        }
    } else if (EPI == 1) {
#pragma unroll
        for (int mt = 0; mt < MTt; mt++) {
            float slo = 0.f, shi = 0.f;
#pragma unroll
            for (int nt = 0; nt < NT; nt++) {
                int il = warpN * NT * 8 + nt * 8 + c4 * 2;
                float v0 = s_bias[il], v1 = s_bias[il + 1];
                float q0 = s_qv[il], q1 = s_qv[il + 1];
                slo += tanhf(acc[mt][nt][0] + v0) * q0 + tanhf(acc[mt][nt][1] + v1) * q1;
                shi += tanhf(acc[mt][nt][2] + v0) * q0 + tanhf(acc[mt][nt][3] + v1) * q1;
            }
            slo += __shfl_xor_sync(0xffffffffu, slo, 1);
            slo += __shfl_xor_sync(0xffffffffu, slo, 2);
            shi += __shfl_xor_sync(0xffffffffu, shi, 1);
            shi += __shfl_xor_sync(0xffffffffu, shi, 2);
            if (c4 == 0) {
                int rl = warpM * (MT / 4) + mt * 16 + r4;
                atomicAdd(&s_red[rl], slo);
                atomicAdd(&s_red[rl + 8], shi);
            }
        }
        __syncthreads();
        for (int i = tid; i < MT; i += 256) OutF[row0 + i] = s_red[i];
    } else {
#pragma unroll
        for (int mt = 0; mt < MTt; mt++) {
            int r0 = row0 + warpM * (MT / 4) + mt * 16 + r4;
            int r1 = r0 + 8;
#pragma unroll
            for (int nt = 0; nt < NT; nt++) {
                int il = warpN * NT * 8 + nt * 8 + c4 * 2;
                int c = col0 + il;
                float b0 = s_bias[il], b1 = s_bias[il + 1];
                if (r0 < 3200) {
                    int bu = r0 / Nn, n_ = r0 - bu * Nn;
                    g_GXt[((long)n_ * 1200 + c) * Bb + bu] = acc[mt][nt][0] + b0;
                    g_GXt[((long)n_ * 1200 + c + 1) * Bb + bu] = acc[mt][nt][1] + b1;
                }
                if (r1 < 3200) {
                    int bu = r1 / Nn, n_ = r1 - bu * Nn;
                    g_GXt[((long)n_ * 1200 + c) * Bb + bu] = acc[mt][nt][2] + b0;
                    g_GXt[((long)n_ * 1200 + c + 1) * Bb + bu] = acc[mt][nt][3] + b1;
                }
            }
        }
    }
}

// ---------------- softmax over titles ----------------
__global__ void softmax_kernel() {
    int idx = blockIdx.x * blockDim.x + threadIdx.x;
    if (idx >= Bb * Tt) return;
    int b = idx / Tt, t = idx - b * Tt;
    const float* s = g_scores + b * Nn * Tt + t;
    float mx = -1e30f;
    for (int n = 0; n < Nn; n++) mx = fmaxf(mx, s[n * Tt]);
    float sum = 0.f;
    for (int n = 0; n < Nn; n++) sum += __expf(s[n * Tt] - mx);
    float inv = 1.f / sum;
    float* al = g_alpha + b * Nn * Tt + t;
    for (int n = 0; n < Nn; n++) al[n * Tt] = __expf(s[n * Tt] - mx) * inv;
}

// ---------------- weighted sum over words (half C -> half E) ----------------
__global__ __launch_bounds__(128) void wsum_kernel() {
    int bn = blockIdx.x;
    __shared__ float al[Tt];
    if (threadIdx.x < Tt) al[threadIdx.x] = g_alpha[bn * Tt + threadIdx.x];
    __syncthreads();
    const __half* Cr = g_C + (long)bn * Tt * KP;
    for (int f = threadIdx.x; f < KP; f += 128) {
        float acc = 0.f;
#pragma unroll
        for (int t = 0; t < Tt; t++) acc += al[t] * __half2float(Cr[t * KP + f]);
        g_E[bn * KP + f] = __float2half_rn(acc);
    }
}

// ---------------- persistent GRU ----------------
__global__ __launch_bounds__(256) void gru_persist(const int* __restrict__ uid,
                                                   const float* __restrict__ user_emb,
                                                   const float* __restrict__ W_hh,
                                                   const float* __restrict__ b_ih,
                                                   const float* __restrict__ b_hh,
                                                   const int* __restrict__ lens,
                                                   float* __restrict__ out) {
    __shared__ float s_w[3 * 4 * Gg];
    int tid = threadIdx.x, blk = blockIdx.x;
    int b = tid & 63, gi = tid >> 6;
    int g = blk * 4 + gi;
    for (int i = tid; i < 3 * 4 * Gg; i += 256) {
        int j = i / (4 * Gg); int rem = i - j * (4 * Gg);
        int gi2 = rem / Gg; int e = rem - gi2 * Gg;
        s_w[i] = W_hh[((long)j * Gg + blk * 4 + gi2) * Gg + e];
    }
    float bi_r = b_ih[g], bi_z = b_ih[Gg + g], bi_n = b_ih[2 * Gg + g];
    float bh_r = b_hh[g], bh_z = b_hh[Gg + g], bh_n = b_hh[2 * Gg + g];
    int len = lens[b];
    float myh = user_emb[(long)uid[b] * Gg + g];
    g_h[0][b * Gg + g] = myh;
    __syncthreads();

    const float4* wr4 = (const float4*)(s_w + gi * Gg);
    const float4* wz4 = (const float4*)(s_w + 4 * Gg + gi * Gg);
    const float4* wn4 = (const float4*)(s_w + 8 * Gg + gi * Gg);

    for (int n = 0; n < Nn; n++) {
        __threadfence();
        __syncthreads();
        if (tid == 0) {
            atomicAdd(&g_bar[n], 1);
            while (*((volatile int*)&g_bar[n]) < (int)gridDim.x) { }
        }
        __syncthreads();
        const float* hin = g_h[n & 1];
        const float4* h4 = (const float4*)(hin + b * Gg);
        float hr = 0.f, hz = 0.f, hn = 0.f;
#pragma unroll 4
        for (int e4 = 0; e4 < Gg / 4; e4++) {
            float4 hv = __ldcg(h4 + e4);
            float4 a = wr4[e4], bz = wz4[e4], cn = wn4[e4];
            hr += a.x * hv.x + a.y * hv.y + a.z * hv.z + a.w * hv.w;
            hz += bz.x * hv.x + bz.y * hv.y + bz.z * hv.z + bz.w * hv.w;
            hn += cn.x * hv.x + cn.y * hv.y + cn.z * hv.z + cn.w * hv.w;
        }
        hr += bh_r; hz += bh_z; hn += bh_n;
        const float* gxt = g_GXt + (long)n * 1200 * Bb;
        float xr = gxt[(0 * Gg + g) * Bb + b] + bi_r;
        float xz = gxt[(1 * Gg + g) * Bb + b] + bi_z;
        float xn = gxt[(2 * Gg + g) * Bb + b] + bi_n;
        float r = 1.f / (1.f + __expf(-(xr + hr)));
        float z = 1.f / (1.f + __expf(-(xz + hz)));
        float nv = tanhf(xn + r * hn);
        float hnew = (1.f - z) * nv + z * myh;
        if (n < len) myh = hnew;
        g_h[(n + 1) & 1][b * Gg + g] = myh;
    }
    out[b * Gg + g] = myh;
}

// ---------------- launch ----------------
extern "C" void kernel_launch(void* const* d_in, const int* in_sizes, int n_in,
                              void* d_out, int out_size) {
    const int*   user_id  = (const int*)d_in[0];
    const int*   title    = (const int*)d_in[1];
    const int*   hist_len = (const int*)d_in[2];
    const float* word_emb = (const float*)d_in[3];
    const float* conv_w   = (const float*)d_in[4];
    const float* conv_b   = (const float*)d_in[5];
    const float* v        = (const float*)d_in[6];
    const float* vb       = (const float*)d_in[7];
    const float* q        = (const float*)d_in[8];
    const float* user_emb = (const float*)d_in[9];
    const float* W_ih     = (const float*)d_in[10];
    const float* W_hh     = (const float*)d_in[11];
    const float* b_ih     = (const float*)d_in[12];
    const float* b_hh     = (const float*)d_in[13];
    float* out = (float*)d_out;

    __half *Xp, *Wtp, *vTp, *Wihp, *Cp, *Ep;
    float *scp;
    int* bar;
    cudaGetSymbolAddress((void**)&Xp, g_X);
    cudaGetSymbolAddress((void**)&Wtp, g_Wt);
    cudaGetSymbolAddress((void**)&vTp, g_vT);
    cudaGetSymbolAddress((void**)&Wihp, g_Wih);
    cudaGetSymbolAddress((void**)&Cp, g_C);
    cudaGetSymbolAddress((void**)&Ep, g_E);
    cudaGetSymbolAddress((void**)&scp, g_scores);
    cudaGetSymbolAddress((void**)&bar, g_bar);

    auto smemsz = [](int mt, int nt) {
        return (3 * (mt * LDKH + nt * 16 * LDKH)) * (int)sizeof(__half);
    };
    cudaFuncSetAttribute((const void*)hgemm<128, 5, 0, 2>,
                         cudaFuncAttributeMaxDynamicSharedMemorySize, smemsz(128, 5));
    cudaFuncSetAttribute((const void*)hgemm<128, 13, 1, 1>,
                         cudaFuncAttributeMaxDynamicSharedMemorySize, smemsz(128, 13));
    cudaFuncSetAttribute((const void*)hgemm<256, 8, 2, 1>,
                         cudaFuncAttributeMaxDynamicSharedMemorySize, smemsz(256, 8));
    cudaFuncSetAttribute((const void*)hgemm<256, 3, 2, 1>,
                         cudaFuncAttributeMaxDynamicSharedMemorySize, smemsz(256, 3));

    gather_kernel<<<Bb * Nn, 256>>>(title, word_emb);
    wtr_kernel<<<(FNf * KCv + 255) / 256, 256>>>(conv_w);
    vtr_kernel<<<(208 * KP + 255) / 256, 256>>>(v);
    wihh_kernel<<<(1200 * KP + 255) / 256, 256>>>(W_ih);
    cudaMemsetAsync(bar, 0, 64 * sizeof(int));
    cudaMemsetAsync(Cp, 0, (long)MROWS * KP * sizeof(__half));   // zero K-pad cols
    cudaMemsetAsync(Ep, 0, 3328L * KP * sizeof(__half));

    // conv: C = X @ Wt^T + b, ReLU -> half.  MT=128, N = 5 x 80 cols, K=960 (30 stages)
    hgemm<128, 5, 0, 2><<<dim3(5, MROWS / 128), 256, smemsz(128, 5)>>>(
        Xp, Wtp, nullptr, Cp, conv_b, nullptr, 0, 0, KCv, KCv / 32, FNf);
    // attn: scores = sum_c tanh(C @ vT^T + vb) * q, all 208 cols, K=416 (13 stages)
    hgemm<128, 13, 1, 1><<<dim3(1, MROWS / 128), 256, smemsz(128, 13)>>>(
        Cp, vTp, scp, nullptr, vb, q, 0, KP, KP, KP / 32, Aa);

    softmax_kernel<<<(Bb * Tt + 255) / 256, 256>>>();
    wsum_kernel<<<Bb * Nn, 128>>>();

    // GX^T: (E @ W_ih^T + b_ih) transposed. N = 9x128 + 48, M = 13 x 256
    hgemm<256, 8, 2, 1><<<dim3(9, 13), 256, smemsz(256, 8)>>>(
        Ep, Wihp, nullptr, nullptr, b_ih, nullptr, 0, KP, KP, KP / 32, 1200);
    hgemm<256, 3, 2, 1><<<dim3(1, 13), 256, smemsz(256, 3)>>>(
        Ep, Wihp, nullptr, nullptr, b_ih, nullptr, 1152, KP, KP, KP / 32, 1200);

    gru_persist<<<100, 256>>>(user_id, user_emb, W_hh, b_ih, b_hh, hist_len, out);
}

// round 8
// speedup vs baseline: 2.8857x; 1.0230x over previous
#include <cuda_runtime.h>
#include <cuda_fp16.h>
#include <cstdint>

#define Bb 64
#define Nn 50
#define Tt 30
#define Ee 300
#define EeP 320
#define FNf 400
#define Aa 200
#define Gg 400
#define KCv 960            // conv GEMM K = 3*320
#define KP 416             // padded K for attn/GX
#define MROWS (Bb*Nn*Tt)   // 96000
#define LDKH 40            // smem k-stride in halves (32 + 8 pad)

// ---------------- scratch ----------------
__device__ __half g_X[(long)Bb * Nn * 32 * EeP];   // gathered embeddings
__device__ __half g_Wt[FNf * KCv];                 // conv weights [400][960]
__device__ __half g_vT[208 * KP];                  // v^T padded [208][416]
__device__ __half g_Wih[1200 * KP];                // W_ih padded [1200][416]
__device__ __half g_C[(long)MROWS * KP];           // conv out [96000][416]; pad cols stay 0
__device__ float  g_scores[MROWS];
__device__ float  g_alpha[MROWS];
__device__ __half g_E[3328 * KP];                  // news embed (rows>=3200 stay 0)
__device__ float  g_GXt[Nn * 1200 * Bb];           // transposed GX: [n][3G][b]
__device__ float  g_h[2][Bb * Gg];
__device__ int    g_bar[64];

// ---------------- helpers ----------------
__device__ __forceinline__ uint32_t smem_u32(const void* p) {
    uint32_t a;
    asm("{ .reg .u64 t; cvta.to.shared.u64 t, %1; cvt.u32.u64 %0, t; }" : "=r"(a) : "l"(p));
    return a;
}
__device__ __forceinline__ void cpasync16(uint32_t dst, const void* src) {
    asm volatile("cp.async.cg.shared.global [%0], [%1], 16;" :: "r"(dst), "l"(src));
}
__device__ __forceinline__ void cpcommit() { asm volatile("cp.async.commit_group;" ::: "memory"); }
template <int N> __device__ __forceinline__ void cpwait() {
    asm volatile("cp.async.wait_group %0;" :: "n"(N) : "memory");
}
__device__ __forceinline__ void mma16816(float* c, const uint32_t* a, uint32_t b0, uint32_t b1) {
    asm volatile("mma.sync.aligned.m16n8k16.row.col.f32.f16.f16.f32 "
                 "{%0,%1,%2,%3}, {%4,%5,%6,%7}, {%8,%9}, {%0,%1,%2,%3};"
                 : "+f"(c[0]), "+f"(c[1]), "+f"(c[2]), "+f"(c[3])
                 : "r"(a[0]), "r"(a[1]), "r"(a[2]), "r"(a[3]), "r"(b0), "r"(b1));
}
__device__ __forceinline__ void ldsm_x4(uint32_t& r0, uint32_t& r1, uint32_t& r2, uint32_t& r3,
                                        uint32_t addr) {
    asm volatile("ldmatrix.sync.aligned.m8n8.x4.shared.b16 {%0,%1,%2,%3}, [%4];"
                 : "=r"(r0), "=r"(r1), "=r"(r2), "=r"(r3) : "r"(addr));
}
__device__ __forceinline__ void ldsm_x2(uint32_t& r0, uint32_t& r1, uint32_t addr) {
    asm volatile("ldmatrix.sync.aligned.m8n8.x2.shared.b16 {%0,%1}, [%2];"
                 : "=r"(r0), "=r"(r1) : "r"(addr));
}

// ---------------- prep ----------------
__global__ __launch_bounds__(256) void gather_kernel(const int* __restrict__ title,
                                                     const float* __restrict__ word_emb) {
    int bn = blockIdx.x;
    __half* X = g_X + (long)bn * 32 * EeP;
    const __half z = __float2half(0.f);
    for (int i = threadIdx.x; i < EeP; i += 256) { X[i] = z; X[31 * EeP + i] = z; }
    const int* tw = title + bn * Tt;
    for (int idx = threadIdx.x; idx < Tt * EeP; idx += 256) {
        int s = idx / EeP, e = idx - s * EeP;
        float v = (e < Ee) ? word_emb[(long)tw[s] * Ee + e] : 0.f;
        X[(s + 1) * EeP + e] = __float2half_rn(v);
    }
}
__global__ void wtr_kernel(const float* __restrict__ conv_w) {
    int i = blockIdx.x * 256 + threadIdx.x;
    if (i >= FNf * KCv) return;
    int n = i / KCv, k = i - n * KCv;
    int tap = k / EeP, e = k - tap * EeP;
    float v = (e < Ee) ? conv_w[(tap * Ee + e) * FNf + n] : 0.f;
    g_Wt[i] = __float2half_rn(v);
}
__global__ void vtr_kernel(const float* __restrict__ v) {
    int i = blockIdx.x * 256 + threadIdx.x;
    if (i >= 208 * KP) return;
    int a = i / KP, f = i - a * KP;
    float x = (a < Aa && f < FNf) ? v[f * Aa + a] : 0.f;
    g_vT[i] = __float2half_rn(x);
}
__global__ void wihh_kernel(const float* __restrict__ W_ih) {
    int i = blockIdx.x * 256 + threadIdx.x;
    if (i >= 1200 * KP) return;
    int n = i / KP, k = i - n * KP;
    float x = (k < FNf) ? W_ih[n * FNf + k] : 0.f;
    g_Wih[i] = __float2half_rn(x);
}

// ---------------- fp16 cp.async GEMM with ldmatrix fragments ----------------
// EPI 0: conv rows via g_X map; bias+ReLU -> half OutH[.][416]
// EPI 1: attn; tanh(+vb)*q block-reduce -> OutF[row] (g_scores)
// EPI 2: GX; bias; transposed fp32 store to g_GXt (guard r < 3200)
template <int MT, int NT, int EPI, int MINB>
__global__ __launch_bounds__(256, MINB) void hgemm(const __half* __restrict__ A,
                                                   const __half* __restrict__ B,
                                                   float* __restrict__ OutF,
                                                   __half* __restrict__ OutH,
                                                   const float* __restrict__ bias,
                                                   const float* __restrict__ qv,
                                                   int colbase, int lda, int ldb,
                                                   int Ksteps, int Nvalid) {
    constexpr int NTILE = NT * 16;
    constexpr int ASTh = MT * LDKH;
    constexpr int BSTh = NTILE * LDKH;
    constexpr int ACH = MT / 64;
    constexpr int BCH = (NTILE * 4 + 255) / 256;
    constexpr int NB = NTILE * 4;
    constexpr int MTt = MT / 64;
    constexpr int NP = NT / 2;                    // x4 B pairs
    extern __shared__ __half dsm[];
    __shared__ float s_bias[224];
    __shared__ float s_qv[224];
    __shared__ float s_red[256];

    int tid = threadIdx.x, lane = tid & 31, wid = tid >> 5;
    int warpM = wid & 3, warpN = wid >> 2;
    int row0 = blockIdx.y * MT;
    int col0 = colbase + blockIdx.x * NTILE;

    for (int i = tid; i < NTILE; i += 256) {
        int c = col0 + i;
        s_bias[i] = (c < Nvalid) ? bias[c] : 0.f;
        if (EPI == 1) s_qv[i] = (c < Nvalid) ? qv[c] : 0.f;
    }
    if (EPI == 1) for (int i = tid; i < MT; i += 256) s_red[i] = 0.f;

    uint32_t su = smem_u32(dsm);
    const __half* aptr[ACH];
    uint32_t aoff[ACH];
#pragma unroll
    for (int j = 0; j < ACH; j++) {
        int i = tid + j * 256;
        int m = i >> 2, kc = i & 3;
        int gr = row0 + m;
        long ro;
        if (EPI == 0) ro = (long)(gr / Tt) * (32 * EeP) + (long)(gr % Tt) * EeP;
        else          ro = (long)gr * lda;
        aptr[j] = A + ro + kc * 8;
        aoff[j] = (uint32_t)(m * 80 + kc * 16);
    }
    const __half* bptr[BCH];
    uint32_t boff[BCH];
    bool bok[BCH];
#pragma unroll
    for (int j = 0; j < BCH; j++) {
        int i = tid + j * 256;
        bok[j] = (i < NB);
        int n = i >> 2, kc = i & 3;
        if (!bok[j]) { n = 0; kc = 0; }
        bptr[j] = B + (long)(col0 + n) * ldb + kc * 8;
        boff[j] = (uint32_t)(n * 80 + kc * 16);
    }

    // ldmatrix per-thread addresses (bytes, relative to stage base)
    uint32_t aLd[MTt];
#pragma unroll
    for (int mt = 0; mt < MTt; mt++)
        aLd[mt] = (uint32_t)((warpM * (MT / 4) + mt * 16 + (lane & 15)) * 80 +
                             ((lane >> 4) * 16));
    uint32_t bLd4[(NP > 0) ? NP : 1];
#pragma unroll
    for (int p = 0; p < NP; p++)
        bLd4[p] = (uint32_t)((warpN * NT * 8 + p * 16 + (lane & 7) + ((lane >> 4) * 8)) * 80 +
                             (((lane >> 3) & 1) * 16));
    uint32_t bLd2 = 0;
    if (NT & 1) {
        int l15 = lane & 15;
        bLd2 = (uint32_t)((warpN * NT * 8 + (NT - 1) * 8 + (l15 & 7)) * 80 +
                          ((l15 >> 3) * 16));
    }

    float acc[MTt][NT][4];
#pragma unroll
    for (int i = 0; i < MTt; i++)
#pragma unroll
        for (int j = 0; j < NT; j++)
#pragma unroll
            for (int k = 0; k < 4; k++) acc[i][j][k] = 0.f;

#define LOAD_STAGE(s, buf)                                                        \
    {                                                                             \
        uint32_t ab = su + (uint32_t)(buf) * (ASTh * 2);                          \
        _Pragma("unroll")                                                         \
        for (int j = 0; j < ACH; j++) cpasync16(ab + aoff[j], aptr[j] + (s) * 32);\
        uint32_t bb = su + (uint32_t)(3 * ASTh + (buf) * BSTh) * 2;               \
        _Pragma("unroll")                                                         \
        for (int j = 0; j < BCH; j++)                                             \
            if (bok[j]) cpasync16(bb + boff[j], bptr[j] + (s) * 32);              \
        cpcommit();                                                               \
    }

    LOAD_STAGE(0, 0)
    LOAD_STAGE(1, 1)
    cpwait<1>();
    __syncthreads();

    int r4 = lane >> 2, c4 = lane & 3;

    for (int s = 0; s < Ksteps; s++) {
        int buf = s % 3;
        uint32_t Abase = su + (uint32_t)buf * (ASTh * 2);
        uint32_t Bbase = su + (uint32_t)(3 * ASTh + buf * BSTh) * 2;
#pragma unroll
        for (int kh = 0; kh < 2; kh++) {
            uint32_t khoff = kh * 32;
            uint32_t af[MTt][4], bfr[NT][2];
#pragma unroll
            for (int mt = 0; mt < MTt; mt++)
                ldsm_x4(af[mt][0], af[mt][1], af[mt][2], af[mt][3],
                        Abase + aLd[mt] + khoff);
#pragma unroll
            for (int p = 0; p < NP; p++)
                ldsm_x4(bfr[2 * p][0], bfr[2 * p][1], bfr[2 * p + 1][0], bfr[2 * p + 1][1],
                        Bbase + bLd4[p] + khoff);
            if (NT & 1)
                ldsm_x2(bfr[NT - 1][0], bfr[NT - 1][1], Bbase + bLd2 + khoff);
#pragma unroll
            for (int nt = 0; nt < NT; nt++)
#pragma unroll
                for (int mt = 0; mt < MTt; mt++)
                    mma16816(acc[mt][nt], af[mt], bfr[nt][0], bfr[nt][1]);
        }
        if (s + 2 < Ksteps) {
            int nb = (s + 2) % 3;
            LOAD_STAGE(s + 2, nb)
            cpwait<1>();
        } else {
            cpwait<0>();
        }
        __syncthreads();
    }
#undef LOAD_STAGE

    // ---------------- epilogues ----------------
    if (EPI == 0) {
#pragma unroll
        for (int mt = 0; mt < MTt; mt++) {
            int r = row0 + warpM * (MT / 4) + mt * 16 + r4;
#pragma unroll
            for (int nt = 0; nt < NT; nt++) {
                int il = warpN * NT * 8 + nt * 8 + c4 * 2;
                int c = col0 + il;
                float b0 = s_bias[il], b1 = s_bias[il + 1];
                __half2 h0 = __floats2half2_rn(fmaxf(acc[mt][nt][0] + b0, 0.f),
                                               fmaxf(acc[mt][nt][1] + b1, 0.f));
                __half2 h1 = __floats2half2_rn(fmaxf(acc[mt][nt][2] + b0, 0.f),
                                               fmaxf(acc[mt][nt][3] + b1, 0.f));
                *(__half2*)&OutH[(long)r * KP + c] = h0;
                *(__half2*)&OutH[(long)(r + 8) * KP + c] = h1;
            }
        }
    } else if (EPI == 1) {
#pragma unroll
        for (int mt = 0; mt < MTt; mt++) {
            float slo = 0.f, shi = 0.f;
#pragma unroll
            for (int nt = 0; nt < NT; nt++) {
                int il = warpN * NT * 8 + nt * 8 + c4 * 2;
                float v0 = s_bias[il], v1 = s_bias[il + 1];
                float q0 = s_qv[il], q1 = s_qv[il + 1];
                slo += tanhf(acc[mt][nt][0] + v0) * q0 + tanhf(acc[mt][nt][1] + v1) * q1;
                shi += tanhf(acc[mt][nt][2] + v0) * q0 + tanhf(acc[mt][nt][3] + v1) * q1;
            }
            slo += __shfl_xor_sync(0xffffffffu, slo, 1);
            slo += __shfl_xor_sync(0xffffffffu, slo, 2);
            shi += __shfl_xor_sync(0xffffffffu, shi, 1);
            shi += __shfl_xor_sync(0xffffffffu, shi, 2);
            if (c4 == 0) {
                int rl = warpM * (MT / 4) + mt * 16 + r4;
                atomicAdd(&s_red[rl], slo);
                atomicAdd(&s_red[rl + 8], shi);
            }
        }
        __syncthreads();
        for (int i = tid; i < MT; i += 256) OutF[row0 + i] = s_red[i];
    } else {
#pragma unroll
        for (int mt = 0; mt < MTt; mt++) {
            int r0 = row0 + warpM * (MT / 4) + mt * 16 + r4;
            int r1 = r0 + 8;
#pragma unroll
            for (int nt = 0; nt < NT; nt++) {
                int il = warpN * NT * 8 + nt * 8 + c4 * 2;
                int c = col0 + il;
                float b0 = s_bias[il], b1 = s_bias[il + 1];
                if (r0 < 3200) {
                    int bu = r0 / Nn, n_ = r0 - bu * Nn;
                    g_GXt[((long)n_ * 1200 + c) * Bb + bu] = acc[mt][nt][0] + b0;
                    g_GXt[((long)n_ * 1200 + c + 1) * Bb + bu] = acc[mt][nt][1] + b1;
                }
                if (r1 < 3200) {
                    int bu = r1 / Nn, n_ = r1 - bu * Nn;
                    g_GXt[((long)n_ * 1200 + c) * Bb + bu] = acc[mt][nt][2] + b0;
                    g_GXt[((long)n_ * 1200 + c + 1) * Bb + bu] = acc[mt][nt][3] + b1;
                }
            }
        }
    }
}

// ---------------- softmax over titles ----------------
__global__ void softmax_kernel() {
    int idx = blockIdx.x * blockDim.x + threadIdx.x;
    if (idx >= Bb * Tt) return;
    int b = idx / Tt, t = idx - b * Tt;
    const float* s = g_scores + b * Nn * Tt + t;
    float mx = -1e30f;
    for (int n = 0; n < Nn; n++) mx = fmaxf(mx, s[n * Tt]);
    float sum = 0.f;
    for (int n = 0; n < Nn; n++) sum += __expf(s[n * Tt] - mx);
    float inv = 1.f / sum;
    float* al = g_alpha + b * Nn * Tt + t;
    for (int n = 0; n < Nn; n++) al[n * Tt] = __expf(s[n * Tt] - mx) * inv;
}

// ---------------- weighted sum over words (half C -> half E) ----------------
__global__ __launch_bounds__(128) void wsum_kernel() {
    int bn = blockIdx.x;
    __shared__ float al[Tt];
    if (threadIdx.x < Tt) al[threadIdx.x] = g_alpha[bn * Tt + threadIdx.x];
    __syncthreads();
    const __half* Cr = g_C + (long)bn * Tt * KP;
    for (int f = threadIdx.x; f < KP; f += 128) {
        float acc = 0.f;
#pragma unroll
        for (int t = 0; t < Tt; t++) acc += al[t] * __half2float(Cr[t * KP + f]);
        g_E[bn * KP + f] = __float2half_rn(acc);
    }
}

// ---------------- persistent GRU ----------------
__global__ __launch_bounds__(256) void gru_persist(const int* __restrict__ uid,
                                                   const float* __restrict__ user_emb,
                                                   const float* __restrict__ W_hh,
                                                   const float* __restrict__ b_ih,
                                                   const float* __restrict__ b_hh,
                                                   const int* __restrict__ lens,
                                                   float* __restrict__ out) {
    __shared__ float s_w[3 * 4 * Gg];
    int tid = threadIdx.x, blk = blockIdx.x;
    int b = tid & 63, gi = tid >> 6;
    int g = blk * 4 + gi;
    for (int i = tid; i < 3 * 4 * Gg; i += 256) {
        int j = i / (4 * Gg); int rem = i - j * (4 * Gg);
        int gi2 = rem / Gg; int e = rem - gi2 * Gg;
        s_w[i] = W_hh[((long)j * Gg + blk * 4 + gi2) * Gg + e];
    }
    float bi_r = b_ih[g], bi_z = b_ih[Gg + g], bi_n = b_ih[2 * Gg + g];
    float bh_r = b_hh[g], bh_z = b_hh[Gg + g], bh_n = b_hh[2 * Gg + g];
    int len = lens[b];
    float myh = user_emb[(long)uid[b] * Gg + g];
    g_h[0][b * Gg + g] = myh;
    __syncthreads();

    const float4* wr4 = (const float4*)(s_w + gi * Gg);
    const float4* wz4 = (const float4*)(s_w + 4 * Gg + gi * Gg);
    const float4* wn4 = (const float4*)(s_w + 8 * Gg + gi * Gg);

    for (int n = 0; n < Nn; n++) {
        __threadfence();
        __syncthreads();
        if (tid == 0) {
            atomicAdd(&g_bar[n], 1);
            while (*((volatile int*)&g_bar[n]) < (int)gridDim.x) { }
        }
        __syncthreads();
        const float* hin = g_h[n & 1];
        const float4* h4 = (const float4*)(hin + b * Gg);
        float hr = 0.f, hz = 0.f, hn = 0.f;
#pragma unroll 4
        for (int e4 = 0; e4 < Gg / 4; e4++) {
            float4 hv = __ldcg(h4 + e4);
            float4 a = wr4[e4], bz = wz4[e4], cn = wn4[e4];
            hr += a.x * hv.x + a.y * hv.y + a.z * hv.z + a.w * hv.w;
            hz += bz.x * hv.x + bz.y * hv.y + bz.z * hv.z + bz.w * hv.w;
            hn += cn.x * hv.x + cn.y * hv.y + cn.z * hv.z + cn.w * hv.w;
        }
        hr += bh_r; hz += bh_z; hn += bh_n;
        const float* gxt = g_GXt + (long)n * 1200 * Bb;
        float xr = gxt[(0 * Gg + g) * Bb + b] + bi_r;
        float xz = gxt[(1 * Gg + g) * Bb + b] + bi_z;
        float xn = gxt[(2 * Gg + g) * Bb + b] + bi_n;
        float r = 1.f / (1.f + __expf(-(xr + hr)));
        float z = 1.f / (1.f + __expf(-(xz + hz)));
        float nv = tanhf(xn + r * hn);
        float hnew = (1.f - z) * nv + z * myh;
        if (n < len) myh = hnew;
        g_h[(n + 1) & 1][b * Gg + g] = myh;
    }
    out[b * Gg + g] = myh;
}

// ---------------- launch ----------------
extern "C" void kernel_launch(void* const* d_in, const int* in_sizes, int n_in,
                              void* d_out, int out_size) {
    const int*   user_id  = (const int*)d_in[0];
    const int*   title    = (const int*)d_in[1];
    const int*   hist_len = (const int*)d_in[2];
    const float* word_emb = (const float*)d_in[3];
    const float* conv_w   = (const float*)d_in[4];
    const float* conv_b   = (const float*)d_in[5];
    const float* v        = (const float*)d_in[6];
    const float* vb       = (const float*)d_in[7];
    const float* q        = (const float*)d_in[8];
    const float* user_emb = (const float*)d_in[9];
    const float* W_ih     = (const float*)d_in[10];
    const float* W_hh     = (const float*)d_in[11];
    const float* b_ih     = (const float*)d_in[12];
    const float* b_hh     = (const float*)d_in[13];
    float* out = (float*)d_out;

    __half *Xp, *Wtp, *vTp, *Wihp, *Cp, *Ep;
    float *scp;
    int* bar;
    cudaGetSymbolAddress((void**)&Xp, g_X);
    cudaGetSymbolAddress((void**)&Wtp, g_Wt);
    cudaGetSymbolAddress((void**)&vTp, g_vT);
    cudaGetSymbolAddress((void**)&Wihp, g_Wih);
    cudaGetSymbolAddress((void**)&Cp, g_C);
    cudaGetSymbolAddress((void**)&Ep, g_E);
    cudaGetSymbolAddress((void**)&scp, g_scores);
    cudaGetSymbolAddress((void**)&bar, g_bar);

    auto smemsz = [](int mt, int nt) {
        return (3 * (mt * LDKH + nt * 16 * LDKH)) * (int)sizeof(__half);
    };
    cudaFuncSetAttribute((const void*)hgemm<128, 5, 0, 2>,
                         cudaFuncAttributeMaxDynamicSharedMemorySize, smemsz(128, 5));
    cudaFuncSetAttribute((const void*)hgemm<128, 13, 1, 1>,
                         cudaFuncAttributeMaxDynamicSharedMemorySize, smemsz(128, 13));
    cudaFuncSetAttribute((const void*)hgemm<256, 8, 2, 1>,
                         cudaFuncAttributeMaxDynamicSharedMemorySize, smemsz(256, 8));
    cudaFuncSetAttribute((const void*)hgemm<256, 3, 2, 1>,
                         cudaFuncAttributeMaxDynamicSharedMemorySize, smemsz(256, 3));

    gather_kernel<<<Bb * Nn, 256>>>(title, word_emb);
    wtr_kernel<<<(FNf * KCv + 255) / 256, 256>>>(conv_w);
    vtr_kernel<<<(208 * KP + 255) / 256, 256>>>(v);
    wihh_kernel<<<(1200 * KP + 255) / 256, 256>>>(W_ih);
    cudaMemsetAsync(bar, 0, 64 * sizeof(int));
    // NOTE: no memsets of g_C / g_E — pad columns/rows are never written and
    // remain zero from static initialization; they only multiply zero-padded
    // B operands.

    // conv: C = X @ Wt^T + b, ReLU -> half.  MT=128, N = 5 x 80 cols, K=960 (30 stages)
    hgemm<128, 5, 0, 2><<<dim3(5, MROWS / 128), 256, smemsz(128, 5)>>>(
        Xp, Wtp, nullptr, Cp, conv_b, nullptr, 0, 0, KCv, KCv / 32, FNf);
    // attn: scores = sum_c tanh(C @ vT^T + vb) * q, all 208 cols, K=416 (13 stages)
    hgemm<128, 13, 1, 1><<<dim3(1, MROWS / 128), 256, smemsz(128, 13)>>>(
        Cp, vTp, scp, nullptr, vb, q, 0, KP, KP, KP / 32, Aa);

    softmax_kernel<<<(Bb * Tt + 255) / 256, 256>>>();
    wsum_kernel<<<Bb * Nn, 128>>>();

    // GX^T: (E @ W_ih^T + b_ih) transposed. N = 9x128 + 48, M = 13 x 256
    hgemm<256, 8, 2, 1><<<dim3(9, 13), 256, smemsz(256, 8)>>>(
        Ep, Wihp, nullptr, nullptr, b_ih, nullptr, 0, KP, KP, KP / 32, 1200);
    hgemm<256, 3, 2, 1><<<dim3(1, 13), 256, smemsz(256, 3)>>>(
        Ep, Wihp, nullptr, nullptr, b_ih, nullptr, 1152, KP, KP, KP / 32, 1200);

    gru_persist<<<100, 256>>>(user_id, user_emb, W_hh, b_ih, b_hh, hist_len, out);
}

// round 9
// speedup vs baseline: 5.3807x; 1.8646x over previous
#include <cuda_runtime.h>
#include <cuda_fp16.h>
#include <cstdint>

#define Bb 64
#define Nn 50
#define Tt 30
#define Ee 300
#define EeP 320
#define FNf 400
#define Aa 200
#define Gg 400
#define KCv 960            // conv GEMM K = 3*320
#define KP 416             // padded K for attn/GX
#define MROWS (Bb*Nn*Tt)   // 96000
#define LDKH 40            // smem k-stride in halves (32 + 8 pad)
#define GBLK 25            // GRU blocks

// ---------------- scratch ----------------
__device__ __half g_X[(long)Bb * Nn * 32 * EeP];   // gathered embeddings
__device__ __half g_Wt[FNf * KCv];                 // conv weights [400][960]
__device__ __half g_vT[208 * KP];                  // v^T padded [208][416]
__device__ __half g_Wih[1200 * KP];                // W_ih padded [1200][416]
__device__ __half g_Whh[1200 * Gg];                // W_hh fp16 [1200][400]
__device__ __half g_C[(long)MROWS * KP];           // conv out; pad cols stay 0
__device__ float  g_scores[MROWS];
__device__ float  g_alpha[MROWS];
__device__ __half g_E[3328 * KP];                  // news embed (rows>=3200 stay 0)
__device__ float  g_GX[3328L * 1200];              // GX row-major [r][1200]
__device__ float  g_GXt[Nn * 1200 * Bb];           // transposed: [n][3G][b]
__device__ float  g_h[2][Bb * Gg];                 // h [b][g], ping-pong
__device__ int    g_bar[64];

// ---------------- helpers ----------------
__device__ __forceinline__ uint32_t smem_u32(const void* p) {
    uint32_t a;
    asm("{ .reg .u64 t; cvta.to.shared.u64 t, %1; cvt.u32.u64 %0, t; }" : "=r"(a) : "l"(p));
    return a;
}
__device__ __forceinline__ void cpasync16(uint32_t dst, const void* src) {
    asm volatile("cp.async.cg.shared.global [%0], [%1], 16;" :: "r"(dst), "l"(src));
}
__device__ __forceinline__ void cpcommit() { asm volatile("cp.async.commit_group;" ::: "memory"); }
template <int N> __device__ __forceinline__ void cpwait() {
    asm volatile("cp.async.wait_group %0;" :: "n"(N) : "memory");
}
__device__ __forceinline__ void mma16816(float* c, const uint32_t* a, uint32_t b0, uint32_t b1) {
    asm volatile("mma.sync.aligned.m16n8k16.row.col.f32.f16.f16.f32 "
                 "{%0,%1,%2,%3}, {%4,%5,%6,%7}, {%8,%9}, {%0,%1,%2,%3};"
                 : "+f"(c[0]), "+f"(c[1]), "+f"(c[2]), "+f"(c[3])
                 : "r"(a[0]), "r"(a[1]), "r"(a[2]), "r"(a[3]), "r"(b0), "r"(b1));
}
__device__ __forceinline__ void ldsm_x4(uint32_t& r0, uint32_t& r1, uint32_t& r2, uint32_t& r3,
                                        uint32_t addr) {
    asm volatile("ldmatrix.sync.aligned.m8n8.x4.shared.b16 {%0,%1,%2,%3}, [%4];"
                 : "=r"(r0), "=r"(r1), "=r"(r2), "=r"(r3) : "r"(addr));
}
__device__ __forceinline__ void ldsm_x2(uint32_t& r0, uint32_t& r1, uint32_t addr) {
    asm volatile("ldmatrix.sync.aligned.m8n8.x2.shared.b16 {%0,%1}, [%2];"
                 : "=r"(r0), "=r"(r1) : "r"(addr));
}

// ---------------- prep ----------------
__global__ __launch_bounds__(256) void gather_kernel(const int* __restrict__ title,
                                                     const float* __restrict__ word_emb) {
    int bn = blockIdx.x;
    __half* X = g_X + (long)bn * 32 * EeP;
    const __half z = __float2half(0.f);
    for (int i = threadIdx.x; i < EeP; i += 256) { X[i] = z; X[31 * EeP + i] = z; }
    const int* tw = title + bn * Tt;
    for (int idx = threadIdx.x; idx < Tt * EeP; idx += 256) {
        int s = idx / EeP, e = idx - s * EeP;
        float v = (e < Ee) ? word_emb[(long)tw[s] * Ee + e] : 0.f;
        X[(s + 1) * EeP + e] = __float2half_rn(v);
    }
}
__global__ void wtr_kernel(const float* __restrict__ conv_w) {
    int i = blockIdx.x * 256 + threadIdx.x;
    if (i >= FNf * KCv) return;
    int n = i / KCv, k = i - n * KCv;
    int tap = k / EeP, e = k - tap * EeP;
    float v = (e < Ee) ? conv_w[(tap * Ee + e) * FNf + n] : 0.f;
    g_Wt[i] = __float2half_rn(v);
}
__global__ void vtr_kernel(const float* __restrict__ v) {
    int i = blockIdx.x * 256 + threadIdx.x;
    if (i >= 208 * KP) return;
    int a = i / KP, f = i - a * KP;
    float x = (a < Aa && f < FNf) ? v[f * Aa + a] : 0.f;
    g_vT[i] = __float2half_rn(x);
}
__global__ void wihh_kernel(const float* __restrict__ W_ih) {
    int i = blockIdx.x * 256 + threadIdx.x;
    if (i >= 1200 * KP) return;
    int n = i / KP, k = i - n * KP;
    float x = (k < FNf) ? W_ih[n * FNf + k] : 0.f;
    g_Wih[i] = __float2half_rn(x);
}
__global__ void whh_kernel(const float* __restrict__ W_hh) {
    int i = blockIdx.x * 256 + threadIdx.x;
    if (i >= 1200 * Gg) return;
    g_Whh[i] = __float2half_rn(W_hh[i]);
}

// ---------------- fp16 cp.async GEMM with ldmatrix fragments ----------------
// EPI 0: conv rows via g_X map; bias+ReLU -> half OutH[.][416]
// EPI 1: attn; tanh(+vb)*q block-reduce -> OutF[row] (g_scores)
// EPI 2: GX; bias; plain fp32 store to OutF[r][1200]
template <int MT, int NT, int EPI, int MINB>
__global__ __launch_bounds__(256, MINB) void hgemm(const __half* __restrict__ A,
                                                   const __half* __restrict__ B,
                                                   float* __restrict__ OutF,
                                                   __half* __restrict__ OutH,
                                                   const float* __restrict__ bias,
                                                   const float* __restrict__ qv,
                                                   int colbase, int lda, int ldb,
                                                   int Ksteps, int Nvalid) {
    constexpr int NTILE = NT * 16;
    constexpr int ASTh = MT * LDKH;
    constexpr int BSTh = NTILE * LDKH;
    constexpr int ACH = MT / 64;
    constexpr int BCH = (NTILE * 4 + 255) / 256;
    constexpr int NB = NTILE * 4;
    constexpr int MTt = MT / 64;
    constexpr int NP = NT / 2;
    extern __shared__ __half dsm[];
    __shared__ float s_bias[224];
    __shared__ float s_qv[224];
    __shared__ float s_red[256];

    int tid = threadIdx.x, lane = tid & 31, wid = tid >> 5;
    int warpM = wid & 3, warpN = wid >> 2;
    int row0 = blockIdx.y * MT;
    int col0 = colbase + blockIdx.x * NTILE;

    for (int i = tid; i < NTILE; i += 256) {
        int c = col0 + i;
        s_bias[i] = (c < Nvalid) ? bias[c] : 0.f;
        if (EPI == 1) s_qv[i] = (c < Nvalid) ? qv[c] : 0.f;
    }
    if (EPI == 1) for (int i = tid; i < MT; i += 256) s_red[i] = 0.f;

    uint32_t su = smem_u32(dsm);
    const __half* aptr[ACH];
    uint32_t aoff[ACH];
#pragma unroll
    for (int j = 0; j < ACH; j++) {
        int i = tid + j * 256;
        int m = i >> 2, kc = i & 3;
        int gr = row0 + m;
        long ro;
        if (EPI == 0) ro = (long)(gr / Tt) * (32 * EeP) + (long)(gr % Tt) * EeP;
        else          ro = (long)gr * lda;
        aptr[j] = A + ro + kc * 8;
        aoff[j] = (uint32_t)(m * 80 + kc * 16);
    }
    const __half* bptr[BCH];
    uint32_t boff[BCH];
    bool bok[BCH];
#pragma unroll
    for (int j = 0; j < BCH; j++) {
        int i = tid + j * 256;
        bok[j] = (i < NB);
        int n = i >> 2, kc = i & 3;
        if (!bok[j]) { n = 0; kc = 0; }
        bptr[j] = B + (long)(col0 + n) * ldb + kc * 8;
        boff[j] = (uint32_t)(n * 80 + kc * 16);
    }

    uint32_t aLd[MTt];
#pragma unroll
    for (int mt = 0; mt < MTt; mt++)
        aLd[mt] = (uint32_t)((warpM * (MT / 4) + mt * 16 + (lane & 15)) * 80 +
                             ((lane >> 4) * 16));
    uint32_t bLd4[(NP > 0) ? NP : 1];
#pragma unroll
    for (int p = 0; p < NP; p++)
        bLd4[p] = (uint32_t)((warpN * NT * 8 + p * 16 + (lane & 7) + ((lane >> 4) * 8)) * 80 +
                             (((lane >> 3) & 1) * 16));
    uint32_t bLd2 = 0;
    if (NT & 1) {
        int l15 = lane & 15;
        bLd2 = (uint32_t)((warpN * NT * 8 + (NT - 1) * 8 + (l15 & 7)) * 80 +
                          ((l15 >> 3) * 16));
    }

    float acc[MTt][NT][4];
#pragma unroll
    for (int i = 0; i < MTt; i++)
#pragma unroll
        for (int j = 0; j < NT; j++)
#pragma unroll
            for (int k = 0; k < 4; k++) acc[i][j][k] = 0.f;

#define LOAD_STAGE(s, buf)                                                        \
    {                                                                             \
        uint32_t ab = su + (uint32_t)(buf) * (ASTh * 2);                          \
        _Pragma("unroll")                                                         \
        for (int j = 0; j < ACH; j++) cpasync16(ab + aoff[j], aptr[j] + (s) * 32);\
        uint32_t bb = su + (uint32_t)(3 * ASTh + (buf) * BSTh) * 2;               \
        _Pragma("unroll")                                                         \
        for (int j = 0; j < BCH; j++)                                             \
            if (bok[j]) cpasync16(bb + boff[j], bptr[j] + (s) * 32);              \
        cpcommit();                                                               \
    }

    LOAD_STAGE(0, 0)
    LOAD_STAGE(1, 1)
    cpwait<1>();
    __syncthreads();

    int r4 = lane >> 2, c4 = lane & 3;

    for (int s = 0; s < Ksteps; s++) {
        int buf = s % 3;
        uint32_t Abase = su + (uint32_t)buf * (ASTh * 2);
        uint32_t Bbase = su + (uint32_t)(3 * ASTh + buf * BSTh) * 2;
#pragma unroll
        for (int kh = 0; kh < 2; kh++) {
            uint32_t khoff = kh * 32;
            uint32_t af[MTt][4], bfr[NT][2];
#pragma unroll
            for (int mt = 0; mt < MTt; mt++)
                ldsm_x4(af[mt][0], af[mt][1], af[mt][2], af[mt][3],
                        Abase + aLd[mt] + khoff);
#pragma unroll
            for (int p = 0; p < NP; p++)
                ldsm_x4(bfr[2 * p][0], bfr[2 * p][1], bfr[2 * p + 1][0], bfr[2 * p + 1][1],
                        Bbase + bLd4[p] + khoff);
            if (NT & 1)
                ldsm_x2(bfr[NT - 1][0], bfr[NT - 1][1], Bbase + bLd2 + khoff);
#pragma unroll
            for (int nt = 0; nt < NT; nt++)
#pragma unroll
                for (int mt = 0; mt < MTt; mt++)
                    mma16816(acc[mt][nt], af[mt], bfr[nt][0], bfr[nt][1]);
        }
        if (s + 2 < Ksteps) {
            int nb = (s + 2) % 3;
            LOAD_STAGE(s + 2, nb)
            cpwait<1>();
        } else {
            cpwait<0>();
        }
        __syncthreads();
    }
#undef LOAD_STAGE

    if (EPI == 0) {
#pragma unroll
        for (int mt = 0; mt < MTt; mt++) {
            int r = row0 + warpM * (MT / 4) + mt * 16 + r4;
#pragma unroll
            for (int nt = 0; nt < NT; nt++) {
                int il = warpN * NT * 8 + nt * 8 + c4 * 2;
                int c = col0 + il;
                float b0 = s_bias[il], b1 = s_bias[il + 1];
                __half2 h0 = __floats2half2_rn(fmaxf(acc[mt][nt][0] + b0, 0.f),
                                               fmaxf(acc[mt][nt][1] + b1, 0.f));
                __half2 h1 = __floats2half2_rn(fmaxf(acc[mt][nt][2] + b0, 0.f),
                                               fmaxf(acc[mt][nt][3] + b1, 0.f));
                *(__half2*)&OutH[(long)r * KP + c] = h0;
                *(__half2*)&OutH[(long)(r + 8) * KP + c] = h1;
            }
        }
    } else if (EPI == 1) {
#pragma unroll
        for (int mt = 0; mt < MTt; mt++) {
            float slo = 0.f, shi = 0.f;
#pragma unroll
            for (int nt = 0; nt < NT; nt++) {
                int il = warpN * NT * 8 + nt * 8 + c4 * 2;
                float v0 = s_bias[il], v1 = s_bias[il + 1];
                float q0 = s_qv[il], q1 = s_qv[il + 1];
                slo += tanhf(acc[mt][nt][0] + v0) * q0 + tanhf(acc[mt][nt][1] + v1) * q1;
                shi += tanhf(acc[mt][nt][2] + v0) * q0 + tanhf(acc[mt][nt][3] + v1) * q1;
            }
            slo += __shfl_xor_sync(0xffffffffu, slo, 1);
            slo += __shfl_xor_sync(0xffffffffu, slo, 2);
            shi += __shfl_xor_sync(0xffffffffu, shi, 1);
            shi += __shfl_xor_sync(0xffffffffu, shi, 2);
            if (c4 == 0) {
                int rl = warpM * (MT / 4) + mt * 16 + r4;
                atomicAdd(&s_red[rl], slo);
                atomicAdd(&s_red[rl + 8], shi);
            }
        }
        __syncthreads();
        for (int i = tid; i < MT; i += 256) OutF[row0 + i] = s_red[i];
    } else {
#pragma unroll
        for (int mt = 0; mt < MTt; mt++) {
            int r0 = row0 + warpM * (MT / 4) + mt * 16 + r4;
            int r1 = r0 + 8;
#pragma unroll
            for (int nt = 0; nt < NT; nt++) {
                int il = warpN * NT * 8 + nt * 8 + c4 * 2;
                int c = col0 + il;
                float b0 = s_bias[il], b1 = s_bias[il + 1];
                *(float2*)&OutF[(long)r0 * 1200 + c] =
                    make_float2(acc[mt][nt][0] + b0, acc[mt][nt][1] + b1);
                *(float2*)&OutF[(long)r1 * 1200 + c] =
                    make_float2(acc[mt][nt][2] + b0, acc[mt][nt][3] + b1);
            }
        }
    }
}

// ---------------- GX transpose: [r=(b,n)][1200] -> [n][1200][64] ----------------
__global__ __launch_bounds__(256) void gx_transpose() {
    __shared__ float t[64][65];
    int c0 = blockIdx.x * 64;
    int n = blockIdx.y;
    for (int i = threadIdx.x; i < 4096; i += 256) {
        int bb = i >> 6, c = i & 63;
        float v = 0.f;
        if (c0 + c < 1200) v = g_GX[(long)(bb * Nn + n) * 1200 + c0 + c];
        t[c][bb] = v;
    }
    __syncthreads();
    for (int i = threadIdx.x; i < 4096; i += 256) {
        int c = i >> 6, bb = i & 63;
        if (c0 + c < 1200)
            g_GXt[((long)n * 1200 + c0 + c) * 64 + bb] = t[c][bb];
    }
}

// ---------------- softmax over titles ----------------
__global__ void softmax_kernel() {
    int idx = blockIdx.x * blockDim.x + threadIdx.x;
    if (idx >= Bb * Tt) return;
    int b = idx / Tt, t = idx - b * Tt;
    const float* s = g_scores + b * Nn * Tt + t;
    float mx = -1e30f;
    for (int n = 0; n < Nn; n++) mx = fmaxf(mx, s[n * Tt]);
    float sum = 0.f;
    for (int n = 0; n < Nn; n++) sum += __expf(s[n * Tt] - mx);
    float inv = 1.f / sum;
    float* al = g_alpha + b * Nn * Tt + t;
    for (int n = 0; n < Nn; n++) al[n * Tt] = __expf(s[n * Tt] - mx) * inv;
}

// ---------------- weighted sum over words (half C -> half E) ----------------
__global__ __launch_bounds__(128) void wsum_kernel() {
    int bn = blockIdx.x;
    __shared__ float al[Tt];
    if (threadIdx.x < Tt) al[threadIdx.x] = g_alpha[bn * Tt + threadIdx.x];
    __syncthreads();
    const __half* Cr = g_C + (long)bn * Tt * KP;
    for (int f = threadIdx.x; f < KP; f += 128) {
        float acc = 0.f;
#pragma unroll
        for (int t = 0; t < Tt; t++) acc += al[t] * __half2float(Cr[t * KP + f]);
        g_E[bn * KP + f] = __float2half_rn(acc);
    }
}

// ---------------- tensor-core persistent GRU (25 blocks) ----------------
// Block bg owns g in [bg*16, bg*16+16). W tile = 48 rows {r,z,n} x 400 (fp16 smem,
// loaded once). Per step: h[64][400] fp32 -> fp16 smem; MMA M=64,N=48,K=400;
// scalar fp32 gate epilogue keeps the recurrence exact-fp32.
__global__ __launch_bounds__(256, 1) void gru_tc(const int* __restrict__ uid,
                                                 const float* __restrict__ user_emb,
                                                 const float* __restrict__ b_ih,
                                                 const float* __restrict__ b_hh,
                                                 const int* __restrict__ lens,
                                                 float* __restrict__ out) {
    extern __shared__ __half gsm[];          // [48*408] W  | [64*408] h
    __shared__ float s_gate[48][66];
    __half* sW = gsm;
    __half* sH = gsm + 48 * 408;
    int tid = threadIdx.x, lane = tid & 31, wid = tid >> 5;
    int bg = blockIdx.x;
    int warpM = wid & 3, warpN = wid >> 2;

    // load W tile once: smem row j -> W_hh row (j/16)*400 + bg*16 + (j%16)
    for (int i = tid; i < 48 * 100; i += 256) {
        int j = i / 100, c4 = (i - j * 100) * 4;
        int grow = (j >> 4) * 400 + bg * 16 + (j & 15);
        *(uint2*)&sW[j * 408 + c4] = *(const uint2*)&g_Whh[(long)grow * Gg + c4];
    }

    int b = tid & 63, gi = tid >> 6;
    int len = lens[b];
    float myh[4], bir[4], biz[4], bin_[4], bhr[4], bhz[4], bhn[4];
    long ub = (long)uid[b] * Gg;
#pragma unroll
    for (int k = 0; k < 4; k++) {
        int gl = k * 4 + gi, gg = bg * 16 + gl;
        myh[k] = user_emb[ub + gg];
        g_h[0][b * Gg + gg] = myh[k];
        bir[k] = b_ih[gg]; biz[k] = b_ih[400 + gg]; bin_[k] = b_ih[800 + gg];
        bhr[k] = b_hh[gg]; bhz[k] = b_hh[400 + gg]; bhn[k] = b_hh[800 + gg];
    }

    uint32_t sHu = smem_u32(sH), sWu = smem_u32(sW);
    uint32_t aLd = sHu + (uint32_t)((warpM * 16 + (lane & 15)) * 816 + ((lane >> 4) * 16));
    uint32_t bLd4 = sWu + (uint32_t)((warpN * 24 + (lane & 7) + ((lane >> 4) * 8)) * 816 +
                                     (((lane >> 3) & 1) * 16));
    int l15 = lane & 15;
    uint32_t bLd2 = sWu + (uint32_t)((warpN * 24 + 16 + (l15 & 7)) * 816 + ((l15 >> 3) * 16));

    for (int n = 0; n < Nn; n++) {
        __threadfence();
        __syncthreads();
        if (tid == 0) {
            atomicAdd(&g_bar[n], 1);
            while (*((volatile int*)&g_bar[n]) < GBLK) { }
        }
        __syncthreads();
        // h fp32 -> fp16 smem
        const float* hin = g_h[n & 1];
        for (int i = tid; i < 6400; i += 256) {
            float4 v = *(const float4*)&hin[i * 4];
            int row = i / 100, c4 = (i - row * 100) * 4;
            __half2 h01 = __floats2half2_rn(v.x, v.y);
            __half2 h23 = __floats2half2_rn(v.z, v.w);
            uint2 pk;
            pk.x = *(uint32_t*)&h01;
            pk.y = *(uint32_t*)&h23;
            *(uint2*)&sH[row * 408 + c4] = pk;
        }
        __syncthreads();

        float acc[3][4] = {};
#pragma unroll 5
        for (int ks = 0; ks < 25; ks++) {
            uint32_t koff = ks * 32;
            uint32_t af[4], b0, b1, b2, b3, c0, c1;
            ldsm_x4(af[0], af[1], af[2], af[3], aLd + koff);
            ldsm_x4(b0, b1, b2, b3, bLd4 + koff);
            ldsm_x2(c0, c1, bLd2 + koff);
            mma16816(acc[0], af, b0, b1);
            mma16816(acc[1], af, b2, b3);
            mma16816(acc[2], af, c0, c1);
        }
        int brow = warpM * 16 + (lane >> 2);
#pragma unroll
        for (int nt = 0; nt < 3; nt++) {
            int col = warpN * 24 + nt * 8 + (lane & 3) * 2;
            s_gate[col][brow] = acc[nt][0];
            s_gate[col + 1][brow] = acc[nt][1];
            s_gate[col][brow + 8] = acc[nt][2];
            s_gate[col + 1][brow + 8] = acc[nt][3];
        }
        __syncthreads();

        const float* gxt = g_GXt + (long)n * 1200 * 64;
        float* hout = g_h[(n + 1) & 1];
#pragma unroll
        for (int k = 0; k < 4; k++) {
            int gl = k * 4 + gi, gg = bg * 16 + gl;
            float hr = s_gate[gl][b] + bhr[k];
            float hz = s_gate[16 + gl][b] + bhz[k];
            float hn = s_gate[32 + gl][b] + bhn[k];
            float xr = gxt[(0 * 400 + gg) * 64 + b] + bir[k];
            float xz = gxt[(400 + gg) * 64 + b] + biz[k];
            float xn = gxt[(800 + gg) * 64 + b] + bin_[k];
            float r = 1.f / (1.f + __expf(-(xr + hr)));
            float z = 1.f / (1.f + __expf(-(xz + hz)));
            float nv = tanhf(xn + r * hn);
            float hnew = (1.f - z) * nv + z * myh[k];
            if (n < len) myh[k] = hnew;
            hout[b * Gg + gg] = myh[k];
        }
    }
#pragma unroll
    for (int k = 0; k < 4; k++) {
        int gg = bg * 16 + k * 4 + gi;
        out[b * Gg + gg] = myh[k];
    }
}

// ---------------- launch ----------------
extern "C" void kernel_launch(void* const* d_in, const int* in_sizes, int n_in,
                              void* d_out, int out_size) {
    const int*   user_id  = (const int*)d_in[0];
    const int*   title    = (const int*)d_in[1];
    const int*   hist_len = (const int*)d_in[2];
    const float* word_emb = (const float*)d_in[3];
    const float* conv_w   = (const float*)d_in[4];
    const float* conv_b   = (const float*)d_in[5];
    const float* v        = (const float*)d_in[6];
    const float* vb       = (const float*)d_in[7];
    const float* q        = (const float*)d_in[8];
    const float* user_emb = (const float*)d_in[9];
    const float* W_ih     = (const float*)d_in[10];
    const float* W_hh     = (const float*)d_in[11];
    const float* b_ih     = (const float*)d_in[12];
    const float* b_hh     = (const float*)d_in[13];
    float* out = (float*)d_out;

    __half *Xp, *Wtp, *vTp, *Wihp, *Cp, *Ep;
    float *scp, *GXp;
    int* bar;
    cudaGetSymbolAddress((void**)&Xp, g_X);
    cudaGetSymbolAddress((void**)&Wtp, g_Wt);
    cudaGetSymbolAddress((void**)&vTp, g_vT);
    cudaGetSymbolAddress((void**)&Wihp, g_Wih);
    cudaGetSymbolAddress((void**)&Cp, g_C);
    cudaGetSymbolAddress((void**)&Ep, g_E);
    cudaGetSymbolAddress((void**)&scp, g_scores);
    cudaGetSymbolAddress((void**)&GXp, g_GX);
    cudaGetSymbolAddress((void**)&bar, g_bar);

    auto smemsz = [](int mt, int nt) {
        return (3 * (mt * LDKH + nt * 16 * LDKH)) * (int)sizeof(__half);
    };
    cudaFuncSetAttribute((const void*)hgemm<128, 5, 0, 2>,
                         cudaFuncAttributeMaxDynamicSharedMemorySize, smemsz(128, 5));
    cudaFuncSetAttribute((const void*)hgemm<64, 13, 1, 2>,
                         cudaFuncAttributeMaxDynamicSharedMemorySize, smemsz(64, 13));
    cudaFuncSetAttribute((const void*)hgemm<256, 8, 2, 1>,
                         cudaFuncAttributeMaxDynamicSharedMemorySize, smemsz(256, 8));
    cudaFuncSetAttribute((const void*)hgemm<256, 3, 2, 1>,
                         cudaFuncAttributeMaxDynamicSharedMemorySize, smemsz(256, 3));
    cudaFuncSetAttribute((const void*)gru_tc,
                         cudaFuncAttributeMaxDynamicSharedMemorySize, (48 + 64) * 408 * 2);

    gather_kernel<<<Bb * Nn, 256>>>(title, word_emb);
    wtr_kernel<<<(FNf * KCv + 255) / 256, 256>>>(conv_w);
    vtr_kernel<<<(208 * KP + 255) / 256, 256>>>(v);
    wihh_kernel<<<(1200 * KP + 255) / 256, 256>>>(W_ih);
    whh_kernel<<<(1200 * Gg + 255) / 256, 256>>>(W_hh);
    cudaMemsetAsync(bar, 0, 64 * sizeof(int));

    // conv: C = X @ Wt^T + b, ReLU -> half.  MT=128, N = 5 x 80 cols, K=960
    hgemm<128, 5, 0, 2><<<dim3(5, MROWS / 128), 256, smemsz(128, 5)>>>(
        Xp, Wtp, nullptr, Cp, conv_b, nullptr, 0, 0, KCv, KCv / 32, FNf);
    // attn: scores = sum_c tanh(C @ vT^T + vb) * q, all 208 cols, 2 CTA/SM
    hgemm<64, 13, 1, 2><<<dim3(1, MROWS / 64), 256, smemsz(64, 13)>>>(
        Cp, vTp, scp, nullptr, vb, q, 0, KP, KP, KP / 32, Aa);

    softmax_kernel<<<(Bb * Tt + 255) / 256, 256>>>();
    wsum_kernel<<<Bb * Nn, 128>>>();

    // GX = E @ W_ih^T + b_ih, row-major [r][1200], then transpose to [n][1200][64]
    hgemm<256, 8, 2, 1><<<dim3(9, 13), 256, smemsz(256, 8)>>>(
        Ep, Wihp, GXp, nullptr, b_ih, nullptr, 0, KP, KP, KP / 32, 1200);
    hgemm<256, 3, 2, 1><<<dim3(1, 13), 256, smemsz(256, 3)>>>(
        Ep, Wihp, GXp, nullptr, b_ih, nullptr, 1152, KP, KP, KP / 32, 1200);
    gx_transpose<<<dim3(19, Nn), 256>>>();

    gru_tc<<<GBLK, 256, (48 + 64) * 408 * 2>>>(user_id, user_emb, b_ih, b_hh, hist_len, out);
}

// round 11
// speedup vs baseline: 6.0441x; 1.1233x over previous
#include <cuda_runtime.h>
#include <cuda_fp16.h>
#include <cstdint>

#define Bb 64
#define Nn 50
#define Tt 30
#define Ee 300
#define EeP 320
#define FNf 400
#define Aa 200
#define Gg 400
#define KCv 960            // conv GEMM K = 3*320
#define KP 416             // padded K for attn/GX
#define MROWS (Bb*Nn*Tt)   // 96000
#define LDKH 40            // smem k-stride in halves (32 + 8 pad)
#define GBLK 25            // GRU blocks

// ---------------- scratch ----------------
__device__ __half g_X[(long)Bb * Nn * 32 * EeP];   // gathered embeddings
__device__ __half g_Wt[416 * KCv];                 // conv weights [416][960], rows>=400 zero
__device__ __half g_vT[208 * KP];                  // v^T padded [208][416]
__device__ __half g_Wih[1200 * KP];                // W_ih padded [1200][416]
__device__ __half g_Whh[1200 * Gg];                // W_hh fp16 [1200][400]
__device__ __half g_C[(long)MROWS * KP];           // conv out; pad cols 0
__device__ float  g_scores[MROWS];
__device__ float  g_alpha[MROWS];
__device__ __half g_E[3328 * KP];                  // news embed (rows>=3200 stay 0)
__device__ float  g_GX[3328L * 1200];              // GX row-major [r][1200]
__device__ float  g_GXt[Nn * 1200 * Bb];           // transposed: [n][3G][b]
__device__ __align__(16) __half g_hH[2][Bb * 408]; // fp16 h exchange, ping-pong
__device__ int    g_bar[64];

// ---------------- helpers ----------------
__device__ __forceinline__ uint32_t smem_u32(const void* p) {
    uint32_t a;
    asm("{ .reg .u64 t; cvta.to.shared.u64 t, %1; cvt.u32.u64 %0, t; }" : "=r"(a) : "l"(p));
    return a;
}
__device__ __forceinline__ void cpasync16(uint32_t dst, const void* src) {
    asm volatile("cp.async.cg.shared.global [%0], [%1], 16;" :: "r"(dst), "l"(src));
}
__device__ __forceinline__ void cpcommit() { asm volatile("cp.async.commit_group;" ::: "memory"); }
template <int N> __device__ __forceinline__ void cpwait() {
    asm volatile("cp.async.wait_group %0;" :: "n"(N) : "memory");
}
__device__ __forceinline__ void mma16816(float* c, const uint32_t* a, uint32_t b0, uint32_t b1) {
    asm volatile("mma.sync.aligned.m16n8k16.row.col.f32.f16.f16.f32 "
                 "{%0,%1,%2,%3}, {%4,%5,%6,%7}, {%8,%9}, {%0,%1,%2,%3};"
                 : "+f"(c[0]), "+f"(c[1]), "+f"(c[2]), "+f"(c[3])
                 : "r"(a[0]), "r"(a[1]), "r"(a[2]), "r"(a[3]), "r"(b0), "r"(b1));
}
__device__ __forceinline__ void ldsm_x4(uint32_t& r0, uint32_t& r1, uint32_t& r2, uint32_t& r3,
                                        uint32_t addr) {
    asm volatile("ldmatrix.sync.aligned.m8n8.x4.shared.b16 {%0,%1,%2,%3}, [%4];"
                 : "=r"(r0), "=r"(r1), "=r"(r2), "=r"(r3) : "r"(addr));
}
__device__ __forceinline__ void ldsm_x2(uint32_t& r0, uint32_t& r1, uint32_t addr) {
    asm volatile("ldmatrix.sync.aligned.m8n8.x2.shared.b16 {%0,%1}, [%2];"
                 : "=r"(r0), "=r"(r1) : "r"(addr));
}

// ---------------- prep ----------------
__global__ __launch_bounds__(256) void gather_kernel(const int* __restrict__ title,
                                                     const float* __restrict__ word_emb) {
    int bn = blockIdx.x;
    __half* X = g_X + (long)bn * 32 * EeP;
    const __half z = __float2half(0.f);
    for (int i = threadIdx.x; i < EeP; i += 256) { X[i] = z; X[31 * EeP + i] = z; }
    const int* tw = title + bn * Tt;
    for (int idx = threadIdx.x; idx < Tt * EeP; idx += 256) {
        int s = idx / EeP, e = idx - s * EeP;
        float v = (e < Ee) ? word_emb[(long)tw[s] * Ee + e] : 0.f;
        X[(s + 1) * EeP + e] = __float2half_rn(v);
    }
}
__global__ void wtr_kernel(const float* __restrict__ conv_w) {
    int i = blockIdx.x * 256 + threadIdx.x;
    if (i >= 416 * KCv) return;
    int n = i / KCv, k = i - n * KCv;
    int tap = k / EeP, e = k - tap * EeP;
    float v = (n < FNf && e < Ee) ? conv_w[(tap * Ee + e) * FNf + n] : 0.f;
    g_Wt[i] = __float2half_rn(v);
}
__global__ void vtr_kernel(const float* __restrict__ v) {
    int i = blockIdx.x * 256 + threadIdx.x;
    if (i >= 208 * KP) return;
    int a = i / KP, f = i - a * KP;
    float x = (a < Aa && f < FNf) ? v[f * Aa + a] : 0.f;
    g_vT[i] = __float2half_rn(x);
}
__global__ void wihh_kernel(const float* __restrict__ W_ih) {
    int i = blockIdx.x * 256 + threadIdx.x;
    if (i >= 1200 * KP) return;
    int n = i / KP, k = i - n * KP;
    float x = (k < FNf) ? W_ih[n * FNf + k] : 0.f;
    g_Wih[i] = __float2half_rn(x);
}
__global__ void whh_kernel(const float* __restrict__ W_hh) {
    int i = blockIdx.x * 256 + threadIdx.x;
    if (i >= 1200 * Gg) return;
    g_Whh[i] = __float2half_rn(W_hh[i]);
}

// ---------------- fp16 cp.async GEMM (3-stage) with ldmatrix fragments ----------------
// EPI 0: conv rows via g_X map; bias+ReLU -> half OutH[.][416]
// EPI 1: attn; tanh(+vb)*q block-reduce -> OutF[row] (g_scores)
// EPI 2: GX; bias; plain fp32 store to OutF[r][1200]
template <int MT, int NT, int EPI, int MINB>
__global__ __launch_bounds__(256, MINB) void hgemm(const __half* __restrict__ A,
                                                   const __half* __restrict__ B,
                                                   float* __restrict__ OutF,
                                                   __half* __restrict__ OutH,
                                                   const float* __restrict__ bias,
                                                   const float* __restrict__ qv,
                                                   int colbase, int lda, int ldb,
                                                   int Ksteps, int Nvalid) {
    constexpr int NTILE = NT * 16;
    constexpr int ASTh = MT * LDKH;
    constexpr int BSTh = NTILE * LDKH;
    constexpr int ACH = MT / 64;
    constexpr int BCH = (NTILE * 4 + 255) / 256;
    constexpr int NB = NTILE * 4;
    constexpr int MTt = MT / 64;
    constexpr int NP = NT / 2;
    extern __shared__ __half dsm[];
    __shared__ float s_bias[224];
    __shared__ float s_qv[224];
    __shared__ float s_red[256];

    int tid = threadIdx.x, lane = tid & 31, wid = tid >> 5;
    int warpM = wid & 3, warpN = wid >> 2;
    int row0 = blockIdx.y * MT;
    int col0 = colbase + blockIdx.x * NTILE;

    for (int i = tid; i < NTILE; i += 256) {
        int c = col0 + i;
        s_bias[i] = (c < Nvalid) ? bias[c] : 0.f;
        if (EPI == 1) s_qv[i] = (c < Nvalid) ? qv[c] : 0.f;
    }
    if (EPI == 1) for (int i = tid; i < MT; i += 256) s_red[i] = 0.f;

    uint32_t su = smem_u32(dsm);
    const __half* aptr[ACH];
    uint32_t aoff[ACH];
#pragma unroll
    for (int j = 0; j < ACH; j++) {
        int i = tid + j * 256;
        int m = i >> 2, kc = i & 3;
        int gr = row0 + m;
        long ro;
        if (EPI == 0) ro = (long)(gr / Tt) * (32 * EeP) + (long)(gr % Tt) * EeP;
        else          ro = (long)gr * lda;
        aptr[j] = A + ro + kc * 8;
        aoff[j] = (uint32_t)(m * 80 + kc * 16);
    }
    const __half* bptr[BCH];
    uint32_t boff[BCH];
    bool bok[BCH];
#pragma unroll
    for (int j = 0; j < BCH; j++) {
        int i = tid + j * 256;
        bok[j] = (i < NB);
        int n = i >> 2, kc = i & 3;
        if (!bok[j]) { n = 0; kc = 0; }
        bptr[j] = B + (long)(col0 + n) * ldb + kc * 8;
        boff[j] = (uint32_t)(n * 80 + kc * 16);
    }

    uint32_t aLd[MTt];
#pragma unroll
    for (int mt = 0; mt < MTt; mt++)
        aLd[mt] = (uint32_t)((warpM * (MT / 4) + mt * 16 + (lane & 15)) * 80 +
                             ((lane >> 4) * 16));
    uint32_t bLd4[(NP > 0) ? NP : 1];
#pragma unroll
    for (int p = 0; p < NP; p++)
        bLd4[p] = (uint32_t)((warpN * NT * 8 + p * 16 + (lane & 7) + ((lane >> 4) * 8)) * 80 +
                             (((lane >> 3) & 1) * 16));
    uint32_t bLd2 = 0;
    if (NT & 1) {
        int l15 = lane & 15;
        bLd2 = (uint32_t)((warpN * NT * 8 + (NT - 1) * 8 + (l15 & 7)) * 80 +
                          ((l15 >> 3) * 16));
    }

    float acc[MTt][NT][4];
#pragma unroll
    for (int i = 0; i < MTt; i++)
#pragma unroll
        for (int j = 0; j < NT; j++)
#pragma unroll
            for (int k = 0; k < 4; k++) acc[i][j][k] = 0.f;

#define LOAD_STAGE(s, buf)                                                        \
    {                                                                             \
        uint32_t ab = su + (uint32_t)(buf) * (ASTh * 2);                          \
        _Pragma("unroll")                                                         \
        for (int j = 0; j < ACH; j++) cpasync16(ab + aoff[j], aptr[j] + (s) * 32);\
        uint32_t bb = su + (uint32_t)(3 * ASTh + (buf) * BSTh) * 2;               \
        _Pragma("unroll")                                                         \
        for (int j = 0; j < BCH; j++)                                             \
            if (bok[j]) cpasync16(bb + boff[j], bptr[j] + (s) * 32);              \
        cpcommit();                                                               \
    }

    LOAD_STAGE(0, 0)
    LOAD_STAGE(1, 1)
    cpwait<1>();
    __syncthreads();

    int r4 = lane >> 2, c4 = lane & 3;

    for (int s = 0; s < Ksteps; s++) {
        int buf = s % 3;
        uint32_t Abase = su + (uint32_t)buf * (ASTh * 2);
        uint32_t Bbase = su + (uint32_t)(3 * ASTh + buf * BSTh) * 2;
#pragma unroll
        for (int kh = 0; kh < 2; kh++) {
            uint32_t khoff = kh * 32;
            uint32_t af[MTt][4], bfr[NT][2];
#pragma unroll
            for (int mt = 0; mt < MTt; mt++)
                ldsm_x4(af[mt][0], af[mt][1], af[mt][2], af[mt][3],
                        Abase + aLd[mt] + khoff);
#pragma unroll
            for (int p = 0; p < NP; p++)
                ldsm_x4(bfr[2 * p][0], bfr[2 * p][1], bfr[2 * p + 1][0], bfr[2 * p + 1][1],
                        Bbase + bLd4[p] + khoff);
            if (NT & 1)
                ldsm_x2(bfr[NT - 1][0], bfr[NT - 1][1], Bbase + bLd2 + khoff);
#pragma unroll
            for (int nt = 0; nt < NT; nt++)
#pragma unroll
                for (int mt = 0; mt < MTt; mt++)
                    mma16816(acc[mt][nt], af[mt], bfr[nt][0], bfr[nt][1]);
        }
        if (s + 2 < Ksteps) {
            int nb = (s + 2) % 3;
            LOAD_STAGE(s + 2, nb)
            cpwait<1>();
        } else {
            cpwait<0>();
        }
        __syncthreads();
    }
#undef LOAD_STAGE

    if (EPI == 0) {
#pragma unroll
        for (int mt = 0; mt < MTt; mt++) {
            int r = row0 + warpM * (MT / 4) + mt * 16 + r4;
#pragma unroll
            for (int nt = 0; nt < NT; nt++) {
                int il = warpN * NT * 8 + nt * 8 + c4 * 2;
                int c = col0 + il;
                if (c < KP) {
                    float b0 = s_bias[il], b1 = s_bias[il + 1];
                    __half2 h0 = __floats2half2_rn(fmaxf(acc[mt][nt][0] + b0, 0.f),
                                                   fmaxf(acc[mt][nt][1] + b1, 0.f));
                    __half2 h1 = __floats2half2_rn(fmaxf(acc[mt][nt][2] + b0, 0.f),
                                                   fmaxf(acc[mt][nt][3] + b1, 0.f));
                    *(__half2*)&OutH[(long)r * KP + c] = h0;
                    *(__half2*)&OutH[(long)(r + 8) * KP + c] = h1;
                }
            }
        }
    } else if (EPI == 1) {
#pragma unroll
        for (int mt = 0; mt < MTt; mt++) {
            float slo = 0.f, shi = 0.f;
#pragma unroll
            for (int nt = 0; nt < NT; nt++) {
                int il = warpN * NT * 8 + nt * 8 + c4 * 2;
                float v0 = s_bias[il], v1 = s_bias[il + 1];
                float q0 = s_qv[il], q1 = s_qv[il + 1];
                slo += tanhf(acc[mt][nt][0] + v0) * q0 + tanhf(acc[mt][nt][1] + v1) * q1;
                shi += tanhf(acc[mt][nt][2] + v0) * q0 + tanhf(acc[mt][nt][3] + v1) * q1;
            }
            slo += __shfl_xor_sync(0xffffffffu, slo, 1);
            slo += __shfl_xor_sync(0xffffffffu, slo, 2);
            shi += __shfl_xor_sync(0xffffffffu, shi, 1);
            shi += __shfl_xor_sync(0xffffffffu, shi, 2);
            if (c4 == 0) {
                int rl = warpM * (MT / 4) + mt * 16 + r4;
                atomicAdd(&s_red[rl], slo);
                atomicAdd(&s_red[rl + 8], shi);
            }
        }
        __syncthreads();
        for (int i = tid; i < MT; i += 256) OutF[row0 + i] = s_red[i];
    } else {
#pragma unroll
        for (int mt = 0; mt < MTt; mt++) {
            int r0 = row0 + warpM * (MT / 4) + mt * 16 + r4;
            int r1 = r0 + 8;
#pragma unroll
            for (int nt = 0; nt < NT; nt++) {
                int il = warpN * NT * 8 + nt * 8 + c4 * 2;
                int c = col0 + il;
                float b0 = s_bias[il], b1 = s_bias[il + 1];
                *(float2*)&OutF[(long)r0 * 1200 + c] =
                    make_float2(acc[mt][nt][0] + b0, acc[mt][nt][1] + b1);
                *(float2*)&OutF[(long)r1 * 1200 + c] =
                    make_float2(acc[mt][nt][2] + b0, acc[mt][nt][3] + b1);
            }
        }
    }
}

// ---------------- GX transpose: [r=(b,n)][1200] -> [n][1200][64] ----------------
__global__ __launch_bounds__(256) void gx_transpose() {
    __shared__ float t[64][65];
    int c0 = blockIdx.x * 64;
    int n = blockIdx.y;
    for (int i = threadIdx.x; i < 4096; i += 256) {
        int bb = i >> 6, c = i & 63;
        float v = 0.f;
        if (c0 + c < 1200) v = g_GX[(long)(bb * Nn + n) * 1200 + c0 + c];
        t[c][bb] = v;
    }
    __syncthreads();
    for (int i = threadIdx.x; i < 4096; i += 256) {
        int c = i >> 6, bb = i & 63;
        if (c0 + c < 1200)
            g_GXt[((long)n * 1200 + c0 + c) * 64 + bb] = t[c][bb];
    }
}

// ---------------- softmax over titles ----------------
__global__ void softmax_kernel() {
    int idx = blockIdx.x * blockDim.x + threadIdx.x;
    if (idx >= Bb * Tt) return;
    int b = idx / Tt, t = idx - b * Tt;
    const float* s = g_scores + b * Nn * Tt + t;
    float mx = -1e30f;
    for (int n = 0; n < Nn; n++) mx = fmaxf(mx, s[n * Tt]);
    float sum = 0.f;
    for (int n = 0; n < Nn; n++) sum += __expf(s[n * Tt] - mx);
    float inv = 1.f / sum;
    float* al = g_alpha + b * Nn * Tt + t;
    for (int n = 0; n < Nn; n++) al[n * Tt] = __expf(s[n * Tt] - mx) * inv;
}

// ---------------- weighted sum over words (half2 vectorized) ----------------
__global__ __launch_bounds__(128) void wsum_kernel() {
    int bn = blockIdx.x;
    __shared__ float al[Tt];
    if (threadIdx.x < Tt) al[threadIdx.x] = g_alpha[bn * Tt + threadIdx.x];
    __syncthreads();
    const __half2* Cr = (const __half2*)(g_C + (long)bn * Tt * KP);
    __half2* Er = (__half2*)(g_E + (long)bn * KP);
    for (int f = threadIdx.x; f < KP / 2; f += 128) {
        float ax = 0.f, ay = 0.f;
#pragma unroll
        for (int t = 0; t < Tt; t++) {
            float2 v = __half22float2(Cr[t * (KP / 2) + f]);
            ax += al[t] * v.x;
            ay += al[t] * v.y;
        }
        Er[f] = __floats2half2_rn(ax, ay);
    }
}

// ---------------- tensor-core persistent GRU (25 blocks, fp16 h exchange) ----------------
__global__ __launch_bounds__(256, 1) void gru_tc(const int* __restrict__ uid,
                                                 const float* __restrict__ user_emb,
                                                 const float* __restrict__ b_ih,
                                                 const float* __restrict__ b_hh,
                                                 const int* __restrict__ lens,
                                                 float* __restrict__ out) {
    extern __shared__ __half gsm[];          // [48*408] W | [64*408] h
    __shared__ float s_gate[48][66];
    __half* sW = gsm;
    __half* sH = gsm + 48 * 408;
    int tid = threadIdx.x, lane = tid & 31, wid = tid >> 5;
    int bg = blockIdx.x;
    int warpM = wid & 3, warpN = wid >> 2;

    for (int i = tid; i < 48 * 100; i += 256) {
        int j = i / 100, c4 = (i - j * 100) * 4;
        int grow = (j >> 4) * 400 + bg * 16 + (j & 15);
        *(uint2*)&sW[j * 408 + c4] = *(const uint2*)&g_Whh[(long)grow * Gg + c4];
    }

    int b = tid & 63, gi = tid >> 6;
    int len = lens[b];
    float myh[4], bir[4], biz[4], bin_[4], bhr[4], bhz[4], bhn[4];
    long ub = (long)uid[b] * Gg;
#pragma unroll
    for (int k = 0; k < 4; k++) {
        int gl = gi * 4 + k, gg = bg * 16 + gl;
        myh[k] = user_emb[ub + gg];
        bir[k] = b_ih[gg]; biz[k] = b_ih[400 + gg]; bin_[k] = b_ih[800 + gg];
        bhr[k] = b_hh[gg]; bhz[k] = b_hh[400 + gg]; bhn[k] = b_hh[800 + gg];
    }
    {
        __half2 p01 = __floats2half2_rn(myh[0], myh[1]);
        __half2 p23 = __floats2half2_rn(myh[2], myh[3]);
        uint2 pk = make_uint2(*(uint32_t*)&p01, *(uint32_t*)&p23);
        *(uint2*)&g_hH[0][b * 408 + bg * 16 + gi * 4] = pk;
    }

    uint32_t sHu = smem_u32(sH), sWu = smem_u32(sW);
    uint32_t aLd = sHu + (uint32_t)((warpM * 16 + (lane & 15)) * 816 + ((lane >> 4) * 16));
    uint32_t bLd4 = sWu + (uint32_t)((warpN * 24 + (lane & 7) + ((lane >> 4) * 8)) * 816 +
                                     (((lane >> 3) & 1) * 16));
    int l15 = lane & 15;
    uint32_t bLd2 = sWu + (uint32_t)((warpN * 24 + 16 + (l15 & 7)) * 816 + ((l15 >> 3) * 16));

    for (int n = 0; n < Nn; n++) {
        __threadfence();
        __syncthreads();
        if (tid == 0) {
            atomicAdd(&g_bar[n], 1);
            while (*((volatile int*)&g_bar[n]) < GBLK) { }
        }
        __syncthreads();
        const __half* hbuf = g_hH[n & 1];
        for (int i = tid; i < 64 * 51; i += 256) {
            int row = i / 51, c = i - row * 51;
            cpasync16(sHu + (uint32_t)(row * 816 + c * 16), hbuf + row * 408 + c * 8);
        }
        cpcommit();
        cpwait<0>();
        __syncthreads();

        float acc[3][4] = {};
#pragma unroll 5
        for (int ks = 0; ks < 25; ks++) {
            uint32_t koff = ks * 32;
            uint32_t af[4], b0, b1, b2, b3, c0, c1;
            ldsm_x4(af[0], af[1], af[2], af[3], aLd + koff);
            ldsm_x4(b0, b1, b2, b3, bLd4 + koff);
            ldsm_x2(c0, c1, bLd2 + koff);
            mma16816(acc[0], af, b0, b1);
            mma16816(acc[1], af, b2, b3);
            mma16816(acc[2], af, c0, c1);
        }
        int brow = warpM * 16 + (lane >> 2);
#pragma unroll
        for (int nt = 0; nt < 3; nt++) {
            int col = warpN * 24 + nt * 8 + (lane & 3) * 2;
            s_gate[col][brow] = acc[nt][0];
            s_gate[col + 1][brow] = acc[nt][1];
            s_gate[col][brow + 8] = acc[nt][2];
            s_gate[col + 1][brow + 8] = acc[nt][3];
        }
        __syncthreads();

        const float* gxt = g_GXt + (long)n * 1200 * 64;
#pragma unroll
        for (int k = 0; k < 4; k++) {
            int gl = gi * 4 + k, gg = bg * 16 + gl;
            float hr = s_gate[gl][b] + bhr[k];
            float hz = s_gate[16 + gl][b] + bhz[k];
            float hn = s_gate[32 + gl][b] + bhn[k];
            float xr = gxt[(0 * 400 + gg) * 64 + b] + bir[k];
            float xz = gxt[(400 + gg) * 64 + b] + biz[k];
            float xn = gxt[(800 + gg) * 64 + b] + bin_[k];
            float r = 1.f / (1.f + __expf(-(xr + hr)));
            float z = 1.f / (1.f + __expf(-(xz + hz)));
            float nv = tanhf(xn + r * hn);
            float hnew = (1.f - z) * nv + z * myh[k];
            if (n < len) myh[k] = hnew;
        }
        {
            __half2 p01 = __floats2half2_rn(myh[0], myh[1]);
            __half2 p23 = __floats2half2_rn(myh[2], myh[3]);
            uint2 pk = make_uint2(*(uint32_t*)&p01, *(uint32_t*)&p23);
            *(uint2*)&g_hH[(n + 1) & 1][b * 408 + bg * 16 + gi * 4] = pk;
        }
    }
#pragma unroll
    for (int k = 0; k < 4; k++) {
        int gg = bg * 16 + gi * 4 + k;
        out[b * Gg + gg] = myh[k];
    }
}

// ---------------- launch ----------------
extern "C" void kernel_launch(void* const* d_in, const int* in_sizes, int n_in,
                              void* d_out, int out_size) {
    const int*   user_id  = (const int*)d_in[0];
    const int*   title    = (const int*)d_in[1];
    const int*   hist_len = (const int*)d_in[2];
    const float* word_emb = (const float*)d_in[3];
    const float* conv_w   = (const float*)d_in[4];
    const float* conv_b   = (const float*)d_in[5];
    const float* v        = (const float*)d_in[6];
    const float* vb       = (const float*)d_in[7];
    const float* q        = (const float*)d_in[8];
    const float* user_emb = (const float*)d_in[9];
    const float* W_ih     = (const float*)d_in[10];
    const float* W_hh     = (const float*)d_in[11];
    const float* b_ih     = (const float*)d_in[12];
    const float* b_hh     = (const float*)d_in[13];
    float* out = (float*)d_out;

    __half *Xp, *Wtp, *vTp, *Wihp, *Cp, *Ep;
    float *scp, *GXp;
    int* bar;
    cudaGetSymbolAddress((void**)&Xp, g_X);
    cudaGetSymbolAddress((void**)&Wtp, g_Wt);
    cudaGetSymbolAddress((void**)&vTp, g_vT);
    cudaGetSymbolAddress((void**)&Wihp, g_Wih);
    cudaGetSymbolAddress((void**)&Cp, g_C);
    cudaGetSymbolAddress((void**)&Ep, g_E);
    cudaGetSymbolAddress((void**)&scp, g_scores);
    cudaGetSymbolAddress((void**)&GXp, g_GX);
    cudaGetSymbolAddress((void**)&bar, g_bar);

    auto smemsz = [](int mt, int nt) {
        return (3 * (mt * LDKH + nt * 16 * LDKH)) * (int)sizeof(__half);
    };
    cudaFuncSetAttribute((const void*)hgemm<64, 13, 0, 2>,
                         cudaFuncAttributeMaxDynamicSharedMemorySize, smemsz(64, 13));
    cudaFuncSetAttribute((const void*)hgemm<64, 13, 1, 2>,
                         cudaFuncAttributeMaxDynamicSharedMemorySize, smemsz(64, 13));
    cudaFuncSetAttribute((const void*)hgemm<256, 8, 2, 1>,
                         cudaFuncAttributeMaxDynamicSharedMemorySize, smemsz(256, 8));
    cudaFuncSetAttribute((const void*)hgemm<256, 3, 2, 1>,
                         cudaFuncAttributeMaxDynamicSharedMemorySize, smemsz(256, 3));
    cudaFuncSetAttribute((const void*)gru_tc,
                         cudaFuncAttributeMaxDynamicSharedMemorySize, (48 + 64) * 408 * 2);

    gather_kernel<<<Bb * Nn, 256>>>(title, word_emb);
    wtr_kernel<<<(416 * KCv + 255) / 256, 256>>>(conv_w);
    vtr_kernel<<<(208 * KP + 255) / 256, 256>>>(v);
    wihh_kernel<<<(1200 * KP + 255) / 256, 256>>>(W_ih);
    whh_kernel<<<(1200 * Gg + 255) / 256, 256>>>(W_hh);
    cudaMemsetAsync(bar, 0, 64 * sizeof(int));

    // conv: C = X @ Wt^T + b, ReLU -> half. MT=64, 2 col tiles of 208, 3-stage, 2 CTA/SM
    hgemm<64, 13, 0, 2><<<dim3(2, MROWS / 64), 256, smemsz(64, 13)>>>(
        Xp, Wtp, nullptr, Cp, conv_b, nullptr, 0, 0, KCv, KCv / 32, FNf);
    // attn: scores = sum_c tanh(C @ vT^T + vb) * q, all 208 cols, 2 CTA/SM
    hgemm<64, 13, 1, 2><<<dim3(1, MROWS / 64), 256, smemsz(64, 13)>>>(
        Cp, vTp, scp, nullptr, vb, q, 0, KP, KP, KP / 32, Aa);

    softmax_kernel<<<(Bb * Tt + 255) / 256, 256>>>();
    wsum_kernel<<<Bb * Nn, 128>>>();

    // GX = E @ W_ih^T + b_ih, row-major [r][1200], then transpose to [n][1200][64]
    hgemm<256, 8, 2, 1><<<dim3(9, 13), 256, smemsz(256, 8)>>>(
        Ep, Wihp, GXp, nullptr, b_ih, nullptr, 0, KP, KP, KP / 32, 1200);
    hgemm<256, 3, 2, 1><<<dim3(1, 13), 256, smemsz(256, 3)>>>(
        Ep, Wihp, GXp, nullptr, b_ih, nullptr, 1152, KP, KP, KP / 32, 1200);
    gx_transpose<<<dim3(19, Nn), 256>>>();

    gru_tc<<<GBLK, 256, (48 + 64) * 408 * 2>>>(user_id, user_emb, b_ih, b_hh, hist_len, out);
}

// round 12
// speedup vs baseline: 6.0896x; 1.0075x over previous
#include <cuda_runtime.h>
#include <cuda_fp16.h>
#include <cstdint>

#define Bb 64
#define Nn 50
#define Tt 30
#define Ee 300
#define EeP 320
#define FNf 400
#define Aa 200
#define Gg 400
#define KCv 960            // conv GEMM K = 3*320
#define KP 416             // padded K for attn/GX
#define MROWS (Bb*Nn*Tt)   // 96000
#define LDKH 40            // smem k-stride in halves (32 + 8 pad)
#define GBLK 25            // GRU blocks

// ---------------- scratch ----------------
__device__ __half g_X[(long)Bb * Nn * 32 * EeP];   // gathered embeddings
__device__ __half g_Wt[416 * KCv];                 // conv weights [416][960], rows>=400 zero
__device__ __half g_vT[208 * KP];                  // v^T padded [208][416]
__device__ __half g_Wih[1200 * KP];                // W_ih padded [1200][416]
__device__ __half g_Whh[1200 * Gg];                // W_hh fp16 [1200][400]
__device__ __half g_C[(long)MROWS * KP];           // conv out; pad cols 0
__device__ float  g_scores[MROWS];
__device__ float  g_alpha[MROWS];
__device__ __half g_E[3328 * KP];                  // news embed (rows>=3200 stay 0)
__device__ float  g_GX[3328L * 1200];              // GX row-major [r][1200]
__device__ float  g_GXt[Nn * 1200 * Bb];           // transposed: [n][3G][b]
__device__ __align__(16) __half g_hH[2][Bb * 408]; // fp16 h exchange, ping-pong
__device__ int    g_bar[64];

// ---------------- helpers ----------------
__device__ __forceinline__ uint32_t smem_u32(const void* p) {
    uint32_t a;
    asm("{ .reg .u64 t; cvta.to.shared.u64 t, %1; cvt.u32.u64 %0, t; }" : "=r"(a) : "l"(p));
    return a;
}
__device__ __forceinline__ void cpasync16(uint32_t dst, const void* src) {
    asm volatile("cp.async.cg.shared.global [%0], [%1], 16;" :: "r"(dst), "l"(src));
}
__device__ __forceinline__ void cpcommit() { asm volatile("cp.async.commit_group;" ::: "memory"); }
template <int N> __device__ __forceinline__ void cpwait() {
    asm volatile("cp.async.wait_group %0;" :: "n"(N) : "memory");
}
__device__ __forceinline__ void mma16816(float* c, const uint32_t* a, uint32_t b0, uint32_t b1) {
    asm volatile("mma.sync.aligned.m16n8k16.row.col.f32.f16.f16.f32 "
                 "{%0,%1,%2,%3}, {%4,%5,%6,%7}, {%8,%9}, {%0,%1,%2,%3};"
                 : "+f"(c[0]), "+f"(c[1]), "+f"(c[2]), "+f"(c[3])
                 : "r"(a[0]), "r"(a[1]), "r"(a[2]), "r"(a[3]), "r"(b0), "r"(b1));
}
__device__ __forceinline__ void ldsm_x4(uint32_t& r0, uint32_t& r1, uint32_t& r2, uint32_t& r3,
                                        uint32_t addr) {
    asm volatile("ldmatrix.sync.aligned.m8n8.x4.shared.b16 {%0,%1,%2,%3}, [%4];"
                 : "=r"(r0), "=r"(r1), "=r"(r2), "=r"(r3) : "r"(addr));
}
__device__ __forceinline__ void ldsm_x2(uint32_t& r0, uint32_t& r1, uint32_t addr) {
    asm volatile("ldmatrix.sync.aligned.m8n8.x2.shared.b16 {%0,%1}, [%2];"
                 : "=r"(r0), "=r"(r1) : "r"(addr));
}

// ---------------- prep ----------------
__global__ __launch_bounds__(256) void gather_kernel(const int* __restrict__ title,
                                                     const float* __restrict__ word_emb) {
    int bn = blockIdx.x;
    __half* X = g_X + (long)bn * 32 * EeP;
    const __half z = __float2half(0.f);
    for (int i = threadIdx.x; i < EeP; i += 256) { X[i] = z; X[31 * EeP + i] = z; }
    const int* tw = title + bn * Tt;
    for (int idx = threadIdx.x; idx < Tt * EeP; idx += 256) {
        int s = idx / EeP, e = idx - s * EeP;
        float v = (e < Ee) ? word_emb[(long)tw[s] * Ee + e] : 0.f;
        X[(s + 1) * EeP + e] = __float2half_rn(v);
    }
}
__global__ void wtr_kernel(const float* __restrict__ conv_w) {
    int i = blockIdx.x * 256 + threadIdx.x;
    if (i >= 416 * KCv) return;
    int n = i / KCv, k = i - n * KCv;
    int tap = k / EeP, e = k - tap * EeP;
    float v = (n < FNf && e < Ee) ? conv_w[(tap * Ee + e) * FNf + n] : 0.f;
    g_Wt[i] = __float2half_rn(v);
}
__global__ void vtr_kernel(const float* __restrict__ v) {
    int i = blockIdx.x * 256 + threadIdx.x;
    if (i >= 208 * KP) return;
    int a = i / KP, f = i - a * KP;
    float x = (a < Aa && f < FNf) ? v[f * Aa + a] : 0.f;
    g_vT[i] = __float2half_rn(x);
}
__global__ void wihh_kernel(const float* __restrict__ W_ih) {
    int i = blockIdx.x * 256 + threadIdx.x;
    if (i >= 1200 * KP) return;
    int n = i / KP, k = i - n * KP;
    float x = (k < FNf) ? W_ih[n * FNf + k] : 0.f;
    g_Wih[i] = __float2half_rn(x);
}
__global__ void whh_kernel(const float* __restrict__ W_hh) {
    int i = blockIdx.x * 256 + threadIdx.x;
    if (i >= 1200 * Gg) return;
    g_Whh[i] = __float2half_rn(W_hh[i]);
}

// ---------------- fp16 cp.async GEMM (3-stage) with ldmatrix fragments ----------------
// EPI 0: conv rows via g_X map; bias+ReLU -> half OutH[.][416]
// EPI 1: attn; tanh(+vb)*q block-reduce -> OutF[row] (g_scores)
// EPI 2: GX; bias; plain fp32 store to OutF[r][1200]
template <int MT, int NT, int EPI, int MINB>
__global__ __launch_bounds__(256, MINB) void hgemm(const __half* __restrict__ A,
                                                   const __half* __restrict__ B,
                                                   float* __restrict__ OutF,
                                                   __half* __restrict__ OutH,
                                                   const float* __restrict__ bias,
                                                   const float* __restrict__ qv,
                                                   int colbase, int lda, int ldb,
                                                   int Ksteps, int Nvalid) {
    constexpr int NTILE = NT * 16;
    constexpr int ASTh = MT * LDKH;
    constexpr int BSTh = NTILE * LDKH;
    constexpr int ACH = MT / 64;
    constexpr int BCH = (NTILE * 4 + 255) / 256;
    constexpr int NB = NTILE * 4;
    constexpr int MTt = MT / 64;
    constexpr int NP = NT / 2;
    extern __shared__ __half dsm[];
    __shared__ float s_bias[224];
    __shared__ float s_qv[224];
    __shared__ float s_red[256];

    int tid = threadIdx.x, lane = tid & 31, wid = tid >> 5;
    int warpM = wid & 3, warpN = wid >> 2;
    int row0 = blockIdx.y * MT;
    int col0 = colbase + blockIdx.x * NTILE;

    for (int i = tid; i < NTILE; i += 256) {
        int c = col0 + i;
        s_bias[i] = (c < Nvalid) ? bias[c] : 0.f;
        if (EPI == 1) s_qv[i] = (c < Nvalid) ? qv[c] : 0.f;
    }
    if (EPI == 1) for (int i = tid; i < MT; i += 256) s_red[i] = 0.f;

    uint32_t su = smem_u32(dsm);
    const __half* aptr[ACH];
    uint32_t aoff[ACH];
#pragma unroll
    for (int j = 0; j < ACH; j++) {
        int i = tid + j * 256;
        int m = i >> 2, kc = i & 3;
        int gr = row0 + m;
        long ro;
        if (EPI == 0) ro = (long)(gr / Tt) * (32 * EeP) + (long)(gr % Tt) * EeP;
        else          ro = (long)gr * lda;
        aptr[j] = A + ro + kc * 8;
        aoff[j] = (uint32_t)(m * 80 + kc * 16);
    }
    const __half* bptr[BCH];
    uint32_t boff[BCH];
    bool bok[BCH];
#pragma unroll
    for (int j = 0; j < BCH; j++) {
        int i = tid + j * 256;
        bok[j] = (i < NB);
        int n = i >> 2, kc = i & 3;
        if (!bok[j]) { n = 0; kc = 0; }
        bptr[j] = B + (long)(col0 + n) * ldb + kc * 8;
        boff[j] = (uint32_t)(n * 80 + kc * 16);
    }

    uint32_t aLd[MTt];
#pragma unroll
    for (int mt = 0; mt < MTt; mt++)
        aLd[mt] = (uint32_t)((warpM * (MT / 4) + mt * 16 + (lane & 15)) * 80 +
                             ((lane >> 4) * 16));
    uint32_t bLd4[(NP > 0) ? NP : 1];
#pragma unroll
    for (int p = 0; p < NP; p++)
        bLd4[p] = (uint32_t)((warpN * NT * 8 + p * 16 + (lane & 7) + ((lane >> 4) * 8)) * 80 +
                             (((lane >> 3) & 1) * 16));
    uint32_t bLd2 = 0;
    if (NT & 1) {
        int l15 = lane & 15;
        bLd2 = (uint32_t)((warpN * NT * 8 + (NT - 1) * 8 + (l15 & 7)) * 80 +
                          ((l15 >> 3) * 16));
    }

    float acc[MTt][NT][4];
#pragma unroll
    for (int i = 0; i < MTt; i++)
#pragma unroll
        for (int j = 0; j < NT; j++)
#pragma unroll
            for (int k = 0; k < 4; k++) acc[i][j][k] = 0.f;

#define LOAD_STAGE(s, buf)                                                        \
    {                                                                             \
        uint32_t ab = su + (uint32_t)(buf) * (ASTh * 2);                          \
        _Pragma("unroll")                                                         \
        for (int j = 0; j < ACH; j++) cpasync16(ab + aoff[j], aptr[j] + (s) * 32);\
        uint32_t bb = su + (uint32_t)(3 * ASTh + (buf) * BSTh) * 2;               \
        _Pragma("unroll")                                                         \
        for (int j = 0; j < BCH; j++)                                             \
            if (bok[j]) cpasync16(bb + boff[j], bptr[j] + (s) * 32);              \
        cpcommit();                                                               \
    }

    LOAD_STAGE(0, 0)
    LOAD_STAGE(1, 1)
    cpwait<1>();
    __syncthreads();

    int r4 = lane >> 2, c4 = lane & 3;

    for (int s = 0; s < Ksteps; s++) {
        int buf = s % 3;
        uint32_t Abase = su + (uint32_t)buf * (ASTh * 2);
        uint32_t Bbase = su + (uint32_t)(3 * ASTh + buf * BSTh) * 2;
#pragma unroll
        for (int kh = 0; kh < 2; kh++) {
            uint32_t khoff = kh * 32;
            uint32_t af[MTt][4], bfr[NT][2];
#pragma unroll
            for (int mt = 0; mt < MTt; mt++)
                ldsm_x4(af[mt][0], af[mt][1], af[mt][2], af[mt][3],
                        Abase + aLd[mt] + khoff);
#pragma unroll
            for (int p = 0; p < NP; p++)
                ldsm_x4(bfr[2 * p][0], bfr[2 * p][1], bfr[2 * p + 1][0], bfr[2 * p + 1][1],
                        Bbase + bLd4[p] + khoff);
            if (NT & 1)
                ldsm_x2(bfr[NT - 1][0], bfr[NT - 1][1], Bbase + bLd2 + khoff);
#pragma unroll
            for (int nt = 0; nt < NT; nt++)
#pragma unroll
                for (int mt = 0; mt < MTt; mt++)
                    mma16816(acc[mt][nt], af[mt], bfr[nt][0], bfr[nt][1]);
        }
        if (s + 2 < Ksteps) {
            int nb = (s + 2) % 3;
            LOAD_STAGE(s + 2, nb)
            cpwait<1>();
        } else {
            cpwait<0>();
        }
        __syncthreads();
    }
#undef LOAD_STAGE

    if (EPI == 0) {
#pragma unroll
        for (int mt = 0; mt < MTt; mt++) {
            int r = row0 + warpM * (MT / 4) + mt * 16 + r4;
#pragma unroll
            for (int nt = 0; nt < NT; nt++) {
                int il = warpN * NT * 8 + nt * 8 + c4 * 2;
                int c = col0 + il;
                if (c < KP) {
                    float b0 = s_bias[il], b1 = s_bias[il + 1];
                    __half2 h0 = __floats2half2_rn(fmaxf(acc[mt][nt][0] + b0, 0.f),
                                                   fmaxf(acc[mt][nt][1] + b1, 0.f));
                    __half2 h1 = __floats2half2_rn(fmaxf(acc[mt][nt][2] + b0, 0.f),
                                                   fmaxf(acc[mt][nt][3] + b1, 0.f));
                    *(__half2*)&OutH[(long)r * KP + c] = h0;
                    *(__half2*)&OutH[(long)(r + 8) * KP + c] = h1;
                }
            }
        }
    } else if (EPI == 1) {
#pragma unroll
        for (int mt = 0; mt < MTt; mt++) {
            float slo = 0.f, shi = 0.f;
#pragma unroll
            for (int nt = 0; nt < NT; nt++) {
                int il = warpN * NT * 8 + nt * 8 + c4 * 2;
                float v0 = s_bias[il], v1 = s_bias[il + 1];
                float q0 = s_qv[il], q1 = s_qv[il + 1];
                slo += tanhf(acc[mt][nt][0] + v0) * q0 + tanhf(acc[mt][nt][1] + v1) * q1;
                shi += tanhf(acc[mt][nt][2] + v0) * q0 + tanhf(acc[mt][nt][3] + v1) * q1;
            }
            slo += __shfl_xor_sync(0xffffffffu, slo, 1);
            slo += __shfl_xor_sync(0xffffffffu, slo, 2);
            shi += __shfl_xor_sync(0xffffffffu, shi, 1);
            shi += __shfl_xor_sync(0xffffffffu, shi, 2);
            if (c4 == 0) {
                int rl = warpM * (MT / 4) + mt * 16 + r4;
                atomicAdd(&s_red[rl], slo);
                atomicAdd(&s_red[rl + 8], shi);
            }
        }
        __syncthreads();
        for (int i = tid; i < MT; i += 256) OutF[row0 + i] = s_red[i];
    } else {
#pragma unroll
        for (int mt = 0; mt < MTt; mt++) {
            int r0 = row0 + warpM * (MT / 4) + mt * 16 + r4;
            int r1 = r0 + 8;
#pragma unroll
            for (int nt = 0; nt < NT; nt++) {
                int il = warpN * NT * 8 + nt * 8 + c4 * 2;
                int c = col0 + il;
                float b0 = s_bias[il], b1 = s_bias[il + 1];
                *(float2*)&OutF[(long)r0 * 1200 + c] =
                    make_float2(acc[mt][nt][0] + b0, acc[mt][nt][1] + b1);
                *(float2*)&OutF[(long)r1 * 1200 + c] =
                    make_float2(acc[mt][nt][2] + b0, acc[mt][nt][3] + b1);
            }
        }
    }
}

// ---------------- GX transpose: [r=(b,n)][1200] -> [n][1200][64] ----------------
__global__ __launch_bounds__(256) void gx_transpose() {
    __shared__ float t[64][65];
    int c0 = blockIdx.x * 64;
    int n = blockIdx.y;
    for (int i = threadIdx.x; i < 4096; i += 256) {
        int bb = i >> 6, c = i & 63;
        float v = 0.f;
        if (c0 + c < 1200) v = g_GX[(long)(bb * Nn + n) * 1200 + c0 + c];
        t[c][bb] = v;
    }
    __syncthreads();
    for (int i = threadIdx.x; i < 4096; i += 256) {
        int c = i >> 6, bb = i & 63;
        if (c0 + c < 1200)
            g_GXt[((long)n * 1200 + c0 + c) * 64 + bb] = t[c][bb];
    }
}

// ---------------- softmax over titles ----------------
__global__ void softmax_kernel() {
    int idx = blockIdx.x * blockDim.x + threadIdx.x;
    if (idx >= Bb * Tt) return;
    int b = idx / Tt, t = idx - b * Tt;
    const float* s = g_scores + b * Nn * Tt + t;
    float mx = -1e30f;
    for (int n = 0; n < Nn; n++) mx = fmaxf(mx, s[n * Tt]);
    float sum = 0.f;
    for (int n = 0; n < Nn; n++) sum += __expf(s[n * Tt] - mx);
    float inv = 1.f / sum;
    float* al = g_alpha + b * Nn * Tt + t;
    for (int n = 0; n < Nn; n++) al[n * Tt] = __expf(s[n * Tt] - mx) * inv;
}

// ---------------- weighted sum over words (half2 vectorized) ----------------
__global__ __launch_bounds__(128) void wsum_kernel() {
    int bn = blockIdx.x;
    __shared__ float al[Tt];
    if (threadIdx.x < Tt) al[threadIdx.x] = g_alpha[bn * Tt + threadIdx.x];
    __syncthreads();
    const __half2* Cr = (const __half2*)(g_C + (long)bn * Tt * KP);
    __half2* Er = (__half2*)(g_E + (long)bn * KP);
    for (int f = threadIdx.x; f < KP / 2; f += 128) {
        float ax = 0.f, ay = 0.f;
#pragma unroll
        for (int t = 0; t < Tt; t++) {
            float2 v = __half22float2(Cr[t * (KP / 2) + f]);
            ax += al[t] * v.x;
            ay += al[t] * v.y;
        }
        Er[f] = __floats2half2_rn(ax, ay);
    }
}

// ---------------- tensor-core persistent GRU (25 blocks, fp16 h exchange) ----------------
__global__ __launch_bounds__(256, 1) void gru_tc(const int* __restrict__ uid,
                                                 const float* __restrict__ user_emb,
                                                 const float* __restrict__ b_ih,
                                                 const float* __restrict__ b_hh,
                                                 const int* __restrict__ lens,
                                                 float* __restrict__ out) {
    extern __shared__ __half gsm[];          // [48*408] W | [64*408] h
    __shared__ float s_gate[48][66];
    __half* sW = gsm;
    __half* sH = gsm + 48 * 408;
    int tid = threadIdx.x, lane = tid & 31, wid = tid >> 5;
    int bg = blockIdx.x;
    int warpM = wid & 3, warpN = wid >> 2;

    for (int i = tid; i < 48 * 100; i += 256) {
        int j = i / 100, c4 = (i - j * 100) * 4;
        int grow = (j >> 4) * 400 + bg * 16 + (j & 15);
        *(uint2*)&sW[j * 408 + c4] = *(const uint2*)&g_Whh[(long)grow * Gg + c4];
    }

    int b = tid & 63, gi = tid >> 6;
    int len = lens[b];
    float myh[4], bir[4], biz[4], bin_[4], bhr[4], bhz[4], bhn[4];
    long ub = (long)uid[b] * Gg;
#pragma unroll
    for (int k = 0; k < 4; k++) {
        int gl = gi * 4 + k, gg = bg * 16 + gl;
        myh[k] = user_emb[ub + gg];
        bir[k] = b_ih[gg]; biz[k] = b_ih[400 + gg]; bin_[k] = b_ih[800 + gg];
        bhr[k] = b_hh[gg]; bhz[k] = b_hh[400 + gg]; bhn[k] = b_hh[800 + gg];
    }
    {
        __half2 p01 = __floats2half2_rn(myh[0], myh[1]);
        __half2 p23 = __floats2half2_rn(myh[2], myh[3]);
        uint2 pk = make_uint2(*(uint32_t*)&p01, *(uint32_t*)&p23);
        *(uint2*)&g_hH[0][b * 408 + bg * 16 + gi * 4] = pk;
    }

    uint32_t sHu = smem_u32(sH), sWu = smem_u32(sW);
    uint32_t aLd = sHu + (uint32_t)((warpM * 16 + (lane & 15)) * 816 + ((lane >> 4) * 16));
    uint32_t bLd4 = sWu + (uint32_t)((warpN * 24 + (lane & 7) + ((lane >> 4) * 8)) * 816 +
                                     (((lane >> 3) & 1) * 16));
    int l15 = lane & 15;
    uint32_t bLd2 = sWu + (uint32_t)((warpN * 24 + 16 + (l15 & 7)) * 816 + ((l15 >> 3) * 16));

    for (int n = 0; n < Nn; n++) {
        __threadfence();
        __syncthreads();
        if (tid == 0) {
            atomicAdd(&g_bar[n], 1);
            while (*((volatile int*)&g_bar[n]) < GBLK) { }
        }
        __syncthreads();
        const __half* hbuf = g_hH[n & 1];
        for (int i = tid; i < 64 * 51; i += 256) {
            int row = i / 51, c = i - row * 51;
            cpasync16(sHu + (uint32_t)(row * 816 + c * 16), hbuf + row * 408 + c * 8);
        }
        cpcommit();
        cpwait<0>();
        __syncthreads();

        float acc[3][4] = {};
#pragma unroll 5
        for (int ks = 0; ks < 25; ks++) {
            uint32_t koff = ks * 32;
            uint32_t af[4], b0, b1, b2, b3, c0, c1;
            ldsm_x4(af[0], af[1], af[2], af[3], aLd + koff);
            ldsm_x4(b0, b1, b2, b3, bLd4 + koff);
            ldsm_x2(c0, c1, bLd2 + koff);
            mma16816(acc[0], af, b0, b1);
            mma16816(acc[1], af, b2, b3);
            mma16816(acc[2], af, c0, c1);
        }
        int brow = warpM * 16 + (lane >> 2);
#pragma unroll
        for (int nt = 0; nt < 3; nt++) {
            int col = warpN * 24 + nt * 8 + (lane & 3) * 2;
            s_gate[col][brow] = acc[nt][0];
            s_gate[col + 1][brow] = acc[nt][1];
            s_gate[col][brow + 8] = acc[nt][2];
            s_gate[col + 1][brow + 8] = acc[nt][3];
        }
        __syncthreads();

        const float* gxt = g_GXt + (long)n * 1200 * 64;
#pragma unroll
        for (int k = 0; k < 4; k++) {
            int gl = gi * 4 + k, gg = bg * 16 + gl;
            float hr = s_gate[gl][b] + bhr[k];
            float hz = s_gate[16 + gl][b] + bhz[k];
            float hn = s_gate[32 + gl][b] + bhn[k];
            float xr = gxt[(0 * 400 + gg) * 64 + b] + bir[k];
            float xz = gxt[(400 + gg) * 64 + b] + biz[k];
            float xn = gxt[(800 + gg) * 64 + b] + bin_[k];
            float r = 1.f / (1.f + __expf(-(xr + hr)));
            float z = 1.f / (1.f + __expf(-(xz + hz)));
            float nv = tanhf(xn + r * hn);
            float hnew = (1.f - z) * nv + z * myh[k];
            if (n < len) myh[k] = hnew;
        }
        {
            __half2 p01 = __floats2half2_rn(myh[0], myh[1]);
            __half2 p23 = __floats2half2_rn(myh[2], myh[3]);
            uint2 pk = make_uint2(*(uint32_t*)&p01, *(uint32_t*)&p23);
            *(uint2*)&g_hH[(n + 1) & 1][b * 408 + bg * 16 + gi * 4] = pk;
        }
    }
#pragma unroll
    for (int k = 0; k < 4; k++) {
        int gg = bg * 16 + gi * 4 + k;
        out[b * Gg + gg] = myh[k];
    }
}

// ---------------- launch ----------------
extern "C" void kernel_launch(void* const* d_in, const int* in_sizes, int n_in,
                              void* d_out, int out_size) {
    const int*   user_id  = (const int*)d_in[0];
    const int*   title    = (const int*)d_in[1];
    const int*   hist_len = (const int*)d_in[2];
    const float* word_emb = (const float*)d_in[3];
    const float* conv_w   = (const float*)d_in[4];
    const float* conv_b   = (const float*)d_in[5];
    const float* v        = (const float*)d_in[6];
    const float* vb       = (const float*)d_in[7];
    const float* q        = (const float*)d_in[8];
    const float* user_emb = (const float*)d_in[9];
    const float* W_ih     = (const float*)d_in[10];
    const float* W_hh     = (const float*)d_in[11];
    const float* b_ih     = (const float*)d_in[12];
    const float* b_hh     = (const float*)d_in[13];
    float* out = (float*)d_out;

    __half *Xp, *Wtp, *vTp, *Wihp, *Cp, *Ep;
    float *scp, *GXp;
    int* bar;
    cudaGetSymbolAddress((void**)&Xp, g_X);
    cudaGetSymbolAddress((void**)&Wtp, g_Wt);
    cudaGetSymbolAddress((void**)&vTp, g_vT);
    cudaGetSymbolAddress((void**)&Wihp, g_Wih);
    cudaGetSymbolAddress((void**)&Cp, g_C);
    cudaGetSymbolAddress((void**)&Ep, g_E);
    cudaGetSymbolAddress((void**)&scp, g_scores);
    cudaGetSymbolAddress((void**)&GXp, g_GX);
    cudaGetSymbolAddress((void**)&bar, g_bar);

    auto smemsz = [](int mt, int nt) {
        return (3 * (mt * LDKH + nt * 16 * LDKH)) * (int)sizeof(__half);
    };
    cudaFuncSetAttribute((const void*)hgemm<64, 13, 0, 2>,
                         cudaFuncAttributeMaxDynamicSharedMemorySize, smemsz(64, 13));
    cudaFuncSetAttribute((const void*)hgemm<64, 13, 1, 2>,
                         cudaFuncAttributeMaxDynamicSharedMemorySize, smemsz(64, 13));
    cudaFuncSetAttribute((const void*)hgemm<256, 8, 2, 1>,
                         cudaFuncAttributeMaxDynamicSharedMemorySize, smemsz(256, 8));
    cudaFuncSetAttribute((const void*)hgemm<256, 3, 2, 1>,
                         cudaFuncAttributeMaxDynamicSharedMemorySize, smemsz(256, 3));
    cudaFuncSetAttribute((const void*)gru_tc,
                         cudaFuncAttributeMaxDynamicSharedMemorySize, (48 + 64) * 408 * 2);

    gather_kernel<<<Bb * Nn, 256>>>(title, word_emb);
    wtr_kernel<<<(416 * KCv + 255) / 256, 256>>>(conv_w);
    vtr_kernel<<<(208 * KP + 255) / 256, 256>>>(v);
    wihh_kernel<<<(1200 * KP + 255) / 256, 256>>>(W_ih);
    whh_kernel<<<(1200 * Gg + 255) / 256, 256>>>(W_hh);
    cudaMemsetAsync(bar, 0, 64 * sizeof(int));

    // conv: C = X @ Wt^T + b, ReLU -> half. MT=64, 2 col tiles of 208, 3-stage, 2 CTA/SM
    hgemm<64, 13, 0, 2><<<dim3(2, MROWS / 64), 256, smemsz(64, 13)>>>(
        Xp, Wtp, nullptr, Cp, conv_b, nullptr, 0, 0, KCv, KCv / 32, FNf);
    // attn: scores = sum_c tanh(C @ vT^T + vb) * q, all 208 cols, 2 CTA/SM
    hgemm<64, 13, 1, 2><<<dim3(1, MROWS / 64), 256, smemsz(64, 13)>>>(
        Cp, vTp, scp, nullptr, vb, q, 0, KP, KP, KP / 32, Aa);

    softmax_kernel<<<(Bb * Tt + 255) / 256, 256>>>();
    wsum_kernel<<<Bb * Nn, 128>>>();

    // GX = E @ W_ih^T + b_ih, row-major [r][1200], then transpose to [n][1200][64]
    hgemm<256, 8, 2, 1><<<dim3(9, 13), 256, smemsz(256, 8)>>>(
        Ep, Wihp, GXp, nullptr, b_ih, nullptr, 0, KP, KP, KP / 32, 1200);
    hgemm<256, 3, 2, 1><<<dim3(1, 13), 256, smemsz(256, 3)>>>(
        Ep, Wihp, GXp, nullptr, b_ih, nullptr, 1152, KP, KP, KP / 32, 1200);
    gx_transpose<<<dim3(19, Nn), 256>>>();

    gru_tc<<<GBLK, 256, (48 + 64) * 408 * 2>>>(user_id, user_emb, b_ih, b_hh, hist_len, out);
}